// round 10
// baseline (speedup 1.0000x reference)
#include <cuda_runtime.h>
#include <cuda_bf16.h>
#include <cstdint>

#define DF 1024
#define NH 16
#define DH 64
#define BB 2
#define SS 2048
#define MROWS (BB*SS)

#define KW   3072              // split-K width (3 * 1024)
#define KC   64                // bf16 K per SMEM chunk
#define NCHUNK (KW / KC)       // 48
#define NSTAGE 3
#define PITCH  72
#define PITCHB 144
#define OP_BYTES (128 * PITCHB)             // 18432
#define STAGE_BYTES (2 * OP_BYTES)          // 36864
#define GEMM_SMEM (512 + NSTAGE * STAGE_BYTES)  // 111104

// attention smem
#define ATILE   9216                       // one 64x64 bf16 tile, pitch 144
#define ASTRIDE (4 * ATILE + 256)          // Kh,Kl,Vh,Vl = 37120
#define QL_OFF  36864                      // 256 rows * 144B
#define ATTN_SMEM (3 * ASTRIDE)            // 111360

// ---------------------------------------------------------------------------
// Scratch
// ---------------------------------------------------------------------------
__device__ __nv_bfloat16 g_A3v3[3][(size_t)MROWS * KW];  // activations, split [hi|lo|hi]
__device__ __nv_bfloat16 g_W3v4[4][(size_t)DF * KW];     // weights,     split [hi|hi|lo]
__device__ __nv_bfloat16 g_Qh[(size_t)BB * NH * SS * DH];
__device__ __nv_bfloat16 g_Ql[(size_t)BB * NH * SS * DH];
__device__ __nv_bfloat16 g_Kh[(size_t)BB * NH * SS * DH];
__device__ __nv_bfloat16 g_Kl[(size_t)BB * NH * SS * DH];
__device__ __nv_bfloat16 g_Vh[(size_t)BB * NH * SS * DH];
__device__ __nv_bfloat16 g_Vl[(size_t)BB * NH * SS * DH];
__device__ int g_pos[BB * SS];
__device__ int g_cnt[BB];

// ---------------------------------------------------------------------------
// helpers
// ---------------------------------------------------------------------------
__device__ __forceinline__ uint32_t smem_u32(const void* p) {
    uint32_t a;
    asm("{ .reg .u64 t; cvta.to.shared.u64 t, %1; cvt.u32.u64 %0, t; }"
        : "=r"(a) : "l"(p));
    return a;
}

__device__ __forceinline__ void cp_async_16(uint32_t dst, const void* src) {
    asm volatile("cp.async.cg.shared.global [%0], [%1], 16;" :: "r"(dst), "l"(src) : "memory");
}
#define CP_COMMIT() asm volatile("cp.async.commit_group;" ::: "memory")
#define CP_WAIT1()  asm volatile("cp.async.wait_group 1;" ::: "memory")
#define CP_WAIT0()  asm volatile("cp.async.wait_group 0;" ::: "memory")

__device__ __forceinline__ void ldsm_x4(uint32_t& r0, uint32_t& r1, uint32_t& r2,
                                        uint32_t& r3, uint32_t addr) {
    asm volatile("ldmatrix.sync.aligned.m8n8.x4.shared.b16 {%0,%1,%2,%3}, [%4];"
                 : "=r"(r0), "=r"(r1), "=r"(r2), "=r"(r3) : "r"(addr));
}
__device__ __forceinline__ void ldsm_x4_t(uint32_t& r0, uint32_t& r1, uint32_t& r2,
                                          uint32_t& r3, uint32_t addr) {
    asm volatile("ldmatrix.sync.aligned.m8n8.x4.trans.shared.b16 {%0,%1,%2,%3}, [%4];"
                 : "=r"(r0), "=r"(r1), "=r"(r2), "=r"(r3) : "r"(addr));
}

__device__ __forceinline__ void mma16816(float* d, const uint32_t* a, const uint32_t* b) {
    asm volatile(
        "mma.sync.aligned.m16n8k16.row.col.f32.bf16.bf16.f32 "
        "{%0,%1,%2,%3}, {%4,%5,%6,%7}, {%8,%9}, {%0,%1,%2,%3};"
        : "+f"(d[0]), "+f"(d[1]), "+f"(d[2]), "+f"(d[3])
        : "r"(a[0]), "r"(a[1]), "r"(a[2]), "r"(a[3]), "r"(b[0]), "r"(b[1]));
}

__device__ __forceinline__ void split_pack(float x, float y, uint32_t& hp, uint32_t& lp) {
    uint32_t ux = __float_as_uint(x), uy = __float_as_uint(y);
    hp = __byte_perm(ux, uy, 0x7632);
    float lx = x - __uint_as_float(ux & 0xffff0000u);
    float ly = y - __uint_as_float(uy & 0xffff0000u);
    __nv_bfloat162 l2 = __floats2bfloat162_rn(lx, ly);
    lp = *reinterpret_cast<uint32_t*>(&l2);
}

// ---------------------------------------------------------------------------
// mask prefix scan: pos[b][s] = #valid keys before s ; cnt[b] = total valid
// ---------------------------------------------------------------------------
__global__ __launch_bounds__(256) void mask_scan(const int* __restrict__ mask,
                                                 int* __restrict__ pos, int* __restrict__ cnt)
{
    __shared__ int partial[256];
    const int b = blockIdx.x, tid = threadIdx.x;
    const int base = b * SS + tid * 8;
    int v[8], s = 0;
    #pragma unroll
    for (int i = 0; i < 8; i++) { v[i] = (mask[base + i] != 0); s += v[i]; }
    partial[tid] = s;
    __syncthreads();
    for (int off = 1; off < 256; off <<= 1) {
        int t = (tid >= off) ? partial[tid - off] : 0;
        __syncthreads();
        partial[tid] += t;
        __syncthreads();
    }
    int ex = (tid == 0) ? 0 : partial[tid - 1];
    #pragma unroll
    for (int i = 0; i < 8; i++) { pos[base + i] = ex; ex += v[i]; }
    if (tid == 255) cnt[b] = partial[255];
}

// ---------------------------------------------------------------------------
// zero pad rows [cnt, ceil64(cnt)) of compacted K/V (NaN guard for tail tile)
// ---------------------------------------------------------------------------
__global__ void zero_tail(const int* __restrict__ cnt_,
                          __nv_bfloat16* __restrict__ Kh, __nv_bfloat16* __restrict__ Kl,
                          __nv_bfloat16* __restrict__ Vh, __nv_bfloat16* __restrict__ Vl)
{
    const int b = blockIdx.x, h = blockIdx.y;
    const int cnt = cnt_[b];
    const int pad = (cnt + 63) & ~63;
    const int total = (pad - cnt) * DH / 8;      // uint4 units
    const size_t base = ((size_t)(b * NH + h) * SS + cnt) * DH;
    uint4 z = {0, 0, 0, 0};
    for (int i = threadIdx.x; i < total; i += blockDim.x) {
        *reinterpret_cast<uint4*>(Kh + base + (size_t)i * 8) = z;
        *reinterpret_cast<uint4*>(Kl + base + (size_t)i * 8) = z;
        *reinterpret_cast<uint4*>(Vh + base + (size_t)i * 8) = z;
        *reinterpret_cast<uint4*>(Vl + base + (size_t)i * 8) = z;
    }
}

// ---------------------------------------------------------------------------
// Split-bf16 conversions. conv_in: z=0 Q dense; z=1 K, z=2 V with row
// compaction (valid rows gathered to pos[r], masked rows skipped).
// ---------------------------------------------------------------------------
__global__ __launch_bounds__(256) void conv_in(const float* __restrict__ Q,
                                               const float* __restrict__ K,
                                               const float* __restrict__ V,
                                               const int* __restrict__ mask,
                                               const int* __restrict__ pos,
                                               __nv_bfloat16* __restrict__ A3)
{
    const int z = blockIdx.y;
    const float* X = z == 0 ? Q : (z == 1 ? K : V);
    __nv_bfloat16* Y = A3 + (size_t)z * MROWS * KW;
    int idx = (blockIdx.x * 256 + threadIdx.x) * 4;
    int r = idx >> 10, k = idx & 1023;
    int rr = r;
    if (z > 0) {
        int bb_ = r >> 11, sidx = r & 2047;
        if (mask[bb_ * SS + sidx] == 0) return;       // masked key row: skip
        rr = bb_ * SS + pos[bb_ * SS + sidx];         // compacted destination
    }
    float4 x = *reinterpret_cast<const float4*>(X + idx);
    float v[4] = {x.x, x.y, x.z, x.w};
    __nv_bfloat16 hi[4], lo[4];
    #pragma unroll
    for (int i = 0; i < 4; i++) {
        hi[i] = __float2bfloat16(v[i]);
        lo[i] = __float2bfloat16(v[i] - __bfloat162float(hi[i]));
    }
    uint64_t hip, lop;
    memcpy(&hip, hi, 8);
    memcpy(&lop, lo, 8);
    size_t base = (size_t)rr * KW + k;
    *reinterpret_cast<uint64_t*>(Y + base)        = hip;
    *reinterpret_cast<uint64_t*>(Y + base + 1024) = lop;
    *reinterpret_cast<uint64_t*>(Y + base + 2048) = hip;
}

__global__ __launch_bounds__(256) void conv_w(const float* __restrict__ Wq,
                                              const float* __restrict__ Wk,
                                              const float* __restrict__ Wv,
                                              const float* __restrict__ Wo,
                                              __nv_bfloat16* __restrict__ W3)
{
    const float* X = blockIdx.y == 0 ? Wq : (blockIdx.y == 1 ? Wk :
                      (blockIdx.y == 2 ? Wv : Wo));
    __nv_bfloat16* Y = W3 + (size_t)blockIdx.y * DF * KW;
    int idx = (blockIdx.x * 256 + threadIdx.x) * 4;
    float4 x = *reinterpret_cast<const float4*>(X + idx);
    float v[4] = {x.x, x.y, x.z, x.w};
    __nv_bfloat16 hi[4], lo[4];
    #pragma unroll
    for (int i = 0; i < 4; i++) {
        hi[i] = __float2bfloat16(v[i]);
        lo[i] = __float2bfloat16(v[i] - __bfloat162float(hi[i]));
    }
    uint64_t hip, lop;
    memcpy(&hip, hi, 8);
    memcpy(&lop, lo, 8);
    int r = idx >> 10, k = idx & 1023;
    size_t base = (size_t)r * KW + k;
    *reinterpret_cast<uint64_t*>(Y + base)        = hip;
    *reinterpret_cast<uint64_t*>(Y + base + 1024) = hip;
    *reinterpret_cast<uint64_t*>(Y + base + 2048) = lop;
}

// ---------------------------------------------------------------------------
// GEMM mainloop body: 128 threads / 4 warps (2M x 2N), warp tile 64x64
// ---------------------------------------------------------------------------
struct GemmCore {
    float acc[4][8][4];
    int m0w, n0w;

    __device__ __forceinline__ void run(uint32_t sb, int tid, int wid, int lid,
                                        const __nv_bfloat16* Abase,
                                        const __nv_bfloat16* Wbase) {
        m0w = (wid & 1) * 64;
        n0w = (wid >> 1) * 64;
        #pragma unroll
        for (int mi = 0; mi < 4; mi++)
            #pragma unroll
            for (int nj = 0; nj < 8; nj++)
                #pragma unroll
                for (int e = 0; e < 4; e++) acc[mi][nj][e] = 0.f;

        auto load_chunk = [&](int c, int s) {
            const int k0 = c * KC;
            const uint32_t stage = sb + 512 + s * STAGE_BYTES;
            #pragma unroll
            for (int i = 0; i < 16; i++) {
                int seg = i * 128 + tid;
                int op  = seg >> 10;
                int r   = (seg & 1023) >> 3;
                int cs  = seg & 7;
                uint32_t dst = stage + op * OP_BYTES + (uint32_t)(r * PITCHB + cs * 16);
                const __nv_bfloat16* src = (op == 0 ? Abase : Wbase)
                                           + (size_t)r * KW + k0 + cs * 8;
                cp_async_16(dst, src);
            }
        };

        load_chunk(0, 0); CP_COMMIT();
        load_chunk(1, 1); CP_COMMIT();

        for (int c = 0; c < NCHUNK; c++) {
            const int s = c % NSTAGE;
            CP_WAIT1();
            __syncthreads();
            int cn = c + 2;
            if (cn < NCHUNK) load_chunk(cn, cn % NSTAGE);
            CP_COMMIT();

            const uint32_t sA = sb + 512 + s * STAGE_BYTES;
            const uint32_t sW = sA + OP_BYTES;
            #pragma unroll
            for (int kk = 0; kk < 4; kk++) {
                uint32_t a[4][4];
                #pragma unroll
                for (int mi = 0; mi < 4; mi++) {
                    uint32_t addr = sA + (uint32_t)((m0w + mi * 16 + (lid & 15)) * PITCHB
                                     + kk * 32 + ((lid >> 4) << 4));
                    ldsm_x4(a[mi][0], a[mi][1], a[mi][2], a[mi][3], addr);
                }
                uint32_t b[8][2];
                #pragma unroll
                for (int ni = 0; ni < 4; ni++) {
                    uint32_t addr = sW + (uint32_t)((n0w + ni * 16 + (lid & 7)
                                     + ((lid >> 4) & 1) * 8) * PITCHB
                                     + kk * 32 + (((lid >> 3) & 1) << 4));
                    uint32_t r0, r1, r2, r3;
                    ldsm_x4(r0, r1, r2, r3, addr);
                    b[2 * ni][0] = r0; b[2 * ni][1] = r1;
                    b[2 * ni + 1][0] = r2; b[2 * ni + 1][1] = r3;
                }
                #pragma unroll
                for (int mi = 0; mi < 4; mi++)
                    #pragma unroll
                    for (int nj = 0; nj < 8; nj++)
                        mma16816(acc[mi][nj], a[mi], b[nj]);
            }
            __syncthreads();
        }
        CP_WAIT0();
    }
};

// ---------------------------------------------------------------------------
// Fused QKV projection GEMM over pre-compacted inputs.
// z=0: Q dense. z=1: K, z=2: V — rows already compacted; tiles past cnt exit.
// ---------------------------------------------------------------------------
__global__ void __launch_bounds__(128, 2)
gemm_qkv(const __nv_bfloat16* __restrict__ A3, const __nv_bfloat16* __restrict__ W3,
         const float* __restrict__ bq, const float* __restrict__ bk,
         const float* __restrict__ bv, const int* __restrict__ cnt_,
         __nv_bfloat16* __restrict__ Qh, __nv_bfloat16* __restrict__ Ql,
         __nv_bfloat16* __restrict__ Kh, __nv_bfloat16* __restrict__ Kl,
         __nv_bfloat16* __restrict__ Vh, __nv_bfloat16* __restrict__ Vl)
{
    extern __shared__ char smem[];
    const uint32_t sb = smem_u32(smem);
    const int tid = threadIdx.x, wid = tid >> 5, lid = tid & 31;
    const int z = blockIdx.z;
    const int m0 = blockIdx.y * 128, n0 = blockIdx.x * 128;

    if (z > 0) {                      // compacted K/V: skip row tiles past cnt
        int bb_ = m0 >> 11, mrel = m0 & 2047;
        if (mrel >= cnt_[bb_]) return;
    }

    const float* bias = (z == 0) ? bq : (z == 1) ? bk : bv;
    float* bias_s = (float*)smem;
    if (tid < 128) bias_s[tid] = bias[n0 + tid];

    __nv_bfloat16* H = (z == 0) ? Qh : (z == 1) ? Kh : Vh;
    __nv_bfloat16* L = (z == 0) ? Ql : (z == 1) ? Kl : Vl;

    GemmCore core;
    core.run(sb, tid, wid, lid,
             A3 + (size_t)z * MROWS * KW + (size_t)m0 * KW,
             W3 + (size_t)z * DF * KW + (size_t)n0 * KW);

    const int g = lid >> 2, t = lid & 3;
    #pragma unroll
    for (int mi = 0; mi < 4; mi++) {
        #pragma unroll
        for (int nj = 0; nj < 8; nj++) {
            int colrel = core.n0w + nj * 8 + 2 * t;
            int col = n0 + colrel;
            int hh = col >> 6, dh = col & 63;
            float c0 = core.acc[mi][nj][0] + bias_s[colrel];
            float c1 = core.acc[mi][nj][1] + bias_s[colrel + 1];
            float c2 = core.acc[mi][nj][2] + bias_s[colrel];
            float c3 = core.acc[mi][nj][3] + bias_s[colrel + 1];
            #pragma unroll
            for (int rr = 0; rr < 2; rr++) {
                int row = m0 + core.m0w + mi * 16 + g + rr * 8;
                int bb_ = row >> 11, sidx = row & 2047;
                size_t dst = ((size_t)(bb_ * NH + hh) * SS + sidx) * DH + dh;
                uint32_t hp, lp;
                if (rr == 0) split_pack(c0, c1, hp, lp);
                else         split_pack(c2, c3, hp, lp);
                *reinterpret_cast<uint32_t*>(H + dst) = hp;
                *reinterpret_cast<uint32_t*>(L + dst) = lp;
            }
        }
    }
}

// ---------------------------------------------------------------------------
// Output projection GEMM: fp32 out
// ---------------------------------------------------------------------------
__global__ void __launch_bounds__(128, 2)
gemm_out(const __nv_bfloat16* __restrict__ A3, const __nv_bfloat16* __restrict__ W3,
         const float* __restrict__ bias, float* __restrict__ C)
{
    extern __shared__ char smem[];
    const uint32_t sb = smem_u32(smem);
    const int tid = threadIdx.x, wid = tid >> 5, lid = tid & 31;
    const int m0 = blockIdx.y * 128, n0 = blockIdx.x * 128;

    float* bias_s = (float*)smem;
    if (tid < 128) bias_s[tid] = bias[n0 + tid];

    GemmCore core;
    core.run(sb, tid, wid, lid, A3 + (size_t)m0 * KW, W3 + (size_t)n0 * KW);

    const int g = lid >> 2, t = lid & 3;
    #pragma unroll
    for (int mi = 0; mi < 4; mi++) {
        #pragma unroll
        for (int nj = 0; nj < 8; nj++) {
            int colrel = core.n0w + nj * 8 + 2 * t;
            int col = n0 + colrel;
            int row0 = m0 + core.m0w + mi * 16 + g;
            float2 v0 = {core.acc[mi][nj][0] + bias_s[colrel],
                         core.acc[mi][nj][1] + bias_s[colrel + 1]};
            float2 v1 = {core.acc[mi][nj][2] + bias_s[colrel],
                         core.acc[mi][nj][3] + bias_s[colrel + 1]};
            *reinterpret_cast<float2*>(C + (size_t)row0 * DF + col) = v0;
            *reinterpret_cast<float2*>(C + (size_t)(row0 + 8) * DF + col) = v1;
        }
    }
}

// ---------------------------------------------------------------------------
// FlashAttention-2 on mma.sync over COMPACTED keys. 256 queries/CTA,
// 8 warps x 32 q-rows (mi=2) — halves smem crossbar traffic per MAC.
// ---------------------------------------------------------------------------
__global__ void __launch_bounds__(256, 1)
attn_mma(const __nv_bfloat16* __restrict__ Qh_, const __nv_bfloat16* __restrict__ Ql_,
         const __nv_bfloat16* __restrict__ Kh_, const __nv_bfloat16* __restrict__ Kl_,
         const __nv_bfloat16* __restrict__ Vh_, const __nv_bfloat16* __restrict__ Vl_,
         const int* __restrict__ cnt_, __nv_bfloat16* __restrict__ A3out)
{
    extern __shared__ char smem[];
    const uint32_t sb = smem_u32(smem);
    const int tid = threadIdx.x, wid = tid >> 5, lid = tid & 31;
    const int g = lid >> 2, t4 = lid & 3;
    const int b = blockIdx.z, h = blockIdx.y;
    const int bh = b * NH + h;
    const int q0 = blockIdx.x * 256;
    const int m0w = wid * 32;
    const float SC = 0.03125f;

    const int cnt = cnt_[b];
    const int nt = (cnt + 63) >> 6;

    // ---- stage Q (hi,lo): 256 rows -> register a-frags ----
    {
        const size_t qbase = ((size_t)bh * SS + q0);
        #pragma unroll
        for (int i = 0; i < 8; i++) {
            int seg = i * 256 + tid;             // 0..2047
            int row = seg >> 3, cs = seg & 7;
            const size_t src = (qbase + row) * DH + cs * 8;
            uint32_t d = sb + (uint32_t)(row * PITCHB + cs * 16);
            cp_async_16(d,          Qh_ + src);
            cp_async_16(d + QL_OFF, Ql_ + src);
        }
    }
    CP_COMMIT(); CP_WAIT0(); __syncthreads();

    uint32_t qh[4][2][4], ql[4][2][4];
    #pragma unroll
    for (int kk = 0; kk < 4; kk++)
        #pragma unroll
        for (int mi = 0; mi < 2; mi++) {
            uint32_t a = sb + (uint32_t)((m0w + mi * 16 + (lid & 15)) * PITCHB
                          + kk * 32 + ((lid >> 4) << 4));
            ldsm_x4(qh[kk][mi][0], qh[kk][mi][1], qh[kk][mi][2], qh[kk][mi][3], a);
            ldsm_x4(ql[kk][mi][0], ql[kk][mi][1], ql[kk][mi][2], ql[kk][mi][3], a + QL_OFF);
        }
    __syncthreads();

    auto load_tile = [&](int ti, int st) {
        const uint32_t stage = sb + st * ASTRIDE;
        const size_t kbase = ((size_t)bh * SS + ti * 64);
        #pragma unroll
        for (int i = 0; i < 2; i++) {
            int seg = i * 256 + tid;
            int row = seg >> 3, cs = seg & 7;
            size_t src = (kbase + row) * DH + cs * 8;
            uint32_t d = stage + (uint32_t)(row * PITCHB + cs * 16);
            cp_async_16(d,             Kh_ + src);
            cp_async_16(d + ATILE,     Kl_ + src);
            cp_async_16(d + 2 * ATILE, Vh_ + src);
            cp_async_16(d + 3 * ATILE, Vl_ + src);
        }
    };

    float mM[2][2], lL[2][2];
    #pragma unroll
    for (int mi = 0; mi < 2; mi++) { mM[mi][0] = mM[mi][1] = -1e30f; lL[mi][0] = lL[mi][1] = 0.f; }
    float o[2][8][4];
    #pragma unroll
    for (int mi = 0; mi < 2; mi++)
        #pragma unroll
        for (int nj = 0; nj < 8; nj++)
            #pragma unroll
            for (int e = 0; e < 4; e++) o[mi][nj][e] = 0.f;

    if (0 < nt) load_tile(0, 0);
    CP_COMMIT();
    if (1 < nt) load_tile(1, 1);
    CP_COMMIT();

    for (int ti = 0; ti < nt; ti++) {
        const int st = ti % 3;
        CP_WAIT1();
        __syncthreads();
        if (ti + 2 < nt) load_tile(ti + 2, (ti + 2) % 3);
        CP_COMMIT();

        const uint32_t sK  = sb + st * ASTRIDE;
        const uint32_t sKl = sK + ATILE, sV = sK + 2 * ATILE, sVl = sK + 3 * ATILE;

        // ---- S = Qh Kh^T + Ql Kh^T + Qh Kl^T ----
        float s[2][8][4];
        #pragma unroll
        for (int mi = 0; mi < 2; mi++)
            #pragma unroll
            for (int nj = 0; nj < 8; nj++)
                #pragma unroll
                for (int e = 0; e < 4; e++) s[mi][nj][e] = 0.f;

        #pragma unroll
        for (int kk = 0; kk < 4; kk++) {
            uint32_t kb[4][4];
            #pragma unroll
            for (int ni = 0; ni < 4; ni++) {
                uint32_t a = sK + (uint32_t)((ni * 16 + (lid & 7) + ((lid >> 4) & 1) * 8) * PITCHB
                             + kk * 32 + (((lid >> 3) & 1) << 4));
                ldsm_x4(kb[ni][0], kb[ni][1], kb[ni][2], kb[ni][3], a);
            }
            #pragma unroll
            for (int mi = 0; mi < 2; mi++)
                #pragma unroll
                for (int nj = 0; nj < 8; nj++)
                    mma16816(s[mi][nj], qh[kk][mi], &kb[nj >> 1][(nj & 1) * 2]);
            #pragma unroll
            for (int mi = 0; mi < 2; mi++)
                #pragma unroll
                for (int nj = 0; nj < 8; nj++)
                    mma16816(s[mi][nj], ql[kk][mi], &kb[nj >> 1][(nj & 1) * 2]);
            #pragma unroll
            for (int ni = 0; ni < 4; ni++) {
                uint32_t a = sKl + (uint32_t)((ni * 16 + (lid & 7) + ((lid >> 4) & 1) * 8) * PITCHB
                             + kk * 32 + (((lid >> 3) & 1) << 4));
                ldsm_x4(kb[ni][0], kb[ni][1], kb[ni][2], kb[ni][3], a);
            }
            #pragma unroll
            for (int mi = 0; mi < 2; mi++)
                #pragma unroll
                for (int nj = 0; nj < 8; nj++)
                    mma16816(s[mi][nj], qh[kk][mi], &kb[nj >> 1][(nj & 1) * 2]);
        }

        // ---- scale + tail mask + online softmax (per mi, per row-half) ----
        const int kbase_idx = ti * 64;
        #pragma unroll
        for (int mi = 0; mi < 2; mi++) {
            float tmax0 = -1e30f, tmax1 = -1e30f;
            #pragma unroll
            for (int nj = 0; nj < 8; nj++) {
                int k0i = kbase_idx + nj * 8 + 2 * t4;
                bool v0 = k0i < cnt, v1 = (k0i + 1) < cnt;
                float s0 = v0 ? s[mi][nj][0] * SC : -1e9f;
                float s1 = v1 ? s[mi][nj][1] * SC : -1e9f;
                float s2 = v0 ? s[mi][nj][2] * SC : -1e9f;
                float s3 = v1 ? s[mi][nj][3] * SC : -1e9f;
                s[mi][nj][0] = s0; s[mi][nj][1] = s1; s[mi][nj][2] = s2; s[mi][nj][3] = s3;
                tmax0 = fmaxf(tmax0, fmaxf(s0, s1));
                tmax1 = fmaxf(tmax1, fmaxf(s2, s3));
            }
            tmax0 = fmaxf(tmax0, __shfl_xor_sync(0xffffffffu, tmax0, 1));
            tmax0 = fmaxf(tmax0, __shfl_xor_sync(0xffffffffu, tmax0, 2));
            tmax1 = fmaxf(tmax1, __shfl_xor_sync(0xffffffffu, tmax1, 1));
            tmax1 = fmaxf(tmax1, __shfl_xor_sync(0xffffffffu, tmax1, 2));

            float mn0 = fmaxf(mM[mi][0], tmax0), mn1 = fmaxf(mM[mi][1], tmax1);
            float sc0 = __expf(mM[mi][0] - mn0), sc1 = __expf(mM[mi][1] - mn1);
            mM[mi][0] = mn0; mM[mi][1] = mn1;
            lL[mi][0] *= sc0; lL[mi][1] *= sc1;
            #pragma unroll
            for (int nj = 0; nj < 8; nj++) {
                o[mi][nj][0] *= sc0; o[mi][nj][1] *= sc0;
                o[mi][nj][2] *= sc1; o[mi][nj][3] *= sc1;
            }
            #pragma unroll
            for (int nj = 0; nj < 8; nj++) {
                float p0 = __expf(s[mi][nj][0] - mn0);
                float p1 = __expf(s[mi][nj][1] - mn0);
                float p2 = __expf(s[mi][nj][2] - mn1);
                float p3 = __expf(s[mi][nj][3] - mn1);
                s[mi][nj][0] = p0; s[mi][nj][1] = p1; s[mi][nj][2] = p2; s[mi][nj][3] = p3;
                lL[mi][0] += p0 + p1; lL[mi][1] += p2 + p3;
            }
        }

        // ---- O += Ph Vh + Pl Vh + Ph Vl ----
        #pragma unroll
        for (int kk = 0; kk < 4; kk++) {
            uint32_t ah[2][4], al[2][4];
            #pragma unroll
            for (int mi = 0; mi < 2; mi++) {
                split_pack(s[mi][2 * kk][0],     s[mi][2 * kk][1],     ah[mi][0], al[mi][0]);
                split_pack(s[mi][2 * kk][2],     s[mi][2 * kk][3],     ah[mi][1], al[mi][1]);
                split_pack(s[mi][2 * kk + 1][0], s[mi][2 * kk + 1][1], ah[mi][2], al[mi][2]);
                split_pack(s[mi][2 * kk + 1][2], s[mi][2 * kk + 1][3], ah[mi][3], al[mi][3]);
            }
            uint32_t vb[4][4];
            #pragma unroll
            for (int njp = 0; njp < 4; njp++) {
                uint32_t a = sV + (uint32_t)((16 * kk + (lid & 7) + ((lid >> 3) & 1) * 8) * PITCHB
                             + (16 * njp + ((lid >> 4) & 1) * 8) * 2);
                ldsm_x4_t(vb[njp][0], vb[njp][1], vb[njp][2], vb[njp][3], a);
            }
            #pragma unroll
            for (int mi = 0; mi < 2; mi++)
                #pragma unroll
                for (int nj = 0; nj < 8; nj++)
                    mma16816(o[mi][nj], ah[mi], &vb[nj >> 1][(nj & 1) * 2]);
            #pragma unroll
            for (int mi = 0; mi < 2; mi++)
                #pragma unroll
                for (int nj = 0; nj < 8; nj++)
                    mma16816(o[mi][nj], al[mi], &vb[nj >> 1][(nj & 1) * 2]);
            #pragma unroll
            for (int njp = 0; njp < 4; njp++) {
                uint32_t a = sVl + (uint32_t)((16 * kk + (lid & 7) + ((lid >> 3) & 1) * 8) * PITCHB
                             + (16 * njp + ((lid >> 4) & 1) * 8) * 2);
                ldsm_x4_t(vb[njp][0], vb[njp][1], vb[njp][2], vb[njp][3], a);
            }
            #pragma unroll
            for (int mi = 0; mi < 2; mi++)
                #pragma unroll
                for (int nj = 0; nj < 8; nj++)
                    mma16816(o[mi][nj], ah[mi], &vb[nj >> 1][(nj & 1) * 2]);
        }
        __syncthreads();
    }
    CP_WAIT0();

    // ---- finalize + write split bf16 straight into A3 [hi|lo|hi] ----
    const int colbase = h * DH;
    #pragma unroll
    for (int mi = 0; mi < 2; mi++) {
        float l0 = lL[mi][0], l1 = lL[mi][1];
        l0 += __shfl_xor_sync(0xffffffffu, l0, 1);
        l0 += __shfl_xor_sync(0xffffffffu, l0, 2);
        l1 += __shfl_xor_sync(0xffffffffu, l1, 1);
        l1 += __shfl_xor_sync(0xffffffffu, l1, 2);
        float inv0 = 1.f / l0, inv1 = 1.f / l1;

        const int srow = q0 + m0w + mi * 16 + g;
        size_t r0 = (size_t)(b * SS + srow) * KW;
        size_t r1 = r0 + (size_t)8 * KW;

        #pragma unroll
        for (int nj = 0; nj < 8; nj++) {
            int c = colbase + nj * 8 + 2 * t4;
            uint32_t hp, lp;
            split_pack(o[mi][nj][0] * inv0, o[mi][nj][1] * inv0, hp, lp);
            *reinterpret_cast<uint32_t*>(A3out + r0 + c)        = hp;
            *reinterpret_cast<uint32_t*>(A3out + r0 + 1024 + c) = lp;
            *reinterpret_cast<uint32_t*>(A3out + r0 + 2048 + c) = hp;
            split_pack(o[mi][nj][2] * inv1, o[mi][nj][3] * inv1, hp, lp);
            *reinterpret_cast<uint32_t*>(A3out + r1 + c)        = hp;
            *reinterpret_cast<uint32_t*>(A3out + r1 + 1024 + c) = lp;
            *reinterpret_cast<uint32_t*>(A3out + r1 + 2048 + c) = hp;
        }
    }
}

// ---------------------------------------------------------------------------
// launch
// ---------------------------------------------------------------------------
extern "C" void kernel_launch(void* const* d_in, const int* in_sizes, int n_in,
                              void* d_out, int out_size)
{
    const float* Q    = (const float*)d_in[0];
    const float* K    = (const float*)d_in[1];
    const float* V    = (const float*)d_in[2];
    const int*   mask = (const int*)  d_in[3];
    const float* Wq   = (const float*)d_in[4];
    const float* bq   = (const float*)d_in[5];
    const float* Wk   = (const float*)d_in[6];
    const float* bk   = (const float*)d_in[7];
    const float* Wv   = (const float*)d_in[8];
    const float* bv   = (const float*)d_in[9];
    const float* Wo   = (const float*)d_in[10];
    const float* bo   = (const float*)d_in[11];
    float* out = (float*)d_out;

    __nv_bfloat16 *A3, *W3, *Qh, *Ql, *Kh, *Kl, *Vh, *Vl;
    int *pos, *cnt;
    cudaGetSymbolAddress((void**)&A3, g_A3v3);
    cudaGetSymbolAddress((void**)&W3, g_W3v4);
    cudaGetSymbolAddress((void**)&Qh, g_Qh);
    cudaGetSymbolAddress((void**)&Ql, g_Ql);
    cudaGetSymbolAddress((void**)&Kh, g_Kh);
    cudaGetSymbolAddress((void**)&Kl, g_Kl);
    cudaGetSymbolAddress((void**)&Vh, g_Vh);
    cudaGetSymbolAddress((void**)&Vl, g_Vl);
    cudaGetSymbolAddress((void**)&pos, g_pos);
    cudaGetSymbolAddress((void**)&cnt, g_cnt);

    cudaFuncSetAttribute(gemm_qkv, cudaFuncAttributeMaxDynamicSharedMemorySize, GEMM_SMEM);
    cudaFuncSetAttribute(gemm_out, cudaFuncAttributeMaxDynamicSharedMemorySize, GEMM_SMEM);
    cudaFuncSetAttribute(attn_mma, cudaFuncAttributeMaxDynamicSharedMemorySize, ATTN_SMEM);

    mask_scan<<<BB, 256>>>(mask, pos, cnt);
    conv_w<<<dim3(DF * DF / 1024, 4), 256>>>(Wq, Wk, Wv, Wo, W3);
    conv_in<<<dim3(MROWS * DF / 1024, 3), 256>>>(Q, K, V, mask, pos, A3);

    gemm_qkv<<<dim3(DF / 128, MROWS / 128, 3), 128, GEMM_SMEM>>>(
        A3, W3, bq, bk, bv, cnt, Qh, Ql, Kh, Kl, Vh, Vl);

    zero_tail<<<dim3(BB, NH), 256>>>(cnt, Kh, Kl, Vh, Vl);

    attn_mma<<<dim3(SS / 256, NH, BB), 256, ATTN_SMEM>>>(Qh, Ql, Kh, Kl, Vh, Vl, cnt, A3);

    gemm_out<<<dim3(DF / 128, MROWS / 128), 128, GEMM_SMEM>>>(
        A3, W3 + (size_t)3 * DF * KW, bo, out);
}

// round 11
// speedup vs baseline: 1.4882x; 1.4882x over previous
#include <cuda_runtime.h>
#include <cuda_bf16.h>
#include <cstdint>

#define DF 1024
#define NH 16
#define DH 64
#define BB 2
#define SS 2048
#define MROWS (BB*SS)

#define KW   3072              // split-K width (3 * 1024)
#define KC   64                // bf16 K per SMEM chunk
#define NCHUNK (KW / KC)       // 48
#define NSTAGE 3
#define PITCH  72
#define PITCHB 144
#define OP_BYTES (128 * PITCHB)             // 18432
#define STAGE_BYTES (2 * OP_BYTES)          // 36864
#define GEMM_SMEM (512 + NSTAGE * STAGE_BYTES)  // 111104

// attention smem (R9 layout: 128 q-rows staged, Ql at +18432)
#define ATILE   9216                       // one 64x64 bf16 tile, pitch 144
#define ASTRIDE (4 * ATILE + 256)          // Kh,Kl,Vh,Vl = 37120
#define QL_OFF  18432
#define ATTN_SMEM (3 * ASTRIDE)            // 111360

// ---------------------------------------------------------------------------
// Scratch
// ---------------------------------------------------------------------------
__device__ __nv_bfloat16 g_A3v3[3][(size_t)MROWS * KW];  // activations, split [hi|lo|hi]
__device__ __nv_bfloat16 g_W3v4[4][(size_t)DF * KW];     // weights,     split [hi|hi|lo]
__device__ __nv_bfloat16 g_Qh[(size_t)BB * NH * SS * DH];
__device__ __nv_bfloat16 g_Ql[(size_t)BB * NH * SS * DH];
__device__ __nv_bfloat16 g_Kh[(size_t)BB * NH * SS * DH];
__device__ __nv_bfloat16 g_Kl[(size_t)BB * NH * SS * DH];
__device__ __nv_bfloat16 g_Vh[(size_t)BB * NH * SS * DH];
__device__ __nv_bfloat16 g_Vl[(size_t)BB * NH * SS * DH];
__device__ int g_pos[BB * SS];
__device__ int g_cnt[BB];

// ---------------------------------------------------------------------------
// helpers
// ---------------------------------------------------------------------------
__device__ __forceinline__ uint32_t smem_u32(const void* p) {
    uint32_t a;
    asm("{ .reg .u64 t; cvta.to.shared.u64 t, %1; cvt.u32.u64 %0, t; }"
        : "=r"(a) : "l"(p));
    return a;
}

__device__ __forceinline__ void cp_async_16(uint32_t dst, const void* src) {
    asm volatile("cp.async.cg.shared.global [%0], [%1], 16;" :: "r"(dst), "l"(src) : "memory");
}
#define CP_COMMIT() asm volatile("cp.async.commit_group;" ::: "memory")
#define CP_WAIT1()  asm volatile("cp.async.wait_group 1;" ::: "memory")
#define CP_WAIT0()  asm volatile("cp.async.wait_group 0;" ::: "memory")

__device__ __forceinline__ void ldsm_x4(uint32_t& r0, uint32_t& r1, uint32_t& r2,
                                        uint32_t& r3, uint32_t addr) {
    asm volatile("ldmatrix.sync.aligned.m8n8.x4.shared.b16 {%0,%1,%2,%3}, [%4];"
                 : "=r"(r0), "=r"(r1), "=r"(r2), "=r"(r3) : "r"(addr));
}
__device__ __forceinline__ void ldsm_x4_t(uint32_t& r0, uint32_t& r1, uint32_t& r2,
                                          uint32_t& r3, uint32_t addr) {
    asm volatile("ldmatrix.sync.aligned.m8n8.x4.trans.shared.b16 {%0,%1,%2,%3}, [%4];"
                 : "=r"(r0), "=r"(r1), "=r"(r2), "=r"(r3) : "r"(addr));
}

__device__ __forceinline__ void mma16816(float* d, const uint32_t* a, const uint32_t* b) {
    asm volatile(
        "mma.sync.aligned.m16n8k16.row.col.f32.bf16.bf16.f32 "
        "{%0,%1,%2,%3}, {%4,%5,%6,%7}, {%8,%9}, {%0,%1,%2,%3};"
        : "+f"(d[0]), "+f"(d[1]), "+f"(d[2]), "+f"(d[3])
        : "r"(a[0]), "r"(a[1]), "r"(a[2]), "r"(a[3]), "r"(b[0]), "r"(b[1]));
}

__device__ __forceinline__ void split_pack(float x, float y, uint32_t& hp, uint32_t& lp) {
    uint32_t ux = __float_as_uint(x), uy = __float_as_uint(y);
    hp = __byte_perm(ux, uy, 0x7632);
    float lx = x - __uint_as_float(ux & 0xffff0000u);
    float ly = y - __uint_as_float(uy & 0xffff0000u);
    __nv_bfloat162 l2 = __floats2bfloat162_rn(lx, ly);
    lp = *reinterpret_cast<uint32_t*>(&l2);
}

// ---------------------------------------------------------------------------
// mask prefix scan: pos[b][s] = #valid keys before s ; cnt[b] = total valid
// ---------------------------------------------------------------------------
__global__ __launch_bounds__(256) void mask_scan(const int* __restrict__ mask,
                                                 int* __restrict__ pos, int* __restrict__ cnt)
{
    __shared__ int partial[256];
    const int b = blockIdx.x, tid = threadIdx.x;
    const int base = b * SS + tid * 8;
    int v[8], s = 0;
    #pragma unroll
    for (int i = 0; i < 8; i++) { v[i] = (mask[base + i] != 0); s += v[i]; }
    partial[tid] = s;
    __syncthreads();
    for (int off = 1; off < 256; off <<= 1) {
        int t = (tid >= off) ? partial[tid - off] : 0;
        __syncthreads();
        partial[tid] += t;
        __syncthreads();
    }
    int ex = (tid == 0) ? 0 : partial[tid - 1];
    #pragma unroll
    for (int i = 0; i < 8; i++) { pos[base + i] = ex; ex += v[i]; }
    if (tid == 255) cnt[b] = partial[255];
}

// ---------------------------------------------------------------------------
// Split-bf16 conversions. conv_in: z=0 Q dense; z=1 K, z=2 V with row
// compaction (valid rows gathered to pos[r], masked rows skipped).
// ---------------------------------------------------------------------------
__global__ __launch_bounds__(256) void conv_in(const float* __restrict__ Q,
                                               const float* __restrict__ K,
                                               const float* __restrict__ V,
                                               const int* __restrict__ mask,
                                               const int* __restrict__ pos,
                                               __nv_bfloat16* __restrict__ A3)
{
    const int z = blockIdx.y;
    const float* X = z == 0 ? Q : (z == 1 ? K : V);
    __nv_bfloat16* Y = A3 + (size_t)z * MROWS * KW;
    int idx = (blockIdx.x * 256 + threadIdx.x) * 4;
    int r = idx >> 10, k = idx & 1023;
    int rr = r;
    if (z > 0) {
        int bb_ = r >> 11, sidx = r & 2047;
        if (mask[bb_ * SS + sidx] == 0) return;       // masked key row: skip
        rr = bb_ * SS + pos[bb_ * SS + sidx];         // compacted destination
    }
    float4 x = *reinterpret_cast<const float4*>(X + idx);
    float v[4] = {x.x, x.y, x.z, x.w};
    __nv_bfloat16 hi[4], lo[4];
    #pragma unroll
    for (int i = 0; i < 4; i++) {
        hi[i] = __float2bfloat16(v[i]);
        lo[i] = __float2bfloat16(v[i] - __bfloat162float(hi[i]));
    }
    uint64_t hip, lop;
    memcpy(&hip, hi, 8);
    memcpy(&lop, lo, 8);
    size_t base = (size_t)rr * KW + k;
    *reinterpret_cast<uint64_t*>(Y + base)        = hip;
    *reinterpret_cast<uint64_t*>(Y + base + 1024) = lop;
    *reinterpret_cast<uint64_t*>(Y + base + 2048) = hip;
}

__global__ __launch_bounds__(256) void conv_w(const float* __restrict__ Wq,
                                              const float* __restrict__ Wk,
                                              const float* __restrict__ Wv,
                                              const float* __restrict__ Wo,
                                              __nv_bfloat16* __restrict__ W3)
{
    const float* X = blockIdx.y == 0 ? Wq : (blockIdx.y == 1 ? Wk :
                      (blockIdx.y == 2 ? Wv : Wo));
    __nv_bfloat16* Y = W3 + (size_t)blockIdx.y * DF * KW;
    int idx = (blockIdx.x * 256 + threadIdx.x) * 4;
    float4 x = *reinterpret_cast<const float4*>(X + idx);
    float v[4] = {x.x, x.y, x.z, x.w};
    __nv_bfloat16 hi[4], lo[4];
    #pragma unroll
    for (int i = 0; i < 4; i++) {
        hi[i] = __float2bfloat16(v[i]);
        lo[i] = __float2bfloat16(v[i] - __bfloat162float(hi[i]));
    }
    uint64_t hip, lop;
    memcpy(&hip, hi, 8);
    memcpy(&lop, lo, 8);
    int r = idx >> 10, k = idx & 1023;
    size_t base = (size_t)r * KW + k;
    *reinterpret_cast<uint64_t*>(Y + base)        = hip;
    *reinterpret_cast<uint64_t*>(Y + base + 1024) = hip;
    *reinterpret_cast<uint64_t*>(Y + base + 2048) = lop;
}

// ---------------------------------------------------------------------------
// GEMM mainloop body: 128 threads / 4 warps (2M x 2N), warp tile 64x64
// ---------------------------------------------------------------------------
struct GemmCore {
    float acc[4][8][4];
    int m0w, n0w;

    __device__ __forceinline__ void run(uint32_t sb, int tid, int wid, int lid,
                                        const __nv_bfloat16* Abase,
                                        const __nv_bfloat16* Wbase) {
        m0w = (wid & 1) * 64;
        n0w = (wid >> 1) * 64;
        #pragma unroll
        for (int mi = 0; mi < 4; mi++)
            #pragma unroll
            for (int nj = 0; nj < 8; nj++)
                #pragma unroll
                for (int e = 0; e < 4; e++) acc[mi][nj][e] = 0.f;

        auto load_chunk = [&](int c, int s) {
            const int k0 = c * KC;
            const uint32_t stage = sb + 512 + s * STAGE_BYTES;
            #pragma unroll
            for (int i = 0; i < 16; i++) {
                int seg = i * 128 + tid;
                int op  = seg >> 10;
                int r   = (seg & 1023) >> 3;
                int cs  = seg & 7;
                uint32_t dst = stage + op * OP_BYTES + (uint32_t)(r * PITCHB + cs * 16);
                const __nv_bfloat16* src = (op == 0 ? Abase : Wbase)
                                           + (size_t)r * KW + k0 + cs * 8;
                cp_async_16(dst, src);
            }
        };

        load_chunk(0, 0); CP_COMMIT();
        load_chunk(1, 1); CP_COMMIT();

        for (int c = 0; c < NCHUNK; c++) {
            const int s = c % NSTAGE;
            CP_WAIT1();
            __syncthreads();
            int cn = c + 2;
            if (cn < NCHUNK) load_chunk(cn, cn % NSTAGE);
            CP_COMMIT();

            const uint32_t sA = sb + 512 + s * STAGE_BYTES;
            const uint32_t sW = sA + OP_BYTES;
            #pragma unroll
            for (int kk = 0; kk < 4; kk++) {
                uint32_t a[4][4];
                #pragma unroll
                for (int mi = 0; mi < 4; mi++) {
                    uint32_t addr = sA + (uint32_t)((m0w + mi * 16 + (lid & 15)) * PITCHB
                                     + kk * 32 + ((lid >> 4) << 4));
                    ldsm_x4(a[mi][0], a[mi][1], a[mi][2], a[mi][3], addr);
                }
                uint32_t b[8][2];
                #pragma unroll
                for (int ni = 0; ni < 4; ni++) {
                    uint32_t addr = sW + (uint32_t)((n0w + ni * 16 + (lid & 7)
                                     + ((lid >> 4) & 1) * 8) * PITCHB
                                     + kk * 32 + (((lid >> 3) & 1) << 4));
                    uint32_t r0, r1, r2, r3;
                    ldsm_x4(r0, r1, r2, r3, addr);
                    b[2 * ni][0] = r0; b[2 * ni][1] = r1;
                    b[2 * ni + 1][0] = r2; b[2 * ni + 1][1] = r3;
                }
                #pragma unroll
                for (int mi = 0; mi < 4; mi++)
                    #pragma unroll
                    for (int nj = 0; nj < 8; nj++)
                        mma16816(acc[mi][nj], a[mi], b[nj]);
            }
            __syncthreads();
        }
        CP_WAIT0();
    }
};

// ---------------------------------------------------------------------------
// Fused QKV projection GEMM over pre-compacted inputs.
// z=0: Q dense. z=1: K, z=2: V — rows already compacted; tiles past cnt exit;
// rows >= cnt in the boundary tile store ZEROS (replaces zero_tail kernel).
// ---------------------------------------------------------------------------
__global__ void __launch_bounds__(128, 2)
gemm_qkv(const __nv_bfloat16* __restrict__ A3, const __nv_bfloat16* __restrict__ W3,
         const float* __restrict__ bq, const float* __restrict__ bk,
         const float* __restrict__ bv, const int* __restrict__ cnt_,
         __nv_bfloat16* __restrict__ Qh, __nv_bfloat16* __restrict__ Ql,
         __nv_bfloat16* __restrict__ Kh, __nv_bfloat16* __restrict__ Kl,
         __nv_bfloat16* __restrict__ Vh, __nv_bfloat16* __restrict__ Vl)
{
    extern __shared__ char smem[];
    const uint32_t sb = smem_u32(smem);
    const int tid = threadIdx.x, wid = tid >> 5, lid = tid & 31;
    const int z = blockIdx.z;
    const int m0 = blockIdx.y * 128, n0 = blockIdx.x * 128;

    int cntb = SS;                    // dense for Q
    if (z > 0) {                      // compacted K/V: skip row tiles past cnt
        cntb = cnt_[m0 >> 11];
        if ((m0 & 2047) >= cntb) return;
    }

    const float* bias = (z == 0) ? bq : (z == 1) ? bk : bv;
    float* bias_s = (float*)smem;
    if (tid < 128) bias_s[tid] = bias[n0 + tid];

    __nv_bfloat16* H = (z == 0) ? Qh : (z == 1) ? Kh : Vh;
    __nv_bfloat16* L = (z == 0) ? Ql : (z == 1) ? Kl : Vl;

    GemmCore core;
    core.run(sb, tid, wid, lid,
             A3 + (size_t)z * MROWS * KW + (size_t)m0 * KW,
             W3 + (size_t)z * DF * KW + (size_t)n0 * KW);

    const int g = lid >> 2, t = lid & 3;
    #pragma unroll
    for (int mi = 0; mi < 4; mi++) {
        #pragma unroll
        for (int nj = 0; nj < 8; nj++) {
            int colrel = core.n0w + nj * 8 + 2 * t;
            int col = n0 + colrel;
            int hh = col >> 6, dh = col & 63;
            float c0 = core.acc[mi][nj][0] + bias_s[colrel];
            float c1 = core.acc[mi][nj][1] + bias_s[colrel + 1];
            float c2 = core.acc[mi][nj][2] + bias_s[colrel];
            float c3 = core.acc[mi][nj][3] + bias_s[colrel + 1];
            #pragma unroll
            for (int rr = 0; rr < 2; rr++) {
                int row = m0 + core.m0w + mi * 16 + g + rr * 8;
                int bb_ = row >> 11, sidx = row & 2047;
                size_t dst = ((size_t)(bb_ * NH + hh) * SS + sidx) * DH + dh;
                uint32_t hp = 0, lp = 0;
                if (sidx < cntb) {
                    if (rr == 0) split_pack(c0, c1, hp, lp);
                    else         split_pack(c2, c3, hp, lp);
                }
                *reinterpret_cast<uint32_t*>(H + dst) = hp;
                *reinterpret_cast<uint32_t*>(L + dst) = lp;
            }
        }
    }
}

// ---------------------------------------------------------------------------
// Output projection GEMM: fp32 out
// ---------------------------------------------------------------------------
__global__ void __launch_bounds__(128, 2)
gemm_out(const __nv_bfloat16* __restrict__ A3, const __nv_bfloat16* __restrict__ W3,
         const float* __restrict__ bias, float* __restrict__ C)
{
    extern __shared__ char smem[];
    const uint32_t sb = smem_u32(smem);
    const int tid = threadIdx.x, wid = tid >> 5, lid = tid & 31;
    const int m0 = blockIdx.y * 128, n0 = blockIdx.x * 128;

    float* bias_s = (float*)smem;
    if (tid < 128) bias_s[tid] = bias[n0 + tid];

    GemmCore core;
    core.run(sb, tid, wid, lid, A3 + (size_t)m0 * KW, W3 + (size_t)n0 * KW);

    const int g = lid >> 2, t = lid & 3;
    #pragma unroll
    for (int mi = 0; mi < 4; mi++) {
        #pragma unroll
        for (int nj = 0; nj < 8; nj++) {
            int colrel = core.n0w + nj * 8 + 2 * t;
            int col = n0 + colrel;
            int row0 = m0 + core.m0w + mi * 16 + g;
            float2 v0 = {core.acc[mi][nj][0] + bias_s[colrel],
                         core.acc[mi][nj][1] + bias_s[colrel + 1]};
            float2 v1 = {core.acc[mi][nj][2] + bias_s[colrel],
                         core.acc[mi][nj][3] + bias_s[colrel + 1]};
            *reinterpret_cast<float2*>(C + (size_t)row0 * DF + col) = v0;
            *reinterpret_cast<float2*>(C + (size_t)(row0 + 8) * DF + col) = v1;
        }
    }
}

// ---------------------------------------------------------------------------
// FlashAttention-2 on mma.sync over COMPACTED keys (R9 shape: 128 q/CTA,
// 8 warps x 16 q-rows — register-safe). Tail tile masked by index >= cnt.
// ---------------------------------------------------------------------------
__global__ void __launch_bounds__(256, 1)
attn_mma(const __nv_bfloat16* __restrict__ Qh_, const __nv_bfloat16* __restrict__ Ql_,
         const __nv_bfloat16* __restrict__ Kh_, const __nv_bfloat16* __restrict__ Kl_,
         const __nv_bfloat16* __restrict__ Vh_, const __nv_bfloat16* __restrict__ Vl_,
         const int* __restrict__ cnt_, __nv_bfloat16* __restrict__ A3out)
{
    extern __shared__ char smem[];
    const uint32_t sb = smem_u32(smem);
    const int tid = threadIdx.x, wid = tid >> 5, lid = tid & 31;
    const int g = lid >> 2, t4 = lid & 3;
    const int b = blockIdx.z, h = blockIdx.y;
    const int bh = b * NH + h;
    const int q0 = blockIdx.x * 128;
    const int m0w = wid * 16;
    const float SC = 0.03125f;

    const int cnt = cnt_[b];
    const int nt = (cnt + 63) >> 6;

    // ---- stage Q (hi,lo) through smem into register a-frags ----
    {
        const size_t qbase = ((size_t)bh * SS + q0);
        #pragma unroll
        for (int i = 0; i < 4; i++) {
            int seg = i * 256 + tid;
            int row = seg >> 3, cs = seg & 7;
            const size_t src = (qbase + row) * DH + cs * 8;
            uint32_t d = sb + (uint32_t)(row * PITCHB + cs * 16);
            cp_async_16(d,          Qh_ + src);
            cp_async_16(d + QL_OFF, Ql_ + src);
        }
    }
    CP_COMMIT(); CP_WAIT0(); __syncthreads();

    uint32_t qh[4][4], ql[4][4];
    #pragma unroll
    for (int kk = 0; kk < 4; kk++) {
        uint32_t a = sb + (uint32_t)((m0w + (lid & 15)) * PITCHB + kk * 32 + ((lid >> 4) << 4));
        ldsm_x4(qh[kk][0], qh[kk][1], qh[kk][2], qh[kk][3], a);
        ldsm_x4(ql[kk][0], ql[kk][1], ql[kk][2], ql[kk][3], a + QL_OFF);
    }
    __syncthreads();

    auto load_tile = [&](int ti, int st) {
        const uint32_t stage = sb + st * ASTRIDE;
        const size_t kbase = ((size_t)bh * SS + ti * 64);
        #pragma unroll
        for (int i = 0; i < 2; i++) {
            int seg = i * 256 + tid;
            int row = seg >> 3, cs = seg & 7;
            size_t src = (kbase + row) * DH + cs * 8;
            uint32_t d = stage + (uint32_t)(row * PITCHB + cs * 16);
            cp_async_16(d,             Kh_ + src);
            cp_async_16(d + ATILE,     Kl_ + src);
            cp_async_16(d + 2 * ATILE, Vh_ + src);
            cp_async_16(d + 3 * ATILE, Vl_ + src);
        }
    };

    float m0 = -1e30f, m1 = -1e30f, l0 = 0.f, l1 = 0.f;
    float o[8][4];
    #pragma unroll
    for (int nj = 0; nj < 8; nj++)
        #pragma unroll
        for (int e = 0; e < 4; e++) o[nj][e] = 0.f;

    if (0 < nt) load_tile(0, 0);
    CP_COMMIT();
    if (1 < nt) load_tile(1, 1);
    CP_COMMIT();

    for (int ti = 0; ti < nt; ti++) {
        const int st = ti % 3;
        CP_WAIT1();
        __syncthreads();
        if (ti + 2 < nt) load_tile(ti + 2, (ti + 2) % 3);
        CP_COMMIT();

        const uint32_t sK  = sb + st * ASTRIDE;
        const uint32_t sKl = sK + ATILE, sV = sK + 2 * ATILE, sVl = sK + 3 * ATILE;

        // ---- S = Qh Kh^T + Ql Kh^T + Qh Kl^T ----
        float s[8][4];
        #pragma unroll
        for (int nj = 0; nj < 8; nj++)
            #pragma unroll
            for (int e = 0; e < 4; e++) s[nj][e] = 0.f;

        #pragma unroll
        for (int kk = 0; kk < 4; kk++) {
            uint32_t kb[4][4];
            #pragma unroll
            for (int ni = 0; ni < 4; ni++) {
                uint32_t a = sK + (uint32_t)((ni * 16 + (lid & 7) + ((lid >> 4) & 1) * 8) * PITCHB
                             + kk * 32 + (((lid >> 3) & 1) << 4));
                ldsm_x4(kb[ni][0], kb[ni][1], kb[ni][2], kb[ni][3], a);
            }
            #pragma unroll
            for (int nj = 0; nj < 8; nj++) mma16816(s[nj], qh[kk], &kb[nj >> 1][(nj & 1) * 2]);
            #pragma unroll
            for (int nj = 0; nj < 8; nj++) mma16816(s[nj], ql[kk], &kb[nj >> 1][(nj & 1) * 2]);
            #pragma unroll
            for (int ni = 0; ni < 4; ni++) {
                uint32_t a = sKl + (uint32_t)((ni * 16 + (lid & 7) + ((lid >> 4) & 1) * 8) * PITCHB
                             + kk * 32 + (((lid >> 3) & 1) << 4));
                ldsm_x4(kb[ni][0], kb[ni][1], kb[ni][2], kb[ni][3], a);
            }
            #pragma unroll
            for (int nj = 0; nj < 8; nj++) mma16816(s[nj], qh[kk], &kb[nj >> 1][(nj & 1) * 2]);
        }

        // ---- scale + tail mask + online softmax ----
        const int kbase_idx = ti * 64;
        float tmax0 = -1e30f, tmax1 = -1e30f;
        #pragma unroll
        for (int nj = 0; nj < 8; nj++) {
            int k0i = kbase_idx + nj * 8 + 2 * t4;
            bool v0 = k0i < cnt, v1 = (k0i + 1) < cnt;
            float s0 = v0 ? s[nj][0] * SC : -1e9f;
            float s1 = v1 ? s[nj][1] * SC : -1e9f;
            float s2 = v0 ? s[nj][2] * SC : -1e9f;
            float s3 = v1 ? s[nj][3] * SC : -1e9f;
            s[nj][0] = s0; s[nj][1] = s1; s[nj][2] = s2; s[nj][3] = s3;
            tmax0 = fmaxf(tmax0, fmaxf(s0, s1));
            tmax1 = fmaxf(tmax1, fmaxf(s2, s3));
        }
        tmax0 = fmaxf(tmax0, __shfl_xor_sync(0xffffffffu, tmax0, 1));
        tmax0 = fmaxf(tmax0, __shfl_xor_sync(0xffffffffu, tmax0, 2));
        tmax1 = fmaxf(tmax1, __shfl_xor_sync(0xffffffffu, tmax1, 1));
        tmax1 = fmaxf(tmax1, __shfl_xor_sync(0xffffffffu, tmax1, 2));

        float mn0 = fmaxf(m0, tmax0), mn1 = fmaxf(m1, tmax1);
        float sc0 = __expf(m0 - mn0), sc1 = __expf(m1 - mn1);
        m0 = mn0; m1 = mn1;
        l0 *= sc0; l1 *= sc1;
        #pragma unroll
        for (int nj = 0; nj < 8; nj++) {
            o[nj][0] *= sc0; o[nj][1] *= sc0;
            o[nj][2] *= sc1; o[nj][3] *= sc1;
        }
        #pragma unroll
        for (int nj = 0; nj < 8; nj++) {
            float p0 = __expf(s[nj][0] - m0);
            float p1 = __expf(s[nj][1] - m0);
            float p2 = __expf(s[nj][2] - m1);
            float p3 = __expf(s[nj][3] - m1);
            s[nj][0] = p0; s[nj][1] = p1; s[nj][2] = p2; s[nj][3] = p3;
            l0 += p0 + p1; l1 += p2 + p3;
        }

        // ---- O += Ph Vh + Pl Vh + Ph Vl ----
        #pragma unroll
        for (int kk = 0; kk < 4; kk++) {
            uint32_t ah[4], al[4];
            split_pack(s[2 * kk][0],     s[2 * kk][1],     ah[0], al[0]);
            split_pack(s[2 * kk][2],     s[2 * kk][3],     ah[1], al[1]);
            split_pack(s[2 * kk + 1][0], s[2 * kk + 1][1], ah[2], al[2]);
            split_pack(s[2 * kk + 1][2], s[2 * kk + 1][3], ah[3], al[3]);

            uint32_t vb[4][4];
            #pragma unroll
            for (int njp = 0; njp < 4; njp++) {
                uint32_t a = sV + (uint32_t)((16 * kk + (lid & 7) + ((lid >> 3) & 1) * 8) * PITCHB
                             + (16 * njp + ((lid >> 4) & 1) * 8) * 2);
                ldsm_x4_t(vb[njp][0], vb[njp][1], vb[njp][2], vb[njp][3], a);
            }
            #pragma unroll
            for (int nj = 0; nj < 8; nj++) mma16816(o[nj], ah, &vb[nj >> 1][(nj & 1) * 2]);
            #pragma unroll
            for (int nj = 0; nj < 8; nj++) mma16816(o[nj], al, &vb[nj >> 1][(nj & 1) * 2]);
            #pragma unroll
            for (int njp = 0; njp < 4; njp++) {
                uint32_t a = sVl + (uint32_t)((16 * kk + (lid & 7) + ((lid >> 3) & 1) * 8) * PITCHB
                             + (16 * njp + ((lid >> 4) & 1) * 8) * 2);
                ldsm_x4_t(vb[njp][0], vb[njp][1], vb[njp][2], vb[njp][3], a);
            }
            #pragma unroll
            for (int nj = 0; nj < 8; nj++) mma16816(o[nj], ah, &vb[nj >> 1][(nj & 1) * 2]);
        }
        __syncthreads();
    }
    CP_WAIT0();

    // ---- finalize + write split bf16 straight into A3 [hi|lo|hi] ----
    l0 += __shfl_xor_sync(0xffffffffu, l0, 1);
    l0 += __shfl_xor_sync(0xffffffffu, l0, 2);
    l1 += __shfl_xor_sync(0xffffffffu, l1, 1);
    l1 += __shfl_xor_sync(0xffffffffu, l1, 2);
    float inv0 = 1.f / l0, inv1 = 1.f / l1;

    const int srow = q0 + m0w + g;
    size_t r0 = (size_t)(b * SS + srow) * KW;
    size_t r1 = r0 + (size_t)8 * KW;
    const int colbase = h * DH;

    #pragma unroll
    for (int nj = 0; nj < 8; nj++) {
        int c = colbase + nj * 8 + 2 * t4;
        uint32_t hp, lp;
        split_pack(o[nj][0] * inv0, o[nj][1] * inv0, hp, lp);
        *reinterpret_cast<uint32_t*>(A3out + r0 + c)        = hp;
        *reinterpret_cast<uint32_t*>(A3out + r0 + 1024 + c) = lp;
        *reinterpret_cast<uint32_t*>(A3out + r0 + 2048 + c) = hp;
        split_pack(o[nj][2] * inv1, o[nj][3] * inv1, hp, lp);
        *reinterpret_cast<uint32_t*>(A3out + r1 + c)        = hp;
        *reinterpret_cast<uint32_t*>(A3out + r1 + 1024 + c) = lp;
        *reinterpret_cast<uint32_t*>(A3out + r1 + 2048 + c) = hp;
    }
}

// ---------------------------------------------------------------------------
// launch
// ---------------------------------------------------------------------------
extern "C" void kernel_launch(void* const* d_in, const int* in_sizes, int n_in,
                              void* d_out, int out_size)
{
    const float* Q    = (const float*)d_in[0];
    const float* K    = (const float*)d_in[1];
    const float* V    = (const float*)d_in[2];
    const int*   mask = (const int*)  d_in[3];
    const float* Wq   = (const float*)d_in[4];
    const float* bq   = (const float*)d_in[5];
    const float* Wk   = (const float*)d_in[6];
    const float* bk   = (const float*)d_in[7];
    const float* Wv   = (const float*)d_in[8];
    const float* bv   = (const float*)d_in[9];
    const float* Wo   = (const float*)d_in[10];
    const float* bo   = (const float*)d_in[11];
    float* out = (float*)d_out;

    __nv_bfloat16 *A3, *W3, *Qh, *Ql, *Kh, *Kl, *Vh, *Vl;
    int *pos, *cnt;
    cudaGetSymbolAddress((void**)&A3, g_A3v3);
    cudaGetSymbolAddress((void**)&W3, g_W3v4);
    cudaGetSymbolAddress((void**)&Qh, g_Qh);
    cudaGetSymbolAddress((void**)&Ql, g_Ql);
    cudaGetSymbolAddress((void**)&Kh, g_Kh);
    cudaGetSymbolAddress((void**)&Kl, g_Kl);
    cudaGetSymbolAddress((void**)&Vh, g_Vh);
    cudaGetSymbolAddress((void**)&Vl, g_Vl);
    cudaGetSymbolAddress((void**)&pos, g_pos);
    cudaGetSymbolAddress((void**)&cnt, g_cnt);

    cudaFuncSetAttribute(gemm_qkv, cudaFuncAttributeMaxDynamicSharedMemorySize, GEMM_SMEM);
    cudaFuncSetAttribute(gemm_out, cudaFuncAttributeMaxDynamicSharedMemorySize, GEMM_SMEM);
    cudaFuncSetAttribute(attn_mma, cudaFuncAttributeMaxDynamicSharedMemorySize, ATTN_SMEM);

    mask_scan<<<BB, 256>>>(mask, pos, cnt);
    conv_w<<<dim3(DF * DF / 1024, 4), 256>>>(Wq, Wk, Wv, Wo, W3);
    conv_in<<<dim3(MROWS * DF / 1024, 3), 256>>>(Q, K, V, mask, pos, A3);

    gemm_qkv<<<dim3(DF / 128, MROWS / 128, 3), 128, GEMM_SMEM>>>(
        A3, W3, bq, bk, bv, cnt, Qh, Ql, Kh, Kl, Vh, Vl);

    attn_mma<<<dim3(SS / 128, NH, BB), 256, ATTN_SMEM>>>(Qh, Ql, Kh, Kl, Vh, Vl, cnt, A3);

    gemm_out<<<dim3(DF / 128, MROWS / 128), 128, GEMM_SMEM>>>(
        A3, W3 + (size_t)3 * DF * KW, bo, out);
}

// round 12
// speedup vs baseline: 1.4955x; 1.0049x over previous
#include <cuda_runtime.h>
#include <cuda_bf16.h>
#include <cstdint>

#define DF 1024
#define NH 16
#define DH 64
#define BB 2
#define SS 2048
#define MROWS (BB*SS)

#define KW   3072              // split-K width (3 * 1024)
#define KC   64                // bf16 K per SMEM chunk
#define NCHUNK (KW / KC)       // 48
#define NSTAGE 3
#define PITCH  72
#define PITCHB 144
#define OP_BYTES (128 * PITCHB)             // 18432
#define STAGE_BYTES (2 * OP_BYTES)          // 36864
#define GEMM_SMEM (512 + NSTAGE * STAGE_BYTES)  // 111104

// attention smem (128 q-rows staged, Ql at +18432)
#define ATILE   9216                       // one 64x64 bf16 tile, pitch 144
#define ASTRIDE (4 * ATILE + 256)          // Kh,Kl,Vh,Vl = 37120
#define QL_OFF  18432
#define ATTN_SMEM (3 * ASTRIDE)            // 111360

// ---------------------------------------------------------------------------
// Scratch
// ---------------------------------------------------------------------------
__device__ __nv_bfloat16 g_A3v3[3][(size_t)MROWS * KW];  // activations, split [hi|lo|hi]
__device__ __nv_bfloat16 g_W3v4[4][(size_t)DF * KW];     // weights,     split [hi|hi|lo]
__device__ __nv_bfloat16 g_Qh[(size_t)BB * NH * SS * DH];
__device__ __nv_bfloat16 g_Ql[(size_t)BB * NH * SS * DH];
__device__ __nv_bfloat16 g_Kh[(size_t)BB * NH * SS * DH];
__device__ __nv_bfloat16 g_Kl[(size_t)BB * NH * SS * DH];
__device__ __nv_bfloat16 g_Vh[(size_t)BB * NH * SS * DH];
__device__ __nv_bfloat16 g_Vl[(size_t)BB * NH * SS * DH];
__device__ int g_pos[BB * SS];
__device__ int g_cnt[BB];

// ---------------------------------------------------------------------------
// helpers
// ---------------------------------------------------------------------------
__device__ __forceinline__ uint32_t smem_u32(const void* p) {
    uint32_t a;
    asm("{ .reg .u64 t; cvta.to.shared.u64 t, %1; cvt.u32.u64 %0, t; }"
        : "=r"(a) : "l"(p));
    return a;
}

__device__ __forceinline__ void cp_async_16(uint32_t dst, const void* src) {
    asm volatile("cp.async.cg.shared.global [%0], [%1], 16;" :: "r"(dst), "l"(src) : "memory");
}
#define CP_COMMIT() asm volatile("cp.async.commit_group;" ::: "memory")
#define CP_WAIT1()  asm volatile("cp.async.wait_group 1;" ::: "memory")
#define CP_WAIT0()  asm volatile("cp.async.wait_group 0;" ::: "memory")

__device__ __forceinline__ void ldsm_x4(uint32_t& r0, uint32_t& r1, uint32_t& r2,
                                        uint32_t& r3, uint32_t addr) {
    asm volatile("ldmatrix.sync.aligned.m8n8.x4.shared.b16 {%0,%1,%2,%3}, [%4];"
                 : "=r"(r0), "=r"(r1), "=r"(r2), "=r"(r3) : "r"(addr));
}
__device__ __forceinline__ void ldsm_x4_t(uint32_t& r0, uint32_t& r1, uint32_t& r2,
                                          uint32_t& r3, uint32_t addr) {
    asm volatile("ldmatrix.sync.aligned.m8n8.x4.trans.shared.b16 {%0,%1,%2,%3}, [%4];"
                 : "=r"(r0), "=r"(r1), "=r"(r2), "=r"(r3) : "r"(addr));
}

__device__ __forceinline__ void mma16816(float* d, const uint32_t* a, const uint32_t* b) {
    asm volatile(
        "mma.sync.aligned.m16n8k16.row.col.f32.bf16.bf16.f32 "
        "{%0,%1,%2,%3}, {%4,%5,%6,%7}, {%8,%9}, {%0,%1,%2,%3};"
        : "+f"(d[0]), "+f"(d[1]), "+f"(d[2]), "+f"(d[3])
        : "r"(a[0]), "r"(a[1]), "r"(a[2]), "r"(a[3]), "r"(b[0]), "r"(b[1]));
}

__device__ __forceinline__ void split_pack(float x, float y, uint32_t& hp, uint32_t& lp) {
    uint32_t ux = __float_as_uint(x), uy = __float_as_uint(y);
    hp = __byte_perm(ux, uy, 0x7632);
    float lx = x - __uint_as_float(ux & 0xffff0000u);
    float ly = y - __uint_as_float(uy & 0xffff0000u);
    __nv_bfloat162 l2 = __floats2bfloat162_rn(lx, ly);
    lp = *reinterpret_cast<uint32_t*>(&l2);
}

// ---------------------------------------------------------------------------
// mask prefix scan: pos[b][s] = #valid keys before s ; cnt[b] = total valid
// ---------------------------------------------------------------------------
__global__ __launch_bounds__(256) void mask_scan(const int* __restrict__ mask,
                                                 int* __restrict__ pos, int* __restrict__ cnt)
{
    __shared__ int partial[256];
    const int b = blockIdx.x, tid = threadIdx.x;
    const int base = b * SS + tid * 8;
    int v[8], s = 0;
    #pragma unroll
    for (int i = 0; i < 8; i++) { v[i] = (mask[base + i] != 0); s += v[i]; }
    partial[tid] = s;
    __syncthreads();
    for (int off = 1; off < 256; off <<= 1) {
        int t = (tid >= off) ? partial[tid - off] : 0;
        __syncthreads();
        partial[tid] += t;
        __syncthreads();
    }
    int ex = (tid == 0) ? 0 : partial[tid - 1];
    #pragma unroll
    for (int i = 0; i < 8; i++) { pos[base + i] = ex; ex += v[i]; }
    if (tid == 255) cnt[b] = partial[255];
}

// ---------------------------------------------------------------------------
// Split-bf16 conversions. conv_in: z=0 Q dense; z=1 K, z=2 V with row
// compaction (valid rows gathered to pos[r], masked rows skipped).
// ---------------------------------------------------------------------------
__global__ __launch_bounds__(256) void conv_in(const float* __restrict__ Q,
                                               const float* __restrict__ K,
                                               const float* __restrict__ V,
                                               const int* __restrict__ mask,
                                               const int* __restrict__ pos,
                                               __nv_bfloat16* __restrict__ A3)
{
    const int z = blockIdx.y;
    const float* X = z == 0 ? Q : (z == 1 ? K : V);
    __nv_bfloat16* Y = A3 + (size_t)z * MROWS * KW;
    int idx = (blockIdx.x * 256 + threadIdx.x) * 4;
    int r = idx >> 10, k = idx & 1023;
    int rr = r;
    if (z > 0) {
        int bb_ = r >> 11, sidx = r & 2047;
        if (mask[bb_ * SS + sidx] == 0) return;       // masked key row: skip
        rr = bb_ * SS + pos[bb_ * SS + sidx];         // compacted destination
    }
    float4 x = *reinterpret_cast<const float4*>(X + idx);
    float v[4] = {x.x, x.y, x.z, x.w};
    __nv_bfloat16 hi[4], lo[4];
    #pragma unroll
    for (int i = 0; i < 4; i++) {
        hi[i] = __float2bfloat16(v[i]);
        lo[i] = __float2bfloat16(v[i] - __bfloat162float(hi[i]));
    }
    uint64_t hip, lop;
    memcpy(&hip, hi, 8);
    memcpy(&lop, lo, 8);
    size_t base = (size_t)rr * KW + k;
    *reinterpret_cast<uint64_t*>(Y + base)        = hip;
    *reinterpret_cast<uint64_t*>(Y + base + 1024) = lop;
    *reinterpret_cast<uint64_t*>(Y + base + 2048) = hip;
}

__global__ __launch_bounds__(256) void conv_w(const float* __restrict__ Wq,
                                              const float* __restrict__ Wk,
                                              const float* __restrict__ Wv,
                                              const float* __restrict__ Wo,
                                              __nv_bfloat16* __restrict__ W3)
{
    const float* X = blockIdx.y == 0 ? Wq : (blockIdx.y == 1 ? Wk :
                      (blockIdx.y == 2 ? Wv : Wo));
    __nv_bfloat16* Y = W3 + (size_t)blockIdx.y * DF * KW;
    int idx = (blockIdx.x * 256 + threadIdx.x) * 4;
    float4 x = *reinterpret_cast<const float4*>(X + idx);
    float v[4] = {x.x, x.y, x.z, x.w};
    __nv_bfloat16 hi[4], lo[4];
    #pragma unroll
    for (int i = 0; i < 4; i++) {
        hi[i] = __float2bfloat16(v[i]);
        lo[i] = __float2bfloat16(v[i] - __bfloat162float(hi[i]));
    }
    uint64_t hip, lop;
    memcpy(&hip, hi, 8);
    memcpy(&lop, lo, 8);
    int r = idx >> 10, k = idx & 1023;
    size_t base = (size_t)r * KW + k;
    *reinterpret_cast<uint64_t*>(Y + base)        = hip;
    *reinterpret_cast<uint64_t*>(Y + base + 1024) = hip;
    *reinterpret_cast<uint64_t*>(Y + base + 2048) = lop;
}

// ---------------------------------------------------------------------------
// GEMM mainloop body: 128 threads / 4 warps (2M x 2N), warp tile 64x64.
// ONE barrier per chunk: the top sync (post cp.async.wait) already proves all
// threads finished the previous chunk's reads before stage reuse.
// ---------------------------------------------------------------------------
struct GemmCore {
    float acc[4][8][4];
    int m0w, n0w;

    __device__ __forceinline__ void run(uint32_t sb, int tid, int wid, int lid,
                                        const __nv_bfloat16* Abase,
                                        const __nv_bfloat16* Wbase) {
        m0w = (wid & 1) * 64;
        n0w = (wid >> 1) * 64;
        #pragma unroll
        for (int mi = 0; mi < 4; mi++)
            #pragma unroll
            for (int nj = 0; nj < 8; nj++)
                #pragma unroll
                for (int e = 0; e < 4; e++) acc[mi][nj][e] = 0.f;

        auto load_chunk = [&](int c, int s) {
            const int k0 = c * KC;
            const uint32_t stage = sb + 512 + s * STAGE_BYTES;
            #pragma unroll
            for (int i = 0; i < 16; i++) {
                int seg = i * 128 + tid;
                int op  = seg >> 10;
                int r   = (seg & 1023) >> 3;
                int cs  = seg & 7;
                uint32_t dst = stage + op * OP_BYTES + (uint32_t)(r * PITCHB + cs * 16);
                const __nv_bfloat16* src = (op == 0 ? Abase : Wbase)
                                           + (size_t)r * KW + k0 + cs * 8;
                cp_async_16(dst, src);
            }
        };

        load_chunk(0, 0); CP_COMMIT();
        load_chunk(1, 1); CP_COMMIT();

        for (int c = 0; c < NCHUNK; c++) {
            const int s = c % NSTAGE;
            CP_WAIT1();
            __syncthreads();                    // sole barrier per chunk
            int cn = c + 2;
            if (cn < NCHUNK) load_chunk(cn, cn % NSTAGE);
            CP_COMMIT();

            const uint32_t sA = sb + 512 + s * STAGE_BYTES;
            const uint32_t sW = sA + OP_BYTES;
            #pragma unroll
            for (int kk = 0; kk < 4; kk++) {
                uint32_t a[4][4];
                #pragma unroll
                for (int mi = 0; mi < 4; mi++) {
                    uint32_t addr = sA + (uint32_t)((m0w + mi * 16 + (lid & 15)) * PITCHB
                                     + kk * 32 + ((lid >> 4) << 4));
                    ldsm_x4(a[mi][0], a[mi][1], a[mi][2], a[mi][3], addr);
                }
                uint32_t b[8][2];
                #pragma unroll
                for (int ni = 0; ni < 4; ni++) {
                    uint32_t addr = sW + (uint32_t)((n0w + ni * 16 + (lid & 7)
                                     + ((lid >> 4) & 1) * 8) * PITCHB
                                     + kk * 32 + (((lid >> 3) & 1) << 4));
                    uint32_t r0, r1, r2, r3;
                    ldsm_x4(r0, r1, r2, r3, addr);
                    b[2 * ni][0] = r0; b[2 * ni][1] = r1;
                    b[2 * ni + 1][0] = r2; b[2 * ni + 1][1] = r3;
                }
                #pragma unroll
                for (int mi = 0; mi < 4; mi++)
                    #pragma unroll
                    for (int nj = 0; nj < 8; nj++)
                        mma16816(acc[mi][nj], a[mi], b[nj]);
            }
        }
        CP_WAIT0();
    }
};

// ---------------------------------------------------------------------------
// Fused QKV projection GEMM over pre-compacted inputs.
// z=0: Q dense. z=1: K, z=2: V — rows already compacted; tiles past cnt exit;
// rows >= cnt in the boundary tile store ZEROS (tail guard).
// ---------------------------------------------------------------------------
__global__ void __launch_bounds__(128, 2)
gemm_qkv(const __nv_bfloat16* __restrict__ A3, const __nv_bfloat16* __restrict__ W3,
         const float* __restrict__ bq, const float* __restrict__ bk,
         const float* __restrict__ bv, const int* __restrict__ cnt_,
         __nv_bfloat16* __restrict__ Qh, __nv_bfloat16* __restrict__ Ql,
         __nv_bfloat16* __restrict__ Kh, __nv_bfloat16* __restrict__ Kl,
         __nv_bfloat16* __restrict__ Vh, __nv_bfloat16* __restrict__ Vl)
{
    extern __shared__ char smem[];
    const uint32_t sb = smem_u32(smem);
    const int tid = threadIdx.x, wid = tid >> 5, lid = tid & 31;
    const int z = blockIdx.z;
    const int m0 = blockIdx.y * 128, n0 = blockIdx.x * 128;

    int cntb = SS;                    // dense for Q
    if (z > 0) {                      // compacted K/V: skip row tiles past cnt
        cntb = cnt_[m0 >> 11];
        if ((m0 & 2047) >= cntb) return;
    }

    const float* bias = (z == 0) ? bq : (z == 1) ? bk : bv;
    float* bias_s = (float*)smem;
    if (tid < 128) bias_s[tid] = bias[n0 + tid];

    __nv_bfloat16* H = (z == 0) ? Qh : (z == 1) ? Kh : Vh;
    __nv_bfloat16* L = (z == 0) ? Ql : (z == 1) ? Kl : Vl;

    GemmCore core;
    core.run(sb, tid, wid, lid,
             A3 + (size_t)z * MROWS * KW + (size_t)m0 * KW,
             W3 + (size_t)z * DF * KW + (size_t)n0 * KW);

    const int g = lid >> 2, t = lid & 3;
    #pragma unroll
    for (int mi = 0; mi < 4; mi++) {
        #pragma unroll
        for (int nj = 0; nj < 8; nj++) {
            int colrel = core.n0w + nj * 8 + 2 * t;
            int col = n0 + colrel;
            int hh = col >> 6, dh = col & 63;
            float c0 = core.acc[mi][nj][0] + bias_s[colrel];
            float c1 = core.acc[mi][nj][1] + bias_s[colrel + 1];
            float c2 = core.acc[mi][nj][2] + bias_s[colrel];
            float c3 = core.acc[mi][nj][3] + bias_s[colrel + 1];
            #pragma unroll
            for (int rr = 0; rr < 2; rr++) {
                int row = m0 + core.m0w + mi * 16 + g + rr * 8;
                int bb_ = row >> 11, sidx = row & 2047;
                size_t dst = ((size_t)(bb_ * NH + hh) * SS + sidx) * DH + dh;
                uint32_t hp = 0, lp = 0;
                if (sidx < cntb) {
                    if (rr == 0) split_pack(c0, c1, hp, lp);
                    else         split_pack(c2, c3, hp, lp);
                }
                *reinterpret_cast<uint32_t*>(H + dst) = hp;
                *reinterpret_cast<uint32_t*>(L + dst) = lp;
            }
        }
    }
}

// ---------------------------------------------------------------------------
// Output projection GEMM: fp32 out
// ---------------------------------------------------------------------------
__global__ void __launch_bounds__(128, 2)
gemm_out(const __nv_bfloat16* __restrict__ A3, const __nv_bfloat16* __restrict__ W3,
         const float* __restrict__ bias, float* __restrict__ C)
{
    extern __shared__ char smem[];
    const uint32_t sb = smem_u32(smem);
    const int tid = threadIdx.x, wid = tid >> 5, lid = tid & 31;
    const int m0 = blockIdx.y * 128, n0 = blockIdx.x * 128;

    float* bias_s = (float*)smem;
    if (tid < 128) bias_s[tid] = bias[n0 + tid];

    GemmCore core;
    core.run(sb, tid, wid, lid, A3 + (size_t)m0 * KW, W3 + (size_t)n0 * KW);

    const int g = lid >> 2, t = lid & 3;
    #pragma unroll
    for (int mi = 0; mi < 4; mi++) {
        #pragma unroll
        for (int nj = 0; nj < 8; nj++) {
            int colrel = core.n0w + nj * 8 + 2 * t;
            int col = n0 + colrel;
            int row0 = m0 + core.m0w + mi * 16 + g;
            float2 v0 = {core.acc[mi][nj][0] + bias_s[colrel],
                         core.acc[mi][nj][1] + bias_s[colrel + 1]};
            float2 v1 = {core.acc[mi][nj][2] + bias_s[colrel],
                         core.acc[mi][nj][3] + bias_s[colrel + 1]};
            *reinterpret_cast<float2*>(C + (size_t)row0 * DF + col) = v0;
            *reinterpret_cast<float2*>(C + (size_t)(row0 + 8) * DF + col) = v1;
        }
    }
}

// ---------------------------------------------------------------------------
// FlashAttention-2 on mma.sync over COMPACTED keys (128 q/CTA, 8 warps x 16
// q-rows). One barrier per key-tile; Kl/Vl ldsm hoisted for latency overlap.
// ---------------------------------------------------------------------------
__global__ void __launch_bounds__(256, 1)
attn_mma(const __nv_bfloat16* __restrict__ Qh_, const __nv_bfloat16* __restrict__ Ql_,
         const __nv_bfloat16* __restrict__ Kh_, const __nv_bfloat16* __restrict__ Kl_,
         const __nv_bfloat16* __restrict__ Vh_, const __nv_bfloat16* __restrict__ Vl_,
         const int* __restrict__ cnt_, __nv_bfloat16* __restrict__ A3out)
{
    extern __shared__ char smem[];
    const uint32_t sb = smem_u32(smem);
    const int tid = threadIdx.x, wid = tid >> 5, lid = tid & 31;
    const int g = lid >> 2, t4 = lid & 3;
    const int b = blockIdx.z, h = blockIdx.y;
    const int bh = b * NH + h;
    const int q0 = blockIdx.x * 128;
    const int m0w = wid * 16;
    const float SC = 0.03125f;

    const int cnt = cnt_[b];
    const int nt = (cnt + 63) >> 6;

    // ---- stage Q (hi,lo) through smem into register a-frags ----
    {
        const size_t qbase = ((size_t)bh * SS + q0);
        #pragma unroll
        for (int i = 0; i < 4; i++) {
            int seg = i * 256 + tid;
            int row = seg >> 3, cs = seg & 7;
            const size_t src = (qbase + row) * DH + cs * 8;
            uint32_t d = sb + (uint32_t)(row * PITCHB + cs * 16);
            cp_async_16(d,          Qh_ + src);
            cp_async_16(d + QL_OFF, Ql_ + src);
        }
    }
    CP_COMMIT(); CP_WAIT0(); __syncthreads();

    uint32_t qh[4][4], ql[4][4];
    #pragma unroll
    for (int kk = 0; kk < 4; kk++) {
        uint32_t a = sb + (uint32_t)((m0w + (lid & 15)) * PITCHB + kk * 32 + ((lid >> 4) << 4));
        ldsm_x4(qh[kk][0], qh[kk][1], qh[kk][2], qh[kk][3], a);
        ldsm_x4(ql[kk][0], ql[kk][1], ql[kk][2], ql[kk][3], a + QL_OFF);
    }
    __syncthreads();

    auto load_tile = [&](int ti, int st) {
        const uint32_t stage = sb + st * ASTRIDE;
        const size_t kbase = ((size_t)bh * SS + ti * 64);
        #pragma unroll
        for (int i = 0; i < 2; i++) {
            int seg = i * 256 + tid;
            int row = seg >> 3, cs = seg & 7;
            size_t src = (kbase + row) * DH + cs * 8;
            uint32_t d = stage + (uint32_t)(row * PITCHB + cs * 16);
            cp_async_16(d,             Kh_ + src);
            cp_async_16(d + ATILE,     Kl_ + src);
            cp_async_16(d + 2 * ATILE, Vh_ + src);
            cp_async_16(d + 3 * ATILE, Vl_ + src);
        }
    };

    float m0 = -1e30f, m1 = -1e30f, l0 = 0.f, l1 = 0.f;
    float o[8][4];
    #pragma unroll
    for (int nj = 0; nj < 8; nj++)
        #pragma unroll
        for (int e = 0; e < 4; e++) o[nj][e] = 0.f;

    if (0 < nt) load_tile(0, 0);
    CP_COMMIT();
    if (1 < nt) load_tile(1, 1);
    CP_COMMIT();

    for (int ti = 0; ti < nt; ti++) {
        const int st = ti % 3;
        CP_WAIT1();
        __syncthreads();                        // sole barrier per tile
        if (ti + 2 < nt) load_tile(ti + 2, (ti + 2) % 3);
        CP_COMMIT();

        const uint32_t sK  = sb + st * ASTRIDE;
        const uint32_t sKl = sK + ATILE, sV = sK + 2 * ATILE, sVl = sK + 3 * ATILE;

        // ---- S = Qh Kh^T + Ql Kh^T + Qh Kl^T (Kl ldsm hoisted) ----
        float s[8][4];
        #pragma unroll
        for (int nj = 0; nj < 8; nj++)
            #pragma unroll
            for (int e = 0; e < 4; e++) s[nj][e] = 0.f;

        #pragma unroll
        for (int kk = 0; kk < 4; kk++) {
            uint32_t kb[4][4], kb2[4][4];
            #pragma unroll
            for (int ni = 0; ni < 4; ni++) {
                uint32_t a = sK + (uint32_t)((ni * 16 + (lid & 7) + ((lid >> 4) & 1) * 8) * PITCHB
                             + kk * 32 + (((lid >> 3) & 1) << 4));
                ldsm_x4(kb[ni][0], kb[ni][1], kb[ni][2], kb[ni][3], a);
            }
            #pragma unroll
            for (int nj = 0; nj < 8; nj++) mma16816(s[nj], qh[kk], &kb[nj >> 1][(nj & 1) * 2]);
            #pragma unroll
            for (int ni = 0; ni < 4; ni++) {
                uint32_t a = sKl + (uint32_t)((ni * 16 + (lid & 7) + ((lid >> 4) & 1) * 8) * PITCHB
                             + kk * 32 + (((lid >> 3) & 1) << 4));
                ldsm_x4(kb2[ni][0], kb2[ni][1], kb2[ni][2], kb2[ni][3], a);
            }
            #pragma unroll
            for (int nj = 0; nj < 8; nj++) mma16816(s[nj], ql[kk], &kb[nj >> 1][(nj & 1) * 2]);
            #pragma unroll
            for (int nj = 0; nj < 8; nj++) mma16816(s[nj], qh[kk], &kb2[nj >> 1][(nj & 1) * 2]);
        }

        // ---- scale + tail mask + online softmax ----
        const int kbase_idx = ti * 64;
        float tmax0 = -1e30f, tmax1 = -1e30f;
        #pragma unroll
        for (int nj = 0; nj < 8; nj++) {
            int k0i = kbase_idx + nj * 8 + 2 * t4;
            bool v0 = k0i < cnt, v1 = (k0i + 1) < cnt;
            float s0 = v0 ? s[nj][0] * SC : -1e9f;
            float s1 = v1 ? s[nj][1] * SC : -1e9f;
            float s2 = v0 ? s[nj][2] * SC : -1e9f;
            float s3 = v1 ? s[nj][3] * SC : -1e9f;
            s[nj][0] = s0; s[nj][1] = s1; s[nj][2] = s2; s[nj][3] = s3;
            tmax0 = fmaxf(tmax0, fmaxf(s0, s1));
            tmax1 = fmaxf(tmax1, fmaxf(s2, s3));
        }
        tmax0 = fmaxf(tmax0, __shfl_xor_sync(0xffffffffu, tmax0, 1));
        tmax0 = fmaxf(tmax0, __shfl_xor_sync(0xffffffffu, tmax0, 2));
        tmax1 = fmaxf(tmax1, __shfl_xor_sync(0xffffffffu, tmax1, 1));
        tmax1 = fmaxf(tmax1, __shfl_xor_sync(0xffffffffu, tmax1, 2));

        float mn0 = fmaxf(m0, tmax0), mn1 = fmaxf(m1, tmax1);
        float sc0 = __expf(m0 - mn0), sc1 = __expf(m1 - mn1);
        m0 = mn0; m1 = mn1;
        l0 *= sc0; l1 *= sc1;
        #pragma unroll
        for (int nj = 0; nj < 8; nj++) {
            o[nj][0] *= sc0; o[nj][1] *= sc0;
            o[nj][2] *= sc1; o[nj][3] *= sc1;
        }
        #pragma unroll
        for (int nj = 0; nj < 8; nj++) {
            float p0 = __expf(s[nj][0] - m0);
            float p1 = __expf(s[nj][1] - m0);
            float p2 = __expf(s[nj][2] - m1);
            float p3 = __expf(s[nj][3] - m1);
            s[nj][0] = p0; s[nj][1] = p1; s[nj][2] = p2; s[nj][3] = p3;
            l0 += p0 + p1; l1 += p2 + p3;
        }

        // ---- O += Ph Vh + Pl Vh + Ph Vl (Vl ldsm hoisted) ----
        #pragma unroll
        for (int kk = 0; kk < 4; kk++) {
            uint32_t ah[4], al[4];
            split_pack(s[2 * kk][0],     s[2 * kk][1],     ah[0], al[0]);
            split_pack(s[2 * kk][2],     s[2 * kk][3],     ah[1], al[1]);
            split_pack(s[2 * kk + 1][0], s[2 * kk + 1][1], ah[2], al[2]);
            split_pack(s[2 * kk + 1][2], s[2 * kk + 1][3], ah[3], al[3]);

            uint32_t vb[4][4], vb2[4][4];
            #pragma unroll
            for (int njp = 0; njp < 4; njp++) {
                uint32_t a = sV + (uint32_t)((16 * kk + (lid & 7) + ((lid >> 3) & 1) * 8) * PITCHB
                             + (16 * njp + ((lid >> 4) & 1) * 8) * 2);
                ldsm_x4_t(vb[njp][0], vb[njp][1], vb[njp][2], vb[njp][3], a);
            }
            #pragma unroll
            for (int nj = 0; nj < 8; nj++) mma16816(o[nj], ah, &vb[nj >> 1][(nj & 1) * 2]);
            #pragma unroll
            for (int njp = 0; njp < 4; njp++) {
                uint32_t a = sVl + (uint32_t)((16 * kk + (lid & 7) + ((lid >> 3) & 1) * 8) * PITCHB
                             + (16 * njp + ((lid >> 4) & 1) * 8) * 2);
                ldsm_x4_t(vb2[njp][0], vb2[njp][1], vb2[njp][2], vb2[njp][3], a);
            }
            #pragma unroll
            for (int nj = 0; nj < 8; nj++) mma16816(o[nj], al, &vb[nj >> 1][(nj & 1) * 2]);
            #pragma unroll
            for (int nj = 0; nj < 8; nj++) mma16816(o[nj], ah, &vb2[nj >> 1][(nj & 1) * 2]);
        }
    }
    CP_WAIT0();

    // ---- finalize + write split bf16 straight into A3 [hi|lo|hi] ----
    l0 += __shfl_xor_sync(0xffffffffu, l0, 1);
    l0 += __shfl_xor_sync(0xffffffffu, l0, 2);
    l1 += __shfl_xor_sync(0xffffffffu, l1, 1);
    l1 += __shfl_xor_sync(0xffffffffu, l1, 2);
    float inv0 = 1.f / l0, inv1 = 1.f / l1;

    const int srow = q0 + m0w + g;
    size_t r0 = (size_t)(b * SS + srow) * KW;
    size_t r1 = r0 + (size_t)8 * KW;
    const int colbase = h * DH;

    #pragma unroll
    for (int nj = 0; nj < 8; nj++) {
        int c = colbase + nj * 8 + 2 * t4;
        uint32_t hp, lp;
        split_pack(o[nj][0] * inv0, o[nj][1] * inv0, hp, lp);
        *reinterpret_cast<uint32_t*>(A3out + r0 + c)        = hp;
        *reinterpret_cast<uint32_t*>(A3out + r0 + 1024 + c) = lp;
        *reinterpret_cast<uint32_t*>(A3out + r0 + 2048 + c) = hp;
        split_pack(o[nj][2] * inv1, o[nj][3] * inv1, hp, lp);
        *reinterpret_cast<uint32_t*>(A3out + r1 + c)        = hp;
        *reinterpret_cast<uint32_t*>(A3out + r1 + 1024 + c) = lp;
        *reinterpret_cast<uint32_t*>(A3out + r1 + 2048 + c) = hp;
    }
}

// ---------------------------------------------------------------------------
// launch
// ---------------------------------------------------------------------------
extern "C" void kernel_launch(void* const* d_in, const int* in_sizes, int n_in,
                              void* d_out, int out_size)
{
    const float* Q    = (const float*)d_in[0];
    const float* K    = (const float*)d_in[1];
    const float* V    = (const float*)d_in[2];
    const int*   mask = (const int*)  d_in[3];
    const float* Wq   = (const float*)d_in[4];
    const float* bq   = (const float*)d_in[5];
    const float* Wk   = (const float*)d_in[6];
    const float* bk   = (const float*)d_in[7];
    const float* Wv   = (const float*)d_in[8];
    const float* bv   = (const float*)d_in[9];
    const float* Wo   = (const float*)d_in[10];
    const float* bo   = (const float*)d_in[11];
    float* out = (float*)d_out;

    __nv_bfloat16 *A3, *W3, *Qh, *Ql, *Kh, *Kl, *Vh, *Vl;
    int *pos, *cnt;
    cudaGetSymbolAddress((void**)&A3, g_A3v3);
    cudaGetSymbolAddress((void**)&W3, g_W3v4);
    cudaGetSymbolAddress((void**)&Qh, g_Qh);
    cudaGetSymbolAddress((void**)&Ql, g_Ql);
    cudaGetSymbolAddress((void**)&Kh, g_Kh);
    cudaGetSymbolAddress((void**)&Kl, g_Kl);
    cudaGetSymbolAddress((void**)&Vh, g_Vh);
    cudaGetSymbolAddress((void**)&Vl, g_Vl);
    cudaGetSymbolAddress((void**)&pos, g_pos);
    cudaGetSymbolAddress((void**)&cnt, g_cnt);

    cudaFuncSetAttribute(gemm_qkv, cudaFuncAttributeMaxDynamicSharedMemorySize, GEMM_SMEM);
    cudaFuncSetAttribute(gemm_out, cudaFuncAttributeMaxDynamicSharedMemorySize, GEMM_SMEM);
    cudaFuncSetAttribute(attn_mma, cudaFuncAttributeMaxDynamicSharedMemorySize, ATTN_SMEM);

    mask_scan<<<BB, 256>>>(mask, pos, cnt);
    conv_w<<<dim3(DF * DF / 1024, 4), 256>>>(Wq, Wk, Wv, Wo, W3);
    conv_in<<<dim3(MROWS * DF / 1024, 3), 256>>>(Q, K, V, mask, pos, A3);

    gemm_qkv<<<dim3(DF / 128, MROWS / 128, 3), 128, GEMM_SMEM>>>(
        A3, W3, bq, bk, bv, cnt, Qh, Ql, Kh, Kl, Vh, Vl);

    attn_mma<<<dim3(SS / 128, NH, BB), 256, ATTN_SMEM>>>(Qh, Ql, Kh, Kl, Vh, Vl, cnt, A3);

    gemm_out<<<dim3(DF / 128, MROWS / 128), 128, GEMM_SMEM>>>(
        A3, W3 + (size_t)3 * DF * KW, bo, out);
}

// round 13
// speedup vs baseline: 2.1460x; 1.4350x over previous
#include <cuda_runtime.h>
#include <cuda_fp16.h>
#include <cstdint>

#define DF 1024
#define NH 16
#define DH 64
#define BB 2
#define SS 2048
#define MROWS (BB*SS)

#define KW   2048              // split-K width (2 * 1024, fp16 [hi|lo])
#define KC   64                // fp16 K per SMEM chunk
#define NCHUNK (KW / KC)       // 32
#define NSTAGE 3
#define PITCH  72
#define PITCHB 144
#define OP_BYTES (128 * PITCHB)             // 18432
#define STAGE_BYTES (2 * OP_BYTES)          // 36864
#define GEMM_SMEM (512 + NSTAGE * STAGE_BYTES)  // 111104

// attention smem: per stage Kh + Vh tiles only
#define ATILE   9216                       // one 64x64 fp16 tile, pitch 144
#define ASTRIDE (2 * ATILE + 256)          // 18688
#define QL_OFF  18432
#define ATTN_SMEM (3 * ASTRIDE)            // 56064 (covers 36864 Q staging)

// ---------------------------------------------------------------------------
// Scratch
// ---------------------------------------------------------------------------
__device__ __half g_A3v3[3][(size_t)MROWS * KW];   // activations, split [hi|lo]
__device__ __half g_Whv4[4][(size_t)DF * 1024];    // weights, hi only
__device__ __half g_Qh[(size_t)BB * NH * SS * DH];
__device__ __half g_Ql[(size_t)BB * NH * SS * DH];
__device__ __half g_Kh[(size_t)BB * NH * SS * DH];
__device__ __half g_Vh[(size_t)BB * NH * SS * DH];
__device__ int g_pos[BB * SS];
__device__ int g_cnt[BB];

// ---------------------------------------------------------------------------
// helpers
// ---------------------------------------------------------------------------
__device__ __forceinline__ uint32_t smem_u32(const void* p) {
    uint32_t a;
    asm("{ .reg .u64 t; cvta.to.shared.u64 t, %1; cvt.u32.u64 %0, t; }"
        : "=r"(a) : "l"(p));
    return a;
}

__device__ __forceinline__ void cp_async_16(uint32_t dst, const void* src) {
    asm volatile("cp.async.cg.shared.global [%0], [%1], 16;" :: "r"(dst), "l"(src) : "memory");
}
#define CP_COMMIT() asm volatile("cp.async.commit_group;" ::: "memory")
#define CP_WAIT1()  asm volatile("cp.async.wait_group 1;" ::: "memory")
#define CP_WAIT0()  asm volatile("cp.async.wait_group 0;" ::: "memory")

__device__ __forceinline__ void ldsm_x4(uint32_t& r0, uint32_t& r1, uint32_t& r2,
                                        uint32_t& r3, uint32_t addr) {
    asm volatile("ldmatrix.sync.aligned.m8n8.x4.shared.b16 {%0,%1,%2,%3}, [%4];"
                 : "=r"(r0), "=r"(r1), "=r"(r2), "=r"(r3) : "r"(addr));
}
__device__ __forceinline__ void ldsm_x4_t(uint32_t& r0, uint32_t& r1, uint32_t& r2,
                                          uint32_t& r3, uint32_t addr) {
    asm volatile("ldmatrix.sync.aligned.m8n8.x4.trans.shared.b16 {%0,%1,%2,%3}, [%4];"
                 : "=r"(r0), "=r"(r1), "=r"(r2), "=r"(r3) : "r"(addr));
}

__device__ __forceinline__ void mma16816(float* d, const uint32_t* a, const uint32_t* b) {
    asm volatile(
        "mma.sync.aligned.m16n8k16.row.col.f32.f16.f16.f32 "
        "{%0,%1,%2,%3}, {%4,%5,%6,%7}, {%8,%9}, {%0,%1,%2,%3};"
        : "+f"(d[0]), "+f"(d[1]), "+f"(d[2]), "+f"(d[3])
        : "r"(a[0]), "r"(a[1]), "r"(a[2]), "r"(a[3]), "r"(b[0]), "r"(b[1]));
}

__device__ __forceinline__ uint32_t h2pack(__half a, __half b) {
    __half2 h = __halves2half2(a, b);
    uint32_t r; memcpy(&r, &h, 4); return r;
}
__device__ __forceinline__ uint32_t pack_rn(float x, float y) {
    __half2 h = __floats2half2_rn(x, y);
    uint32_t r; memcpy(&r, &h, 4); return r;
}
// fp16 round-to-nearest hi + residual lo (residual <= 2^-12 relative)
__device__ __forceinline__ void split_pack(float x, float y, uint32_t& hp, uint32_t& lp) {
    __half hx = __float2half_rn(x), hy = __float2half_rn(y);
    hp = h2pack(hx, hy);
    lp = h2pack(__float2half_rn(x - __half2float(hx)),
                __float2half_rn(y - __half2float(hy)));
}

// ---------------------------------------------------------------------------
// mask prefix scan: pos[b][s] = #valid keys before s ; cnt[b] = total valid
// ---------------------------------------------------------------------------
__global__ __launch_bounds__(256) void mask_scan(const int* __restrict__ mask,
                                                 int* __restrict__ pos, int* __restrict__ cnt)
{
    __shared__ int partial[256];
    const int b = blockIdx.x, tid = threadIdx.x;
    const int base = b * SS + tid * 8;
    int v[8], s = 0;
    #pragma unroll
    for (int i = 0; i < 8; i++) { v[i] = (mask[base + i] != 0); s += v[i]; }
    partial[tid] = s;
    __syncthreads();
    for (int off = 1; off < 256; off <<= 1) {
        int t = (tid >= off) ? partial[tid - off] : 0;
        __syncthreads();
        partial[tid] += t;
        __syncthreads();
    }
    int ex = (tid == 0) ? 0 : partial[tid - 1];
    #pragma unroll
    for (int i = 0; i < 8; i++) { pos[base + i] = ex; ex += v[i]; }
    if (tid == 255) cnt[b] = partial[255];
}

// ---------------------------------------------------------------------------
// Split-fp16 conversions. conv_in: z=0 Q dense; z=1 K, z=2 V with row
// compaction. Output row layout: [hi(1024) | lo(1024)].
// ---------------------------------------------------------------------------
__global__ __launch_bounds__(256) void conv_in(const float* __restrict__ Q,
                                               const float* __restrict__ K,
                                               const float* __restrict__ V,
                                               const int* __restrict__ mask,
                                               const int* __restrict__ pos,
                                               __half* __restrict__ A3)
{
    const int z = blockIdx.y;
    const float* X = z == 0 ? Q : (z == 1 ? K : V);
    __half* Y = A3 + (size_t)z * MROWS * KW;
    int idx = (blockIdx.x * 256 + threadIdx.x) * 4;
    int r = idx >> 10, k = idx & 1023;
    int rr = r;
    if (z > 0) {
        int bb_ = r >> 11, sidx = r & 2047;
        if (mask[bb_ * SS + sidx] == 0) return;       // masked key row: skip
        rr = bb_ * SS + pos[bb_ * SS + sidx];         // compacted destination
    }
    float4 x = *reinterpret_cast<const float4*>(X + idx);
    float v[4] = {x.x, x.y, x.z, x.w};
    __half hi[4], lo[4];
    #pragma unroll
    for (int i = 0; i < 4; i++) {
        hi[i] = __float2half_rn(v[i]);
        lo[i] = __float2half_rn(v[i] - __half2float(hi[i]));
    }
    uint64_t hip, lop;
    memcpy(&hip, hi, 8);
    memcpy(&lop, lo, 8);
    size_t base = (size_t)rr * KW + k;
    *reinterpret_cast<uint64_t*>(Y + base)        = hip;
    *reinterpret_cast<uint64_t*>(Y + base + 1024) = lop;
}

__global__ __launch_bounds__(256) void conv_w(const float* __restrict__ Wq,
                                              const float* __restrict__ Wk,
                                              const float* __restrict__ Wv,
                                              const float* __restrict__ Wo,
                                              __half* __restrict__ Wh)
{
    const float* X = blockIdx.y == 0 ? Wq : (blockIdx.y == 1 ? Wk :
                      (blockIdx.y == 2 ? Wv : Wo));
    __half* Y = Wh + (size_t)blockIdx.y * DF * 1024;
    int idx = (blockIdx.x * 256 + threadIdx.x) * 4;
    float4 x = *reinterpret_cast<const float4*>(X + idx);
    float v[4] = {x.x, x.y, x.z, x.w};
    __half hi[4];
    #pragma unroll
    for (int i = 0; i < 4; i++) hi[i] = __float2half_rn(v[i]);
    uint64_t hip;
    memcpy(&hip, hi, 8);
    *reinterpret_cast<uint64_t*>(Y + idx) = hip;
}

// ---------------------------------------------------------------------------
// GEMM mainloop: 128 threads / 4 warps (2M x 2N), warp tile 64x64.
// A is [M, 2048] split [hi|lo]; W is [N, 1024] hi only, indexed k0 & 1023
// (each W column block used by both A halves): C = (Ah+Al) . Wh.
// ---------------------------------------------------------------------------
struct GemmCore {
    float acc[4][8][4];
    int m0w, n0w;

    __device__ __forceinline__ void run(uint32_t sb, int tid, int wid, int lid,
                                        const __half* Abase,
                                        const __half* Wbase) {
        m0w = (wid & 1) * 64;
        n0w = (wid >> 1) * 64;
        #pragma unroll
        for (int mi = 0; mi < 4; mi++)
            #pragma unroll
            for (int nj = 0; nj < 8; nj++)
                #pragma unroll
                for (int e = 0; e < 4; e++) acc[mi][nj][e] = 0.f;

        auto load_chunk = [&](int c, int s) {
            const int k0 = c * KC;
            const int kw = k0 & 1023;           // W reuses hi for both halves
            const uint32_t stage = sb + 512 + s * STAGE_BYTES;
            #pragma unroll
            for (int i = 0; i < 16; i++) {
                int seg = i * 128 + tid;
                int op  = seg >> 10;
                int r   = (seg & 1023) >> 3;
                int cs  = seg & 7;
                uint32_t dst = stage + op * OP_BYTES + (uint32_t)(r * PITCHB + cs * 16);
                const __half* src = (op == 0)
                    ? Abase + (size_t)r * KW + k0 + cs * 8
                    : Wbase + (size_t)r * 1024 + kw + cs * 8;
                cp_async_16(dst, src);
            }
        };

        load_chunk(0, 0); CP_COMMIT();
        load_chunk(1, 1); CP_COMMIT();

        for (int c = 0; c < NCHUNK; c++) {
            const int s = c % NSTAGE;
            CP_WAIT1();
            __syncthreads();                    // sole barrier per chunk
            int cn = c + 2;
            if (cn < NCHUNK) load_chunk(cn, cn % NSTAGE);
            CP_COMMIT();

            const uint32_t sA = sb + 512 + s * STAGE_BYTES;
            const uint32_t sW = sA + OP_BYTES;
            #pragma unroll
            for (int kk = 0; kk < 4; kk++) {
                uint32_t a[4][4];
                #pragma unroll
                for (int mi = 0; mi < 4; mi++) {
                    uint32_t addr = sA + (uint32_t)((m0w + mi * 16 + (lid & 15)) * PITCHB
                                     + kk * 32 + ((lid >> 4) << 4));
                    ldsm_x4(a[mi][0], a[mi][1], a[mi][2], a[mi][3], addr);
                }
                uint32_t b[8][2];
                #pragma unroll
                for (int ni = 0; ni < 4; ni++) {
                    uint32_t addr = sW + (uint32_t)((n0w + ni * 16 + (lid & 7)
                                     + ((lid >> 4) & 1) * 8) * PITCHB
                                     + kk * 32 + (((lid >> 3) & 1) << 4));
                    uint32_t r0, r1, r2, r3;
                    ldsm_x4(r0, r1, r2, r3, addr);
                    b[2 * ni][0] = r0; b[2 * ni][1] = r1;
                    b[2 * ni + 1][0] = r2; b[2 * ni + 1][1] = r3;
                }
                #pragma unroll
                for (int mi = 0; mi < 4; mi++)
                    #pragma unroll
                    for (int nj = 0; nj < 8; nj++)
                        mma16816(acc[mi][nj], a[mi], b[nj]);
            }
        }
        CP_WAIT0();
    }
};

// ---------------------------------------------------------------------------
// Fused QKV projection GEMM over pre-compacted inputs.
// z=0: Q dense -> (Qh, Ql) split.  z=1: K -> Kh only.  z=2: V -> Vh only.
// Rows >= cnt in the boundary tile store ZEROS (tail guard).
// ---------------------------------------------------------------------------
__global__ void __launch_bounds__(128, 2)
gemm_qkv(const __half* __restrict__ A3, const __half* __restrict__ Wh,
         const float* __restrict__ bq, const float* __restrict__ bk,
         const float* __restrict__ bv, const int* __restrict__ cnt_,
         __half* __restrict__ Qh, __half* __restrict__ Ql,
         __half* __restrict__ Kh, __half* __restrict__ Vh)
{
    extern __shared__ char smem[];
    const uint32_t sb = smem_u32(smem);
    const int tid = threadIdx.x, wid = tid >> 5, lid = tid & 31;
    const int z = blockIdx.z;
    const int m0 = blockIdx.y * 128, n0 = blockIdx.x * 128;

    int cntb = SS;                    // dense for Q
    if (z > 0) {                      // compacted K/V: skip row tiles past cnt
        cntb = cnt_[m0 >> 11];
        if ((m0 & 2047) >= cntb) return;
    }

    const float* bias = (z == 0) ? bq : (z == 1) ? bk : bv;
    float* bias_s = (float*)smem;
    if (tid < 128) bias_s[tid] = bias[n0 + tid];

    __half* H = (z == 0) ? Qh : (z == 1) ? Kh : Vh;

    GemmCore core;
    core.run(sb, tid, wid, lid,
             A3 + (size_t)z * MROWS * KW + (size_t)m0 * KW,
             Wh + (size_t)z * DF * 1024 + (size_t)n0 * 1024);

    const int g = lid >> 2, t = lid & 3;
    #pragma unroll
    for (int mi = 0; mi < 4; mi++) {
        #pragma unroll
        for (int nj = 0; nj < 8; nj++) {
            int colrel = core.n0w + nj * 8 + 2 * t;
            int col = n0 + colrel;
            int hh = col >> 6, dh = col & 63;
            float c0 = core.acc[mi][nj][0] + bias_s[colrel];
            float c1 = core.acc[mi][nj][1] + bias_s[colrel + 1];
            float c2 = core.acc[mi][nj][2] + bias_s[colrel];
            float c3 = core.acc[mi][nj][3] + bias_s[colrel + 1];
            #pragma unroll
            for (int rr = 0; rr < 2; rr++) {
                int row = m0 + core.m0w + mi * 16 + g + rr * 8;
                int bb_ = row >> 11, sidx = row & 2047;
                size_t dst = ((size_t)(bb_ * NH + hh) * SS + sidx) * DH + dh;
                float x = rr ? c2 : c0, y = rr ? c3 : c1;
                if (z == 0) {
                    uint32_t hp = 0, lp = 0;
                    split_pack(x, y, hp, lp);
                    *reinterpret_cast<uint32_t*>(H + dst)  = hp;
                    *reinterpret_cast<uint32_t*>(Ql + dst) = lp;
                } else {
                    uint32_t hp = (sidx < cntb) ? pack_rn(x, y) : 0u;
                    *reinterpret_cast<uint32_t*>(H + dst) = hp;
                }
            }
        }
    }
}

// ---------------------------------------------------------------------------
// Output projection GEMM: fp32 out
// ---------------------------------------------------------------------------
__global__ void __launch_bounds__(128, 2)
gemm_out(const __half* __restrict__ A3, const __half* __restrict__ Wh,
         const float* __restrict__ bias, float* __restrict__ C)
{
    extern __shared__ char smem[];
    const uint32_t sb = smem_u32(smem);
    const int tid = threadIdx.x, wid = tid >> 5, lid = tid & 31;
    const int m0 = blockIdx.y * 128, n0 = blockIdx.x * 128;

    float* bias_s = (float*)smem;
    if (tid < 128) bias_s[tid] = bias[n0 + tid];

    GemmCore core;
    core.run(sb, tid, wid, lid, A3 + (size_t)m0 * KW, Wh + (size_t)n0 * 1024);

    const int g = lid >> 2, t = lid & 3;
    #pragma unroll
    for (int mi = 0; mi < 4; mi++) {
        #pragma unroll
        for (int nj = 0; nj < 8; nj++) {
            int colrel = core.n0w + nj * 8 + 2 * t;
            int col = n0 + colrel;
            int row0 = m0 + core.m0w + mi * 16 + g;
            float2 v0 = {core.acc[mi][nj][0] + bias_s[colrel],
                         core.acc[mi][nj][1] + bias_s[colrel + 1]};
            float2 v1 = {core.acc[mi][nj][2] + bias_s[colrel],
                         core.acc[mi][nj][3] + bias_s[colrel + 1]};
            *reinterpret_cast<float2*>(C + (size_t)row0 * DF + col) = v0;
            *reinterpret_cast<float2*>(C + (size_t)(row0 + 8) * DF + col) = v1;
        }
    }
}

// ---------------------------------------------------------------------------
// FlashAttention-2 on mma.sync over COMPACTED keys (128 q/CTA, 8 warps x 16
// q-rows). fp16 2-term: S = (Qh+Ql).Kh, O = (Ph+Pl).Vh.
// ---------------------------------------------------------------------------
__global__ void __launch_bounds__(256, 1)
attn_mma(const __half* __restrict__ Qh_, const __half* __restrict__ Ql_,
         const __half* __restrict__ Kh_, const __half* __restrict__ Vh_,
         const int* __restrict__ cnt_, __half* __restrict__ A3out)
{
    extern __shared__ char smem[];
    const uint32_t sb = smem_u32(smem);
    const int tid = threadIdx.x, wid = tid >> 5, lid = tid & 31;
    const int g = lid >> 2, t4 = lid & 3;
    const int b = blockIdx.z, h = blockIdx.y;
    const int bh = b * NH + h;
    const int q0 = blockIdx.x * 128;
    const int m0w = wid * 16;
    const float SC = 0.03125f;

    const int cnt = cnt_[b];
    const int nt = (cnt + 63) >> 6;

    // ---- stage Q (hi,lo) through smem into register a-frags ----
    {
        const size_t qbase = ((size_t)bh * SS + q0);
        #pragma unroll
        for (int i = 0; i < 4; i++) {
            int seg = i * 256 + tid;
            int row = seg >> 3, cs = seg & 7;
            const size_t src = (qbase + row) * DH + cs * 8;
            uint32_t d = sb + (uint32_t)(row * PITCHB + cs * 16);
            cp_async_16(d,          Qh_ + src);
            cp_async_16(d + QL_OFF, Ql_ + src);
        }
    }
    CP_COMMIT(); CP_WAIT0(); __syncthreads();

    uint32_t qh[4][4], ql[4][4];
    #pragma unroll
    for (int kk = 0; kk < 4; kk++) {
        uint32_t a = sb + (uint32_t)((m0w + (lid & 15)) * PITCHB + kk * 32 + ((lid >> 4) << 4));
        ldsm_x4(qh[kk][0], qh[kk][1], qh[kk][2], qh[kk][3], a);
        ldsm_x4(ql[kk][0], ql[kk][1], ql[kk][2], ql[kk][3], a + QL_OFF);
    }
    __syncthreads();

    auto load_tile = [&](int ti, int st) {
        const uint32_t stage = sb + st * ASTRIDE;
        const size_t kbase = ((size_t)bh * SS + ti * 64);
        #pragma unroll
        for (int i = 0; i < 2; i++) {
            int seg = i * 256 + tid;
            int row = seg >> 3, cs = seg & 7;
            size_t src = (kbase + row) * DH + cs * 8;
            uint32_t d = stage + (uint32_t)(row * PITCHB + cs * 16);
            cp_async_16(d,         Kh_ + src);
            cp_async_16(d + ATILE, Vh_ + src);
        }
    };

    float m0 = -1e30f, m1 = -1e30f, l0 = 0.f, l1 = 0.f;
    float o[8][4];
    #pragma unroll
    for (int nj = 0; nj < 8; nj++)
        #pragma unroll
        for (int e = 0; e < 4; e++) o[nj][e] = 0.f;

    if (0 < nt) load_tile(0, 0);
    CP_COMMIT();
    if (1 < nt) load_tile(1, 1);
    CP_COMMIT();

    for (int ti = 0; ti < nt; ti++) {
        const int st = ti % 3;
        CP_WAIT1();
        __syncthreads();                        // sole barrier per tile
        if (ti + 2 < nt) load_tile(ti + 2, (ti + 2) % 3);
        CP_COMMIT();

        const uint32_t sK = sb + st * ASTRIDE;
        const uint32_t sV = sK + ATILE;

        // ---- S = Qh Kh^T + Ql Kh^T ----
        float s[8][4];
        #pragma unroll
        for (int nj = 0; nj < 8; nj++)
            #pragma unroll
            for (int e = 0; e < 4; e++) s[nj][e] = 0.f;

        #pragma unroll
        for (int kk = 0; kk < 4; kk++) {
            uint32_t kb[4][4];
            #pragma unroll
            for (int ni = 0; ni < 4; ni++) {
                uint32_t a = sK + (uint32_t)((ni * 16 + (lid & 7) + ((lid >> 4) & 1) * 8) * PITCHB
                             + kk * 32 + (((lid >> 3) & 1) << 4));
                ldsm_x4(kb[ni][0], kb[ni][1], kb[ni][2], kb[ni][3], a);
            }
            #pragma unroll
            for (int nj = 0; nj < 8; nj++) mma16816(s[nj], qh[kk], &kb[nj >> 1][(nj & 1) * 2]);
            #pragma unroll
            for (int nj = 0; nj < 8; nj++) mma16816(s[nj], ql[kk], &kb[nj >> 1][(nj & 1) * 2]);
        }

        // ---- scale + tail mask + online softmax ----
        const int kbase_idx = ti * 64;
        float tmax0 = -1e30f, tmax1 = -1e30f;
        #pragma unroll
        for (int nj = 0; nj < 8; nj++) {
            int k0i = kbase_idx + nj * 8 + 2 * t4;
            bool v0 = k0i < cnt, v1 = (k0i + 1) < cnt;
            float s0 = v0 ? s[nj][0] * SC : -1e9f;
            float s1 = v1 ? s[nj][1] * SC : -1e9f;
            float s2 = v0 ? s[nj][2] * SC : -1e9f;
            float s3 = v1 ? s[nj][3] * SC : -1e9f;
            s[nj][0] = s0; s[nj][1] = s1; s[nj][2] = s2; s[nj][3] = s3;
            tmax0 = fmaxf(tmax0, fmaxf(s0, s1));
            tmax1 = fmaxf(tmax1, fmaxf(s2, s3));
        }
        tmax0 = fmaxf(tmax0, __shfl_xor_sync(0xffffffffu, tmax0, 1));
        tmax0 = fmaxf(tmax0, __shfl_xor_sync(0xffffffffu, tmax0, 2));
        tmax1 = fmaxf(tmax1, __shfl_xor_sync(0xffffffffu, tmax1, 1));
        tmax1 = fmaxf(tmax1, __shfl_xor_sync(0xffffffffu, tmax1, 2));

        float mn0 = fmaxf(m0, tmax0), mn1 = fmaxf(m1, tmax1);
        float sc0 = __expf(m0 - mn0), sc1 = __expf(m1 - mn1);
        m0 = mn0; m1 = mn1;
        l0 *= sc0; l1 *= sc1;
        #pragma unroll
        for (int nj = 0; nj < 8; nj++) {
            o[nj][0] *= sc0; o[nj][1] *= sc0;
            o[nj][2] *= sc1; o[nj][3] *= sc1;
        }
        #pragma unroll
        for (int nj = 0; nj < 8; nj++) {
            float p0 = __expf(s[nj][0] - m0);
            float p1 = __expf(s[nj][1] - m0);
            float p2 = __expf(s[nj][2] - m1);
            float p3 = __expf(s[nj][3] - m1);
            s[nj][0] = p0; s[nj][1] = p1; s[nj][2] = p2; s[nj][3] = p3;
            l0 += p0 + p1; l1 += p2 + p3;
        }

        // ---- O += Ph Vh + Pl Vh ----
        #pragma unroll
        for (int kk = 0; kk < 4; kk++) {
            uint32_t ah[4], al[4];
            split_pack(s[2 * kk][0],     s[2 * kk][1],     ah[0], al[0]);
            split_pack(s[2 * kk][2],     s[2 * kk][3],     ah[1], al[1]);
            split_pack(s[2 * kk + 1][0], s[2 * kk + 1][1], ah[2], al[2]);
            split_pack(s[2 * kk + 1][2], s[2 * kk + 1][3], ah[3], al[3]);

            uint32_t vb[4][4];
            #pragma unroll
            for (int njp = 0; njp < 4; njp++) {
                uint32_t a = sV + (uint32_t)((16 * kk + (lid & 7) + ((lid >> 3) & 1) * 8) * PITCHB
                             + (16 * njp + ((lid >> 4) & 1) * 8) * 2);
                ldsm_x4_t(vb[njp][0], vb[njp][1], vb[njp][2], vb[njp][3], a);
            }
            #pragma unroll
            for (int nj = 0; nj < 8; nj++) mma16816(o[nj], ah, &vb[nj >> 1][(nj & 1) * 2]);
            #pragma unroll
            for (int nj = 0; nj < 8; nj++) mma16816(o[nj], al, &vb[nj >> 1][(nj & 1) * 2]);
        }
    }
    CP_WAIT0();

    // ---- finalize + write split fp16 straight into A3 [hi|lo] ----
    l0 += __shfl_xor_sync(0xffffffffu, l0, 1);
    l0 += __shfl_xor_sync(0xffffffffu, l0, 2);
    l1 += __shfl_xor_sync(0xffffffffu, l1, 1);
    l1 += __shfl_xor_sync(0xffffffffu, l1, 2);
    float inv0 = 1.f / l0, inv1 = 1.f / l1;

    const int srow = q0 + m0w + g;
    size_t r0 = (size_t)(b * SS + srow) * KW;
    size_t r1 = r0 + (size_t)8 * KW;
    const int colbase = h * DH;

    #pragma unroll
    for (int nj = 0; nj < 8; nj++) {
        int c = colbase + nj * 8 + 2 * t4;
        uint32_t hp, lp;
        split_pack(o[nj][0] * inv0, o[nj][1] * inv0, hp, lp);
        *reinterpret_cast<uint32_t*>(A3out + r0 + c)        = hp;
        *reinterpret_cast<uint32_t*>(A3out + r0 + 1024 + c) = lp;
        split_pack(o[nj][2] * inv1, o[nj][3] * inv1, hp, lp);
        *reinterpret_cast<uint32_t*>(A3out + r1 + c)        = hp;
        *reinterpret_cast<uint32_t*>(A3out + r1 + 1024 + c) = lp;
    }
}

// ---------------------------------------------------------------------------
// launch
// ---------------------------------------------------------------------------
extern "C" void kernel_launch(void* const* d_in, const int* in_sizes, int n_in,
                              void* d_out, int out_size)
{
    const float* Q    = (const float*)d_in[0];
    const float* K    = (const float*)d_in[1];
    const float* V    = (const float*)d_in[2];
    const int*   mask = (const int*)  d_in[3];
    const float* Wq   = (const float*)d_in[4];
    const float* bq   = (const float*)d_in[5];
    const float* Wk   = (const float*)d_in[6];
    const float* bk   = (const float*)d_in[7];
    const float* Wv   = (const float*)d_in[8];
    const float* bv   = (const float*)d_in[9];
    const float* Wo   = (const float*)d_in[10];
    const float* bo   = (const float*)d_in[11];
    float* out = (float*)d_out;

    __half *A3, *Wh, *Qh, *Ql, *Kh, *Vh;
    int *pos, *cnt;
    cudaGetSymbolAddress((void**)&A3, g_A3v3);
    cudaGetSymbolAddress((void**)&Wh, g_Whv4);
    cudaGetSymbolAddress((void**)&Qh, g_Qh);
    cudaGetSymbolAddress((void**)&Ql, g_Ql);
    cudaGetSymbolAddress((void**)&Kh, g_Kh);
    cudaGetSymbolAddress((void**)&Vh, g_Vh);
    cudaGetSymbolAddress((void**)&pos, g_pos);
    cudaGetSymbolAddress((void**)&cnt, g_cnt);

    cudaFuncSetAttribute(gemm_qkv, cudaFuncAttributeMaxDynamicSharedMemorySize, GEMM_SMEM);
    cudaFuncSetAttribute(gemm_out, cudaFuncAttributeMaxDynamicSharedMemorySize, GEMM_SMEM);
    cudaFuncSetAttribute(attn_mma, cudaFuncAttributeMaxDynamicSharedMemorySize, ATTN_SMEM);

    mask_scan<<<BB, 256>>>(mask, pos, cnt);
    conv_w<<<dim3(DF * DF / 1024, 4), 256>>>(Wq, Wk, Wv, Wo, Wh);
    conv_in<<<dim3(MROWS * DF / 1024, 3), 256>>>(Q, K, V, mask, pos, A3);

    gemm_qkv<<<dim3(DF / 128, MROWS / 128, 3), 128, GEMM_SMEM>>>(
        A3, Wh, bq, bk, bv, cnt, Qh, Ql, Kh, Vh);

    attn_mma<<<dim3(SS / 128, NH, BB), 256, ATTN_SMEM>>>(Qh, Ql, Kh, Vh, cnt, A3);

    gemm_out<<<dim3(DF / 128, MROWS / 128), 128, GEMM_SMEM>>>(
        A3, Wh + (size_t)3 * DF * 1024, bo, out);
}

// round 14
// speedup vs baseline: 2.2252x; 1.0369x over previous
#include <cuda_runtime.h>
#include <cuda_fp16.h>
#include <cstdint>

#define DF 1024
#define NH 16
#define DH 64
#define BB 2
#define SS 2048
#define MROWS (BB*SS)

#define KW   2048              // A split width (fp16 [hi|lo])
#define KC   64                // fp16 K per chunk
#define NCHUNK 16              // 1024 / KC unique W chunks
#define NSTAGE 2
#define PITCH  72
#define PITCHB 144
#define TILE_B (128 * PITCHB)               // 18432
#define STAGE_BYTES (3 * TILE_B)            // Ah + Al + W = 55296
#define GEMM_SMEM (512 + NSTAGE * STAGE_BYTES)  // 111104

// attention smem: per stage Kh + Vh tiles only
#define ATILE   9216                       // one 64x64 fp16 tile, pitch 144
#define ASTRIDE (2 * ATILE + 256)          // 18688
#define QL_OFF  18432
#define ATTN_SMEM (3 * ASTRIDE)            // 56064 (covers 36864 Q staging)

// ---------------------------------------------------------------------------
// Scratch
// ---------------------------------------------------------------------------
__device__ __half g_A3v3[3][(size_t)MROWS * KW];   // activations, split [hi|lo]
__device__ __half g_Whv4[4][(size_t)DF * 1024];    // weights, hi only
__device__ __half g_Qh[(size_t)BB * NH * SS * DH];
__device__ __half g_Ql[(size_t)BB * NH * SS * DH];
__device__ __half g_Kh[(size_t)BB * NH * SS * DH];
__device__ __half g_Vh[(size_t)BB * NH * SS * DH];
__device__ int g_pos[BB * SS];
__device__ int g_cnt[BB];

// ---------------------------------------------------------------------------
// helpers
// ---------------------------------------------------------------------------
__device__ __forceinline__ uint32_t smem_u32(const void* p) {
    uint32_t a;
    asm("{ .reg .u64 t; cvta.to.shared.u64 t, %1; cvt.u32.u64 %0, t; }"
        : "=r"(a) : "l"(p));
    return a;
}

__device__ __forceinline__ void cp_async_16(uint32_t dst, const void* src) {
    asm volatile("cp.async.cg.shared.global [%0], [%1], 16;" :: "r"(dst), "l"(src) : "memory");
}
#define CP_COMMIT() asm volatile("cp.async.commit_group;" ::: "memory")
#define CP_WAIT1()  asm volatile("cp.async.wait_group 1;" ::: "memory")
#define CP_WAIT0()  asm volatile("cp.async.wait_group 0;" ::: "memory")

__device__ __forceinline__ void ldsm_x4(uint32_t& r0, uint32_t& r1, uint32_t& r2,
                                        uint32_t& r3, uint32_t addr) {
    asm volatile("ldmatrix.sync.aligned.m8n8.x4.shared.b16 {%0,%1,%2,%3}, [%4];"
                 : "=r"(r0), "=r"(r1), "=r"(r2), "=r"(r3) : "r"(addr));
}
__device__ __forceinline__ void ldsm_x4_t(uint32_t& r0, uint32_t& r1, uint32_t& r2,
                                          uint32_t& r3, uint32_t addr) {
    asm volatile("ldmatrix.sync.aligned.m8n8.x4.trans.shared.b16 {%0,%1,%2,%3}, [%4];"
                 : "=r"(r0), "=r"(r1), "=r"(r2), "=r"(r3) : "r"(addr));
}

__device__ __forceinline__ void mma16816(float* d, const uint32_t* a, const uint32_t* b) {
    asm volatile(
        "mma.sync.aligned.m16n8k16.row.col.f32.f16.f16.f32 "
        "{%0,%1,%2,%3}, {%4,%5,%6,%7}, {%8,%9}, {%0,%1,%2,%3};"
        : "+f"(d[0]), "+f"(d[1]), "+f"(d[2]), "+f"(d[3])
        : "r"(a[0]), "r"(a[1]), "r"(a[2]), "r"(a[3]), "r"(b[0]), "r"(b[1]));
}

__device__ __forceinline__ uint32_t h2pack(__half a, __half b) {
    __half2 h = __halves2half2(a, b);
    uint32_t r; memcpy(&r, &h, 4); return r;
}
__device__ __forceinline__ uint32_t pack_rn(float x, float y) {
    __half2 h = __floats2half2_rn(x, y);
    uint32_t r; memcpy(&r, &h, 4); return r;
}
// fp16 round-to-nearest hi + residual lo (residual <= 2^-12 relative)
__device__ __forceinline__ void split_pack(float x, float y, uint32_t& hp, uint32_t& lp) {
    __half hx = __float2half_rn(x), hy = __float2half_rn(y);
    hp = h2pack(hx, hy);
    lp = h2pack(__float2half_rn(x - __half2float(hx)),
                __float2half_rn(y - __half2float(hy)));
}

// ---------------------------------------------------------------------------
// mask prefix scan: pos[b][s] = #valid keys before s ; cnt[b] = total valid
// ---------------------------------------------------------------------------
__global__ __launch_bounds__(256) void mask_scan(const int* __restrict__ mask,
                                                 int* __restrict__ pos, int* __restrict__ cnt)
{
    __shared__ int partial[256];
    const int b = blockIdx.x, tid = threadIdx.x;
    const int base = b * SS + tid * 8;
    int v[8], s = 0;
    #pragma unroll
    for (int i = 0; i < 8; i++) { v[i] = (mask[base + i] != 0); s += v[i]; }
    partial[tid] = s;
    __syncthreads();
    for (int off = 1; off < 256; off <<= 1) {
        int t = (tid >= off) ? partial[tid - off] : 0;
        __syncthreads();
        partial[tid] += t;
        __syncthreads();
    }
    int ex = (tid == 0) ? 0 : partial[tid - 1];
    #pragma unroll
    for (int i = 0; i < 8; i++) { pos[base + i] = ex; ex += v[i]; }
    if (tid == 255) cnt[b] = partial[255];
}

// ---------------------------------------------------------------------------
// Split-fp16 conversions. conv_in: z=0 Q dense; z=1 K, z=2 V with row
// compaction. Output row layout: [hi(1024) | lo(1024)].
// ---------------------------------------------------------------------------
__global__ __launch_bounds__(256) void conv_in(const float* __restrict__ Q,
                                               const float* __restrict__ K,
                                               const float* __restrict__ V,
                                               const int* __restrict__ mask,
                                               const int* __restrict__ pos,
                                               __half* __restrict__ A3)
{
    const int z = blockIdx.y;
    const float* X = z == 0 ? Q : (z == 1 ? K : V);
    __half* Y = A3 + (size_t)z * MROWS * KW;
    int idx = (blockIdx.x * 256 + threadIdx.x) * 4;
    int r = idx >> 10, k = idx & 1023;
    int rr = r;
    if (z > 0) {
        int bb_ = r >> 11, sidx = r & 2047;
        if (mask[bb_ * SS + sidx] == 0) return;       // masked key row: skip
        rr = bb_ * SS + pos[bb_ * SS + sidx];         // compacted destination
    }
    float4 x = *reinterpret_cast<const float4*>(X + idx);
    float v[4] = {x.x, x.y, x.z, x.w};
    __half hi[4], lo[4];
    #pragma unroll
    for (int i = 0; i < 4; i++) {
        hi[i] = __float2half_rn(v[i]);
        lo[i] = __float2half_rn(v[i] - __half2float(hi[i]));
    }
    uint64_t hip, lop;
    memcpy(&hip, hi, 8);
    memcpy(&lop, lo, 8);
    size_t base = (size_t)rr * KW + k;
    *reinterpret_cast<uint64_t*>(Y + base)        = hip;
    *reinterpret_cast<uint64_t*>(Y + base + 1024) = lop;
}

__global__ __launch_bounds__(256) void conv_w(const float* __restrict__ Wq,
                                              const float* __restrict__ Wk,
                                              const float* __restrict__ Wv,
                                              const float* __restrict__ Wo,
                                              __half* __restrict__ Wh)
{
    const float* X = blockIdx.y == 0 ? Wq : (blockIdx.y == 1 ? Wk :
                      (blockIdx.y == 2 ? Wv : Wo));
    __half* Y = Wh + (size_t)blockIdx.y * DF * 1024;
    int idx = (blockIdx.x * 256 + threadIdx.x) * 4;
    float4 x = *reinterpret_cast<const float4*>(X + idx);
    float v[4] = {x.x, x.y, x.z, x.w};
    __half hi[4];
    #pragma unroll
    for (int i = 0; i < 4; i++) hi[i] = __float2half_rn(v[i]);
    uint64_t hip;
    memcpy(&hip, hi, 8);
    *reinterpret_cast<uint64_t*>(Y + idx) = hip;
}

// ---------------------------------------------------------------------------
// GEMM mainloop: 128 threads / 4 warps (2M x 2N), warp tile 64x64.
// Merged-W: per chunk load Ah(k), Al(k+1024), W(k); compute Ah.W and Al.W
// against ONE set of W b-frags. 16 chunks, 2-stage double buffer.
// ---------------------------------------------------------------------------
struct GemmCore {
    float acc[4][8][4];
    int m0w, n0w;

    __device__ __forceinline__ void run(uint32_t sb, int tid, int wid, int lid,
                                        const __half* Abase,
                                        const __half* Wbase) {
        m0w = (wid & 1) * 64;
        n0w = (wid >> 1) * 64;
        #pragma unroll
        for (int mi = 0; mi < 4; mi++)
            #pragma unroll
            for (int nj = 0; nj < 8; nj++)
                #pragma unroll
                for (int e = 0; e < 4; e++) acc[mi][nj][e] = 0.f;

        auto load_chunk = [&](int c, int s) {
            const int k0 = c * KC;
            const uint32_t stage = sb + 512 + s * STAGE_BYTES;
            #pragma unroll
            for (int i = 0; i < 24; i++) {
                int seg = i * 128 + tid;
                int op  = seg >> 10;                // 0=Ah, 1=Al, 2=W
                int r   = (seg & 1023) >> 3;
                int cs  = seg & 7;
                uint32_t dst = stage + op * TILE_B + (uint32_t)(r * PITCHB + cs * 16);
                const __half* src = (op == 2)
                    ? Wbase + (size_t)r * 1024 + k0 + cs * 8
                    : Abase + (size_t)r * KW + op * 1024 + k0 + cs * 8;
                cp_async_16(dst, src);
            }
        };

        load_chunk(0, 0); CP_COMMIT();

        for (int c = 0; c < NCHUNK; c++) {
            const int s = c & 1;
            if (c + 1 < NCHUNK) load_chunk(c + 1, (c + 1) & 1);
            CP_COMMIT();
            CP_WAIT1();                 // chunk c resident (c+1 in flight)
            __syncthreads();            // visibility of c across threads

            const uint32_t sAh = sb + 512 + s * STAGE_BYTES;
            const uint32_t sAl = sAh + TILE_B;
            const uint32_t sW  = sAh + 2 * TILE_B;
            #pragma unroll
            for (int kk = 0; kk < 4; kk++) {
                uint32_t b[8][2];
                #pragma unroll
                for (int ni = 0; ni < 4; ni++) {
                    uint32_t addr = sW + (uint32_t)((n0w + ni * 16 + (lid & 7)
                                     + ((lid >> 4) & 1) * 8) * PITCHB
                                     + kk * 32 + (((lid >> 3) & 1) << 4));
                    uint32_t r0, r1, r2, r3;
                    ldsm_x4(r0, r1, r2, r3, addr);
                    b[2 * ni][0] = r0; b[2 * ni][1] = r1;
                    b[2 * ni + 1][0] = r2; b[2 * ni + 1][1] = r3;
                }
                uint32_t a[4][4];
                #pragma unroll
                for (int mi = 0; mi < 4; mi++) {
                    uint32_t addr = sAh + (uint32_t)((m0w + mi * 16 + (lid & 15)) * PITCHB
                                     + kk * 32 + ((lid >> 4) << 4));
                    ldsm_x4(a[mi][0], a[mi][1], a[mi][2], a[mi][3], addr);
                }
                #pragma unroll
                for (int mi = 0; mi < 4; mi++)
                    #pragma unroll
                    for (int nj = 0; nj < 8; nj++)
                        mma16816(acc[mi][nj], a[mi], b[nj]);
                #pragma unroll
                for (int mi = 0; mi < 4; mi++) {
                    uint32_t addr = sAl + (uint32_t)((m0w + mi * 16 + (lid & 15)) * PITCHB
                                     + kk * 32 + ((lid >> 4) << 4));
                    ldsm_x4(a[mi][0], a[mi][1], a[mi][2], a[mi][3], addr);
                }
                #pragma unroll
                for (int mi = 0; mi < 4; mi++)
                    #pragma unroll
                    for (int nj = 0; nj < 8; nj++)
                        mma16816(acc[mi][nj], a[mi], b[nj]);
            }
            __syncthreads();            // reads of stage s done before reuse
        }
        CP_WAIT0();
    }
};

// ---------------------------------------------------------------------------
// Fused QKV projection GEMM over pre-compacted inputs.
// z=0: Q dense -> (Qh, Ql) split.  z=1: K -> Kh only.  z=2: V -> Vh only.
// Rows >= cnt in the boundary tile store ZEROS (tail guard).
// ---------------------------------------------------------------------------
__global__ void __launch_bounds__(128, 2)
gemm_qkv(const __half* __restrict__ A3, const __half* __restrict__ Wh,
         const float* __restrict__ bq, const float* __restrict__ bk,
         const float* __restrict__ bv, const int* __restrict__ cnt_,
         __half* __restrict__ Qh, __half* __restrict__ Ql,
         __half* __restrict__ Kh, __half* __restrict__ Vh)
{
    extern __shared__ char smem[];
    const uint32_t sb = smem_u32(smem);
    const int tid = threadIdx.x, wid = tid >> 5, lid = tid & 31;
    const int z = blockIdx.z;
    const int m0 = blockIdx.y * 128, n0 = blockIdx.x * 128;

    int cntb = SS;                    // dense for Q
    if (z > 0) {                      // compacted K/V: skip row tiles past cnt
        cntb = cnt_[m0 >> 11];
        if ((m0 & 2047) >= cntb) return;
    }

    const float* bias = (z == 0) ? bq : (z == 1) ? bk : bv;
    float* bias_s = (float*)smem;
    if (tid < 128) bias_s[tid] = bias[n0 + tid];

    __half* H = (z == 0) ? Qh : (z == 1) ? Kh : Vh;

    GemmCore core;
    core.run(sb, tid, wid, lid,
             A3 + (size_t)z * MROWS * KW + (size_t)m0 * KW,
             Wh + (size_t)z * DF * 1024 + (size_t)n0 * 1024);

    const int g = lid >> 2, t = lid & 3;
    #pragma unroll
    for (int mi = 0; mi < 4; mi++) {
        #pragma unroll
        for (int nj = 0; nj < 8; nj++) {
            int colrel = core.n0w + nj * 8 + 2 * t;
            int col = n0 + colrel;
            int hh = col >> 6, dh = col & 63;
            float c0 = core.acc[mi][nj][0] + bias_s[colrel];
            float c1 = core.acc[mi][nj][1] + bias_s[colrel + 1];
            float c2 = core.acc[mi][nj][2] + bias_s[colrel];
            float c3 = core.acc[mi][nj][3] + bias_s[colrel + 1];
            #pragma unroll
            for (int rr = 0; rr < 2; rr++) {
                int row = m0 + core.m0w + mi * 16 + g + rr * 8;
                int bb_ = row >> 11, sidx = row & 2047;
                size_t dst = ((size_t)(bb_ * NH + hh) * SS + sidx) * DH + dh;
                float x = rr ? c2 : c0, y = rr ? c3 : c1;
                if (z == 0) {
                    uint32_t hp = 0, lp = 0;
                    split_pack(x, y, hp, lp);
                    *reinterpret_cast<uint32_t*>(H + dst)  = hp;
                    *reinterpret_cast<uint32_t*>(Ql + dst) = lp;
                } else {
                    uint32_t hp = (sidx < cntb) ? pack_rn(x, y) : 0u;
                    *reinterpret_cast<uint32_t*>(H + dst) = hp;
                }
            }
        }
    }
}

// ---------------------------------------------------------------------------
// Output projection GEMM: fp32 out
// ---------------------------------------------------------------------------
__global__ void __launch_bounds__(128, 2)
gemm_out(const __half* __restrict__ A3, const __half* __restrict__ Wh,
         const float* __restrict__ bias, float* __restrict__ C)
{
    extern __shared__ char smem[];
    const uint32_t sb = smem_u32(smem);
    const int tid = threadIdx.x, wid = tid >> 5, lid = tid & 31;
    const int m0 = blockIdx.y * 128, n0 = blockIdx.x * 128;

    float* bias_s = (float*)smem;
    if (tid < 128) bias_s[tid] = bias[n0 + tid];

    GemmCore core;
    core.run(sb, tid, wid, lid, A3 + (size_t)m0 * KW, Wh + (size_t)n0 * 1024);

    const int g = lid >> 2, t = lid & 3;
    #pragma unroll
    for (int mi = 0; mi < 4; mi++) {
        #pragma unroll
        for (int nj = 0; nj < 8; nj++) {
            int colrel = core.n0w + nj * 8 + 2 * t;
            int col = n0 + colrel;
            int row0 = m0 + core.m0w + mi * 16 + g;
            float2 v0 = {core.acc[mi][nj][0] + bias_s[colrel],
                         core.acc[mi][nj][1] + bias_s[colrel + 1]};
            float2 v1 = {core.acc[mi][nj][2] + bias_s[colrel],
                         core.acc[mi][nj][3] + bias_s[colrel + 1]};
            *reinterpret_cast<float2*>(C + (size_t)row0 * DF + col) = v0;
            *reinterpret_cast<float2*>(C + (size_t)(row0 + 8) * DF + col) = v1;
        }
    }
}

// ---------------------------------------------------------------------------
// FlashAttention-2 on mma.sync over COMPACTED keys (128 q/CTA, 8 warps x 16
// q-rows). fp16 2-term: S = (Qh+Ql).Kh, O = (Ph+Pl).Vh.
// ---------------------------------------------------------------------------
__global__ void __launch_bounds__(256, 1)
attn_mma(const __half* __restrict__ Qh_, const __half* __restrict__ Ql_,
         const __half* __restrict__ Kh_, const __half* __restrict__ Vh_,
         const int* __restrict__ cnt_, __half* __restrict__ A3out)
{
    extern __shared__ char smem[];
    const uint32_t sb = smem_u32(smem);
    const int tid = threadIdx.x, wid = tid >> 5, lid = tid & 31;
    const int g = lid >> 2, t4 = lid & 3;
    const int b = blockIdx.z, h = blockIdx.y;
    const int bh = b * NH + h;
    const int q0 = blockIdx.x * 128;
    const int m0w = wid * 16;
    const float SC = 0.03125f;

    const int cnt = cnt_[b];
    const int nt = (cnt + 63) >> 6;

    // ---- stage Q (hi,lo) through smem into register a-frags ----
    {
        const size_t qbase = ((size_t)bh * SS + q0);
        #pragma unroll
        for (int i = 0; i < 4; i++) {
            int seg = i * 256 + tid;
            int row = seg >> 3, cs = seg & 7;
            const size_t src = (qbase + row) * DH + cs * 8;
            uint32_t d = sb + (uint32_t)(row * PITCHB + cs * 16);
            cp_async_16(d,          Qh_ + src);
            cp_async_16(d + QL_OFF, Ql_ + src);
        }
    }
    CP_COMMIT(); CP_WAIT0(); __syncthreads();

    uint32_t qh[4][4], ql[4][4];
    #pragma unroll
    for (int kk = 0; kk < 4; kk++) {
        uint32_t a = sb + (uint32_t)((m0w + (lid & 15)) * PITCHB + kk * 32 + ((lid >> 4) << 4));
        ldsm_x4(qh[kk][0], qh[kk][1], qh[kk][2], qh[kk][3], a);
        ldsm_x4(ql[kk][0], ql[kk][1], ql[kk][2], ql[kk][3], a + QL_OFF);
    }
    __syncthreads();

    auto load_tile = [&](int ti, int st) {
        const uint32_t stage = sb + st * ASTRIDE;
        const size_t kbase = ((size_t)bh * SS + ti * 64);
        #pragma unroll
        for (int i = 0; i < 2; i++) {
            int seg = i * 256 + tid;
            int row = seg >> 3, cs = seg & 7;
            size_t src = (kbase + row) * DH + cs * 8;
            uint32_t d = stage + (uint32_t)(row * PITCHB + cs * 16);
            cp_async_16(d,         Kh_ + src);
            cp_async_16(d + ATILE, Vh_ + src);
        }
    };

    float m0 = -1e30f, m1 = -1e30f, l0 = 0.f, l1 = 0.f;
    float o[8][4];
    #pragma unroll
    for (int nj = 0; nj < 8; nj++)
        #pragma unroll
        for (int e = 0; e < 4; e++) o[nj][e] = 0.f;

    if (0 < nt) load_tile(0, 0);
    CP_COMMIT();
    if (1 < nt) load_tile(1, 1);
    CP_COMMIT();

    for (int ti = 0; ti < nt; ti++) {
        const int st = ti % 3;
        CP_WAIT1();
        __syncthreads();                        // sole barrier per tile
        if (ti + 2 < nt) load_tile(ti + 2, (ti + 2) % 3);
        CP_COMMIT();

        const uint32_t sK = sb + st * ASTRIDE;
        const uint32_t sV = sK + ATILE;

        // ---- S = Qh Kh^T + Ql Kh^T ----
        float s[8][4];
        #pragma unroll
        for (int nj = 0; nj < 8; nj++)
            #pragma unroll
            for (int e = 0; e < 4; e++) s[nj][e] = 0.f;

        #pragma unroll
        for (int kk = 0; kk < 4; kk++) {
            uint32_t kb[4][4];
            #pragma unroll
            for (int ni = 0; ni < 4; ni++) {
                uint32_t a = sK + (uint32_t)((ni * 16 + (lid & 7) + ((lid >> 4) & 1) * 8) * PITCHB
                             + kk * 32 + (((lid >> 3) & 1) << 4));
                ldsm_x4(kb[ni][0], kb[ni][1], kb[ni][2], kb[ni][3], a);
            }
            #pragma unroll
            for (int nj = 0; nj < 8; nj++) mma16816(s[nj], qh[kk], &kb[nj >> 1][(nj & 1) * 2]);
            #pragma unroll
            for (int nj = 0; nj < 8; nj++) mma16816(s[nj], ql[kk], &kb[nj >> 1][(nj & 1) * 2]);
        }

        // ---- scale + tail mask + online softmax ----
        const int kbase_idx = ti * 64;
        float tmax0 = -1e30f, tmax1 = -1e30f;
        #pragma unroll
        for (int nj = 0; nj < 8; nj++) {
            int k0i = kbase_idx + nj * 8 + 2 * t4;
            bool v0 = k0i < cnt, v1 = (k0i + 1) < cnt;
            float s0 = v0 ? s[nj][0] * SC : -1e9f;
            float s1 = v1 ? s[nj][1] * SC : -1e9f;
            float s2 = v0 ? s[nj][2] * SC : -1e9f;
            float s3 = v1 ? s[nj][3] * SC : -1e9f;
            s[nj][0] = s0; s[nj][1] = s1; s[nj][2] = s2; s[nj][3] = s3;
            tmax0 = fmaxf(tmax0, fmaxf(s0, s1));
            tmax1 = fmaxf(tmax1, fmaxf(s2, s3));
        }
        tmax0 = fmaxf(tmax0, __shfl_xor_sync(0xffffffffu, tmax0, 1));
        tmax0 = fmaxf(tmax0, __shfl_xor_sync(0xffffffffu, tmax0, 2));
        tmax1 = fmaxf(tmax1, __shfl_xor_sync(0xffffffffu, tmax1, 1));
        tmax1 = fmaxf(tmax1, __shfl_xor_sync(0xffffffffu, tmax1, 2));

        float mn0 = fmaxf(m0, tmax0), mn1 = fmaxf(m1, tmax1);
        float sc0 = __expf(m0 - mn0), sc1 = __expf(m1 - mn1);
        m0 = mn0; m1 = mn1;
        l0 *= sc0; l1 *= sc1;
        #pragma unroll
        for (int nj = 0; nj < 8; nj++) {
            o[nj][0] *= sc0; o[nj][1] *= sc0;
            o[nj][2] *= sc1; o[nj][3] *= sc1;
        }
        #pragma unroll
        for (int nj = 0; nj < 8; nj++) {
            float p0 = __expf(s[nj][0] - m0);
            float p1 = __expf(s[nj][1] - m0);
            float p2 = __expf(s[nj][2] - m1);
            float p3 = __expf(s[nj][3] - m1);
            s[nj][0] = p0; s[nj][1] = p1; s[nj][2] = p2; s[nj][3] = p3;
            l0 += p0 + p1; l1 += p2 + p3;
        }

        // ---- O += Ph Vh + Pl Vh ----
        #pragma unroll
        for (int kk = 0; kk < 4; kk++) {
            uint32_t ah[4], al[4];
            split_pack(s[2 * kk][0],     s[2 * kk][1],     ah[0], al[0]);
            split_pack(s[2 * kk][2],     s[2 * kk][3],     ah[1], al[1]);
            split_pack(s[2 * kk + 1][0], s[2 * kk + 1][1], ah[2], al[2]);
            split_pack(s[2 * kk + 1][2], s[2 * kk + 1][3], ah[3], al[3]);

            uint32_t vb[4][4];
            #pragma unroll
            for (int njp = 0; njp < 4; njp++) {
                uint32_t a = sV + (uint32_t)((16 * kk + (lid & 7) + ((lid >> 3) & 1) * 8) * PITCHB
                             + (16 * njp + ((lid >> 4) & 1) * 8) * 2);
                ldsm_x4_t(vb[njp][0], vb[njp][1], vb[njp][2], vb[njp][3], a);
            }
            #pragma unroll
            for (int nj = 0; nj < 8; nj++) mma16816(o[nj], ah, &vb[nj >> 1][(nj & 1) * 2]);
            #pragma unroll
            for (int nj = 0; nj < 8; nj++) mma16816(o[nj], al, &vb[nj >> 1][(nj & 1) * 2]);
        }
    }
    CP_WAIT0();

    // ---- finalize + write split fp16 straight into A3 [hi|lo] ----
    l0 += __shfl_xor_sync(0xffffffffu, l0, 1);
    l0 += __shfl_xor_sync(0xffffffffu, l0, 2);
    l1 += __shfl_xor_sync(0xffffffffu, l1, 1);
    l1 += __shfl_xor_sync(0xffffffffu, l1, 2);
    float inv0 = 1.f / l0, inv1 = 1.f / l1;

    const int srow = q0 + m0w + g;
    size_t r0 = (size_t)(b * SS + srow) * KW;
    size_t r1 = r0 + (size_t)8 * KW;
    const int colbase = h * DH;

    #pragma unroll
    for (int nj = 0; nj < 8; nj++) {
        int c = colbase + nj * 8 + 2 * t4;
        uint32_t hp, lp;
        split_pack(o[nj][0] * inv0, o[nj][1] * inv0, hp, lp);
        *reinterpret_cast<uint32_t*>(A3out + r0 + c)        = hp;
        *reinterpret_cast<uint32_t*>(A3out + r0 + 1024 + c) = lp;
        split_pack(o[nj][2] * inv1, o[nj][3] * inv1, hp, lp);
        *reinterpret_cast<uint32_t*>(A3out + r1 + c)        = hp;
        *reinterpret_cast<uint32_t*>(A3out + r1 + 1024 + c) = lp;
    }
}

// ---------------------------------------------------------------------------
// launch
// ---------------------------------------------------------------------------
extern "C" void kernel_launch(void* const* d_in, const int* in_sizes, int n_in,
                              void* d_out, int out_size)
{
    const float* Q    = (const float*)d_in[0];
    const float* K    = (const float*)d_in[1];
    const float* V    = (const float*)d_in[2];
    const int*   mask = (const int*)  d_in[3];
    const float* Wq   = (const float*)d_in[4];
    const float* bq   = (const float*)d_in[5];
    const float* Wk   = (const float*)d_in[6];
    const float* bk   = (const float*)d_in[7];
    const float* Wv   = (const float*)d_in[8];
    const float* bv   = (const float*)d_in[9];
    const float* Wo   = (const float*)d_in[10];
    const float* bo   = (const float*)d_in[11];
    float* out = (float*)d_out;

    __half *A3, *Wh, *Qh, *Ql, *Kh, *Vh;
    int *pos, *cnt;
    cudaGetSymbolAddress((void**)&A3, g_A3v3);
    cudaGetSymbolAddress((void**)&Wh, g_Whv4);
    cudaGetSymbolAddress((void**)&Qh, g_Qh);
    cudaGetSymbolAddress((void**)&Ql, g_Ql);
    cudaGetSymbolAddress((void**)&Kh, g_Kh);
    cudaGetSymbolAddress((void**)&Vh, g_Vh);
    cudaGetSymbolAddress((void**)&pos, g_pos);
    cudaGetSymbolAddress((void**)&cnt, g_cnt);

    cudaFuncSetAttribute(gemm_qkv, cudaFuncAttributeMaxDynamicSharedMemorySize, GEMM_SMEM);
    cudaFuncSetAttribute(gemm_out, cudaFuncAttributeMaxDynamicSharedMemorySize, GEMM_SMEM);
    cudaFuncSetAttribute(attn_mma, cudaFuncAttributeMaxDynamicSharedMemorySize, ATTN_SMEM);

    mask_scan<<<BB, 256>>>(mask, pos, cnt);
    conv_w<<<dim3(DF * DF / 1024, 4), 256>>>(Wq, Wk, Wv, Wo, Wh);
    conv_in<<<dim3(MROWS * DF / 1024, 3), 256>>>(Q, K, V, mask, pos, A3);

    gemm_qkv<<<dim3(DF / 128, MROWS / 128, 3), 128, GEMM_SMEM>>>(
        A3, Wh, bq, bk, bv, cnt, Qh, Ql, Kh, Vh);

    attn_mma<<<dim3(SS / 128, NH, BB), 256, ATTN_SMEM>>>(Qh, Ql, Kh, Vh, cnt, A3);

    gemm_out<<<dim3(DF / 128, MROWS / 128), 128, GEMM_SMEM>>>(
        A3, Wh + (size_t)3 * DF * 1024, bo, out);
}

// round 15
// speedup vs baseline: 2.6221x; 1.1784x over previous
#include <cuda_runtime.h>
#include <cuda_fp16.h>
#include <cstdint>

#define DF 1024
#define NH 16
#define DH 64
#define BB 2
#define SS 2048
#define MROWS (BB*SS)

#define KW   2048              // A split width (fp16 [hi|lo])
#define KC   64                // fp16 K per chunk
#define NCHUNK 16              // 1024 / KC unique W chunks
#define NSTAGE 2
#define PITCH  72
#define PITCHB 144
#define TILE_B (128 * PITCHB)               // 18432
#define STAGE_BYTES (3 * TILE_B)            // Ah + Al + W = 55296
#define GEMM_SMEM (512 + NSTAGE * STAGE_BYTES)  // 111104

// attention smem: per stage Kh + Vh tiles only
#define ATILE   9216                       // one 64x64 fp16 tile, pitch 144
#define ASTRIDE (2 * ATILE + 256)          // 18688
#define QL_OFF  18432
#define ATTN_SMEM (3 * ASTRIDE)            // 56064 (covers 36864 Q staging)

// ---------------------------------------------------------------------------
// Scratch
// ---------------------------------------------------------------------------
__device__ __half g_A3v3[3][(size_t)MROWS * KW];   // activations, split [hi|lo]
__device__ __half g_Whv4[4][(size_t)DF * 1024];    // weights, hi only
__device__ __half g_Qh[(size_t)BB * NH * SS * DH];
__device__ __half g_Ql[(size_t)BB * NH * SS * DH];
__device__ __half g_Kh[(size_t)BB * NH * SS * DH];
__device__ __half g_Vh[(size_t)BB * NH * SS * DH];
__device__ int g_pos[BB * SS];
__device__ int g_cnt[BB];

// ---------------------------------------------------------------------------
// helpers
// ---------------------------------------------------------------------------
__device__ __forceinline__ uint32_t smem_u32(const void* p) {
    uint32_t a;
    asm("{ .reg .u64 t; cvta.to.shared.u64 t, %1; cvt.u32.u64 %0, t; }"
        : "=r"(a) : "l"(p));
    return a;
}

__device__ __forceinline__ void cp_async_16(uint32_t dst, const void* src) {
    asm volatile("cp.async.cg.shared.global [%0], [%1], 16;" :: "r"(dst), "l"(src) : "memory");
}
#define CP_COMMIT() asm volatile("cp.async.commit_group;" ::: "memory")
#define CP_WAIT1()  asm volatile("cp.async.wait_group 1;" ::: "memory")
#define CP_WAIT0()  asm volatile("cp.async.wait_group 0;" ::: "memory")

__device__ __forceinline__ void ldsm_x4(uint32_t& r0, uint32_t& r1, uint32_t& r2,
                                        uint32_t& r3, uint32_t addr) {
    asm volatile("ldmatrix.sync.aligned.m8n8.x4.shared.b16 {%0,%1,%2,%3}, [%4];"
                 : "=r"(r0), "=r"(r1), "=r"(r2), "=r"(r3) : "r"(addr));
}
__device__ __forceinline__ void ldsm_x4_t(uint32_t& r0, uint32_t& r1, uint32_t& r2,
                                          uint32_t& r3, uint32_t addr) {
    asm volatile("ldmatrix.sync.aligned.m8n8.x4.trans.shared.b16 {%0,%1,%2,%3}, [%4];"
                 : "=r"(r0), "=r"(r1), "=r"(r2), "=r"(r3) : "r"(addr));
}

__device__ __forceinline__ void mma16816(float* d, const uint32_t* a, const uint32_t* b) {
    asm volatile(
        "mma.sync.aligned.m16n8k16.row.col.f32.f16.f16.f32 "
        "{%0,%1,%2,%3}, {%4,%5,%6,%7}, {%8,%9}, {%0,%1,%2,%3};"
        : "+f"(d[0]), "+f"(d[1]), "+f"(d[2]), "+f"(d[3])
        : "r"(a[0]), "r"(a[1]), "r"(a[2]), "r"(a[3]), "r"(b[0]), "r"(b[1]));
}

__device__ __forceinline__ uint32_t h2pack(__half a, __half b) {
    __half2 h = __halves2half2(a, b);
    uint32_t r; memcpy(&r, &h, 4); return r;
}
__device__ __forceinline__ uint32_t pack_rn(float x, float y) {
    __half2 h = __floats2half2_rn(x, y);
    uint32_t r; memcpy(&r, &h, 4); return r;
}
// fp16 round-to-nearest hi + residual lo
__device__ __forceinline__ void split_pack(float x, float y, uint32_t& hp, uint32_t& lp) {
    __half hx = __float2half_rn(x), hy = __float2half_rn(y);
    hp = h2pack(hx, hy);
    lp = h2pack(__float2half_rn(x - __half2float(hx)),
                __float2half_rn(y - __half2float(hy)));
}

// ---------------------------------------------------------------------------
// mask prefix scan: pos[b][s] = #valid keys before s ; cnt[b] = total valid
// ---------------------------------------------------------------------------
__global__ __launch_bounds__(256) void mask_scan(const int* __restrict__ mask,
                                                 int* __restrict__ pos, int* __restrict__ cnt)
{
    __shared__ int partial[256];
    const int b = blockIdx.x, tid = threadIdx.x;
    const int base = b * SS + tid * 8;
    int v[8], s = 0;
    #pragma unroll
    for (int i = 0; i < 8; i++) { v[i] = (mask[base + i] != 0); s += v[i]; }
    partial[tid] = s;
    __syncthreads();
    for (int off = 1; off < 256; off <<= 1) {
        int t = (tid >= off) ? partial[tid - off] : 0;
        __syncthreads();
        partial[tid] += t;
        __syncthreads();
    }
    int ex = (tid == 0) ? 0 : partial[tid - 1];
    #pragma unroll
    for (int i = 0; i < 8; i++) { pos[base + i] = ex; ex += v[i]; }
    if (tid == 255) cnt[b] = partial[255];
}

// ---------------------------------------------------------------------------
// Split-fp16 conversions. conv_in: z=0 Q dense; z=1 K, z=2 V with row
// compaction. Output row layout: [hi(1024) | lo(1024)].
// ---------------------------------------------------------------------------
__global__ __launch_bounds__(256) void conv_in(const float* __restrict__ Q,
                                               const float* __restrict__ K,
                                               const float* __restrict__ V,
                                               const int* __restrict__ mask,
                                               const int* __restrict__ pos,
                                               __half* __restrict__ A3)
{
    const int z = blockIdx.y;
    const float* X = z == 0 ? Q : (z == 1 ? K : V);
    __half* Y = A3 + (size_t)z * MROWS * KW;
    int idx = (blockIdx.x * 256 + threadIdx.x) * 4;
    int r = idx >> 10, k = idx & 1023;
    int rr = r;
    if (z > 0) {
        int bb_ = r >> 11, sidx = r & 2047;
        if (mask[bb_ * SS + sidx] == 0) return;       // masked key row: skip
        rr = bb_ * SS + pos[bb_ * SS + sidx];         // compacted destination
    }
    float4 x = *reinterpret_cast<const float4*>(X + idx);
    float v[4] = {x.x, x.y, x.z, x.w};
    __half hi[4], lo[4];
    #pragma unroll
    for (int i = 0; i < 4; i++) {
        hi[i] = __float2half_rn(v[i]);
        lo[i] = __float2half_rn(v[i] - __half2float(hi[i]));
    }
    uint64_t hip, lop;
    memcpy(&hip, hi, 8);
    memcpy(&lop, lo, 8);
    size_t base = (size_t)rr * KW + k;
    *reinterpret_cast<uint64_t*>(Y + base)        = hip;
    if (z == 0)                                        // lo only needed for Q
        *reinterpret_cast<uint64_t*>(Y + base + 1024) = lop;
}

__global__ __launch_bounds__(256) void conv_w(const float* __restrict__ Wq,
                                              const float* __restrict__ Wk,
                                              const float* __restrict__ Wv,
                                              const float* __restrict__ Wo,
                                              __half* __restrict__ Wh)
{
    const float* X = blockIdx.y == 0 ? Wq : (blockIdx.y == 1 ? Wk :
                      (blockIdx.y == 2 ? Wv : Wo));
    __half* Y = Wh + (size_t)blockIdx.y * DF * 1024;
    int idx = (blockIdx.x * 256 + threadIdx.x) * 4;
    float4 x = *reinterpret_cast<const float4*>(X + idx);
    float v[4] = {x.x, x.y, x.z, x.w};
    __half hi[4];
    #pragma unroll
    for (int i = 0; i < 4; i++) hi[i] = __float2half_rn(v[i]);
    uint64_t hip;
    memcpy(&hip, hi, 8);
    *reinterpret_cast<uint64_t*>(Y + idx) = hip;
}

// ---------------------------------------------------------------------------
// GEMM mainloop: 128 threads / 4 warps (2M x 2N), warp tile 64x64.
// Merged-W: per chunk load Ah(k), [Al(k+1024)], W(k); compute Ah.W (+ Al.W
// when lo_term) against ONE set of W b-frags. 16 chunks, 2-stage buffer.
// ---------------------------------------------------------------------------
struct GemmCore {
    float acc[4][8][4];
    int m0w, n0w;

    __device__ __forceinline__ void run(uint32_t sb, int tid, int wid, int lid,
                                        const __half* Abase,
                                        const __half* Wbase, bool lo_term) {
        m0w = (wid & 1) * 64;
        n0w = (wid >> 1) * 64;
        #pragma unroll
        for (int mi = 0; mi < 4; mi++)
            #pragma unroll
            for (int nj = 0; nj < 8; nj++)
                #pragma unroll
                for (int e = 0; e < 4; e++) acc[mi][nj][e] = 0.f;

        auto load_chunk = [&](int c, int s) {
            const int k0 = c * KC;
            const uint32_t stage = sb + 512 + s * STAGE_BYTES;
            #pragma unroll
            for (int i = 0; i < 24; i++) {
                int seg = i * 128 + tid;
                int op  = seg >> 10;                // 0=Ah, 1=Al, 2=W
                if (op == 1 && !lo_term) continue;  // skip lo tile
                int r   = (seg & 1023) >> 3;
                int cs  = seg & 7;
                uint32_t dst = stage + op * TILE_B + (uint32_t)(r * PITCHB + cs * 16);
                const __half* src = (op == 2)
                    ? Wbase + (size_t)r * 1024 + k0 + cs * 8
                    : Abase + (size_t)r * KW + op * 1024 + k0 + cs * 8;
                cp_async_16(dst, src);
            }
        };

        load_chunk(0, 0); CP_COMMIT();

        for (int c = 0; c < NCHUNK; c++) {
            const int s = c & 1;
            if (c + 1 < NCHUNK) load_chunk(c + 1, (c + 1) & 1);
            CP_COMMIT();
            CP_WAIT1();                 // chunk c resident (c+1 in flight)
            __syncthreads();            // visibility of c across threads

            const uint32_t sAh = sb + 512 + s * STAGE_BYTES;
            const uint32_t sAl = sAh + TILE_B;
            const uint32_t sW  = sAh + 2 * TILE_B;
            #pragma unroll
            for (int kk = 0; kk < 4; kk++) {
                uint32_t b[8][2];
                #pragma unroll
                for (int ni = 0; ni < 4; ni++) {
                    uint32_t addr = sW + (uint32_t)((n0w + ni * 16 + (lid & 7)
                                     + ((lid >> 4) & 1) * 8) * PITCHB
                                     + kk * 32 + (((lid >> 3) & 1) << 4));
                    uint32_t r0, r1, r2, r3;
                    ldsm_x4(r0, r1, r2, r3, addr);
                    b[2 * ni][0] = r0; b[2 * ni][1] = r1;
                    b[2 * ni + 1][0] = r2; b[2 * ni + 1][1] = r3;
                }
                uint32_t a[4][4];
                #pragma unroll
                for (int mi = 0; mi < 4; mi++) {
                    uint32_t addr = sAh + (uint32_t)((m0w + mi * 16 + (lid & 15)) * PITCHB
                                     + kk * 32 + ((lid >> 4) << 4));
                    ldsm_x4(a[mi][0], a[mi][1], a[mi][2], a[mi][3], addr);
                }
                #pragma unroll
                for (int mi = 0; mi < 4; mi++)
                    #pragma unroll
                    for (int nj = 0; nj < 8; nj++)
                        mma16816(acc[mi][nj], a[mi], b[nj]);
                if (lo_term) {
                    #pragma unroll
                    for (int mi = 0; mi < 4; mi++) {
                        uint32_t addr = sAl + (uint32_t)((m0w + mi * 16 + (lid & 15)) * PITCHB
                                         + kk * 32 + ((lid >> 4) << 4));
                        ldsm_x4(a[mi][0], a[mi][1], a[mi][2], a[mi][3], addr);
                    }
                    #pragma unroll
                    for (int mi = 0; mi < 4; mi++)
                        #pragma unroll
                        for (int nj = 0; nj < 8; nj++)
                            mma16816(acc[mi][nj], a[mi], b[nj]);
                }
            }
            __syncthreads();            // reads of stage s done before reuse
        }
        CP_WAIT0();
    }
};

// ---------------------------------------------------------------------------
// Fused QKV projection GEMM over pre-compacted inputs.
// z=0: Q dense, 2-term -> (Qh, Ql).  z=1: K hi-only -> Kh.  z=2: V -> Vh.
// Rows >= cnt in the boundary tile store ZEROS (tail guard).
// ---------------------------------------------------------------------------
__global__ void __launch_bounds__(128, 2)
gemm_qkv(const __half* __restrict__ A3, const __half* __restrict__ Wh,
         const float* __restrict__ bq, const float* __restrict__ bk,
         const float* __restrict__ bv, const int* __restrict__ cnt_,
         __half* __restrict__ Qh, __half* __restrict__ Ql,
         __half* __restrict__ Kh, __half* __restrict__ Vh)
{
    extern __shared__ char smem[];
    const uint32_t sb = smem_u32(smem);
    const int tid = threadIdx.x, wid = tid >> 5, lid = tid & 31;
    const int z = blockIdx.z;
    const int m0 = blockIdx.y * 128, n0 = blockIdx.x * 128;

    int cntb = SS;                    // dense for Q
    if (z > 0) {                      // compacted K/V: skip row tiles past cnt
        cntb = cnt_[m0 >> 11];
        if ((m0 & 2047) >= cntb) return;
    }

    const float* bias = (z == 0) ? bq : (z == 1) ? bk : bv;
    float* bias_s = (float*)smem;
    if (tid < 128) bias_s[tid] = bias[n0 + tid];

    __half* H = (z == 0) ? Qh : (z == 1) ? Kh : Vh;

    GemmCore core;
    core.run(sb, tid, wid, lid,
             A3 + (size_t)z * MROWS * KW + (size_t)m0 * KW,
             Wh + (size_t)z * DF * 1024 + (size_t)n0 * 1024,
             /*lo_term=*/z == 0);

    const int g = lid >> 2, t = lid & 3;
    #pragma unroll
    for (int mi = 0; mi < 4; mi++) {
        #pragma unroll
        for (int nj = 0; nj < 8; nj++) {
            int colrel = core.n0w + nj * 8 + 2 * t;
            int col = n0 + colrel;
            int hh = col >> 6, dh = col & 63;
            float c0 = core.acc[mi][nj][0] + bias_s[colrel];
            float c1 = core.acc[mi][nj][1] + bias_s[colrel + 1];
            float c2 = core.acc[mi][nj][2] + bias_s[colrel];
            float c3 = core.acc[mi][nj][3] + bias_s[colrel + 1];
            #pragma unroll
            for (int rr = 0; rr < 2; rr++) {
                int row = m0 + core.m0w + mi * 16 + g + rr * 8;
                int bb_ = row >> 11, sidx = row & 2047;
                size_t dst = ((size_t)(bb_ * NH + hh) * SS + sidx) * DH + dh;
                float x = rr ? c2 : c0, y = rr ? c3 : c1;
                if (z == 0) {
                    uint32_t hp = 0, lp = 0;
                    split_pack(x, y, hp, lp);
                    *reinterpret_cast<uint32_t*>(H + dst)  = hp;
                    *reinterpret_cast<uint32_t*>(Ql + dst) = lp;
                } else {
                    uint32_t hp = (sidx < cntb) ? pack_rn(x, y) : 0u;
                    *reinterpret_cast<uint32_t*>(H + dst) = hp;
                }
            }
        }
    }
}

// ---------------------------------------------------------------------------
// Output projection GEMM: fp32 out (2-term A)
// ---------------------------------------------------------------------------
__global__ void __launch_bounds__(128, 2)
gemm_out(const __half* __restrict__ A3, const __half* __restrict__ Wh,
         const float* __restrict__ bias, float* __restrict__ C)
{
    extern __shared__ char smem[];
    const uint32_t sb = smem_u32(smem);
    const int tid = threadIdx.x, wid = tid >> 5, lid = tid & 31;
    const int m0 = blockIdx.y * 128, n0 = blockIdx.x * 128;

    float* bias_s = (float*)smem;
    if (tid < 128) bias_s[tid] = bias[n0 + tid];

    GemmCore core;
    core.run(sb, tid, wid, lid, A3 + (size_t)m0 * KW, Wh + (size_t)n0 * 1024,
             /*lo_term=*/true);

    const int g = lid >> 2, t = lid & 3;
    #pragma unroll
    for (int mi = 0; mi < 4; mi++) {
        #pragma unroll
        for (int nj = 0; nj < 8; nj++) {
            int colrel = core.n0w + nj * 8 + 2 * t;
            int col = n0 + colrel;
            int row0 = m0 + core.m0w + mi * 16 + g;
            float2 v0 = {core.acc[mi][nj][0] + bias_s[colrel],
                         core.acc[mi][nj][1] + bias_s[colrel + 1]};
            float2 v1 = {core.acc[mi][nj][2] + bias_s[colrel],
                         core.acc[mi][nj][3] + bias_s[colrel + 1]};
            *reinterpret_cast<float2*>(C + (size_t)row0 * DF + col) = v0;
            *reinterpret_cast<float2*>(C + (size_t)(row0 + 8) * DF + col) = v1;
        }
    }
}

// ---------------------------------------------------------------------------
// FlashAttention-2 on mma.sync over COMPACTED keys (128 q/CTA, 8 warps x 16
// q-rows). S = (Qh+Ql).Kh ; O = Ph.Vh (P rounded to fp16 once).
// ---------------------------------------------------------------------------
__global__ void __launch_bounds__(256, 1)
attn_mma(const __half* __restrict__ Qh_, const __half* __restrict__ Ql_,
         const __half* __restrict__ Kh_, const __half* __restrict__ Vh_,
         const int* __restrict__ cnt_, __half* __restrict__ A3out)
{
    extern __shared__ char smem[];
    const uint32_t sb = smem_u32(smem);
    const int tid = threadIdx.x, wid = tid >> 5, lid = tid & 31;
    const int g = lid >> 2, t4 = lid & 3;
    const int b = blockIdx.z, h = blockIdx.y;
    const int bh = b * NH + h;
    const int q0 = blockIdx.x * 128;
    const int m0w = wid * 16;
    const float SC = 0.03125f;

    const int cnt = cnt_[b];
    const int nt = (cnt + 63) >> 6;

    // ---- stage Q (hi,lo) through smem into register a-frags ----
    {
        const size_t qbase = ((size_t)bh * SS + q0);
        #pragma unroll
        for (int i = 0; i < 4; i++) {
            int seg = i * 256 + tid;
            int row = seg >> 3, cs = seg & 7;
            const size_t src = (qbase + row) * DH + cs * 8;
            uint32_t d = sb + (uint32_t)(row * PITCHB + cs * 16);
            cp_async_16(d,          Qh_ + src);
            cp_async_16(d + QL_OFF, Ql_ + src);
        }
    }
    CP_COMMIT(); CP_WAIT0(); __syncthreads();

    uint32_t qh[4][4], ql[4][4];
    #pragma unroll
    for (int kk = 0; kk < 4; kk++) {
        uint32_t a = sb + (uint32_t)((m0w + (lid & 15)) * PITCHB + kk * 32 + ((lid >> 4) << 4));
        ldsm_x4(qh[kk][0], qh[kk][1], qh[kk][2], qh[kk][3], a);
        ldsm_x4(ql[kk][0], ql[kk][1], ql[kk][2], ql[kk][3], a + QL_OFF);
    }
    __syncthreads();

    auto load_tile = [&](int ti, int st) {
        const uint32_t stage = sb + st * ASTRIDE;
        const size_t kbase = ((size_t)bh * SS + ti * 64);
        #pragma unroll
        for (int i = 0; i < 2; i++) {
            int seg = i * 256 + tid;
            int row = seg >> 3, cs = seg & 7;
            size_t src = (kbase + row) * DH + cs * 8;
            uint32_t d = stage + (uint32_t)(row * PITCHB + cs * 16);
            cp_async_16(d,         Kh_ + src);
            cp_async_16(d + ATILE, Vh_ + src);
        }
    };

    float m0 = -1e30f, m1 = -1e30f, l0 = 0.f, l1 = 0.f;
    float o[8][4];
    #pragma unroll
    for (int nj = 0; nj < 8; nj++)
        #pragma unroll
        for (int e = 0; e < 4; e++) o[nj][e] = 0.f;

    if (0 < nt) load_tile(0, 0);
    CP_COMMIT();
    if (1 < nt) load_tile(1, 1);
    CP_COMMIT();

    for (int ti = 0; ti < nt; ti++) {
        const int st = ti % 3;
        CP_WAIT1();
        __syncthreads();                        // sole barrier per tile
        if (ti + 2 < nt) load_tile(ti + 2, (ti + 2) % 3);
        CP_COMMIT();

        const uint32_t sK = sb + st * ASTRIDE;
        const uint32_t sV = sK + ATILE;

        // ---- S = Qh Kh^T + Ql Kh^T ----
        float s[8][4];
        #pragma unroll
        for (int nj = 0; nj < 8; nj++)
            #pragma unroll
            for (int e = 0; e < 4; e++) s[nj][e] = 0.f;

        #pragma unroll
        for (int kk = 0; kk < 4; kk++) {
            uint32_t kb[4][4];
            #pragma unroll
            for (int ni = 0; ni < 4; ni++) {
                uint32_t a = sK + (uint32_t)((ni * 16 + (lid & 7) + ((lid >> 4) & 1) * 8) * PITCHB
                             + kk * 32 + (((lid >> 3) & 1) << 4));
                ldsm_x4(kb[ni][0], kb[ni][1], kb[ni][2], kb[ni][3], a);
            }
            #pragma unroll
            for (int nj = 0; nj < 8; nj++) mma16816(s[nj], qh[kk], &kb[nj >> 1][(nj & 1) * 2]);
            #pragma unroll
            for (int nj = 0; nj < 8; nj++) mma16816(s[nj], ql[kk], &kb[nj >> 1][(nj & 1) * 2]);
        }

        // ---- scale + tail mask + online softmax ----
        const int kbase_idx = ti * 64;
        float tmax0 = -1e30f, tmax1 = -1e30f;
        #pragma unroll
        for (int nj = 0; nj < 8; nj++) {
            int k0i = kbase_idx + nj * 8 + 2 * t4;
            bool v0 = k0i < cnt, v1 = (k0i + 1) < cnt;
            float s0 = v0 ? s[nj][0] * SC : -1e9f;
            float s1 = v1 ? s[nj][1] * SC : -1e9f;
            float s2 = v0 ? s[nj][2] * SC : -1e9f;
            float s3 = v1 ? s[nj][3] * SC : -1e9f;
            s[nj][0] = s0; s[nj][1] = s1; s[nj][2] = s2; s[nj][3] = s3;
            tmax0 = fmaxf(tmax0, fmaxf(s0, s1));
            tmax1 = fmaxf(tmax1, fmaxf(s2, s3));
        }
        tmax0 = fmaxf(tmax0, __shfl_xor_sync(0xffffffffu, tmax0, 1));
        tmax0 = fmaxf(tmax0, __shfl_xor_sync(0xffffffffu, tmax0, 2));
        tmax1 = fmaxf(tmax1, __shfl_xor_sync(0xffffffffu, tmax1, 1));
        tmax1 = fmaxf(tmax1, __shfl_xor_sync(0xffffffffu, tmax1, 2));

        float mn0 = fmaxf(m0, tmax0), mn1 = fmaxf(m1, tmax1);
        float sc0 = __expf(m0 - mn0), sc1 = __expf(m1 - mn1);
        m0 = mn0; m1 = mn1;
        l0 *= sc0; l1 *= sc1;
        #pragma unroll
        for (int nj = 0; nj < 8; nj++) {
            o[nj][0] *= sc0; o[nj][1] *= sc0;
            o[nj][2] *= sc1; o[nj][3] *= sc1;
        }
        #pragma unroll
        for (int nj = 0; nj < 8; nj++) {
            float p0 = __expf(s[nj][0] - m0);
            float p1 = __expf(s[nj][1] - m0);
            float p2 = __expf(s[nj][2] - m1);
            float p3 = __expf(s[nj][3] - m1);
            s[nj][0] = p0; s[nj][1] = p1; s[nj][2] = p2; s[nj][3] = p3;
            l0 += p0 + p1; l1 += p2 + p3;
        }

        // ---- O += Ph Vh (single-term P) ----
        #pragma unroll
        for (int kk = 0; kk < 4; kk++) {
            uint32_t ah[4];
            ah[0] = pack_rn(s[2 * kk][0],     s[2 * kk][1]);
            ah[1] = pack_rn(s[2 * kk][2],     s[2 * kk][3]);
            ah[2] = pack_rn(s[2 * kk + 1][0], s[2 * kk + 1][1]);
            ah[3] = pack_rn(s[2 * kk + 1][2], s[2 * kk + 1][3]);

            uint32_t vb[4][4];
            #pragma unroll
            for (int njp = 0; njp < 4; njp++) {
                uint32_t a = sV + (uint32_t)((16 * kk + (lid & 7) + ((lid >> 3) & 1) * 8) * PITCHB
                             + (16 * njp + ((lid >> 4) & 1) * 8) * 2);
                ldsm_x4_t(vb[njp][0], vb[njp][1], vb[njp][2], vb[njp][3], a);
            }
            #pragma unroll
            for (int nj = 0; nj < 8; nj++) mma16816(o[nj], ah, &vb[nj >> 1][(nj & 1) * 2]);
        }
    }
    CP_WAIT0();

    // ---- finalize + write split fp16 straight into A3 [hi|lo] ----
    l0 += __shfl_xor_sync(0xffffffffu, l0, 1);
    l0 += __shfl_xor_sync(0xffffffffu, l0, 2);
    l1 += __shfl_xor_sync(0xffffffffu, l1, 1);
    l1 += __shfl_xor_sync(0xffffffffu, l1, 2);
    float inv0 = 1.f / l0, inv1 = 1.f / l1;

    const int srow = q0 + m0w + g;
    size_t r0 = (size_t)(b * SS + srow) * KW;
    size_t r1 = r0 + (size_t)8 * KW;
    const int colbase = h * DH;

    #pragma unroll
    for (int nj = 0; nj < 8; nj++) {
        int c = colbase + nj * 8 + 2 * t4;
        uint32_t hp, lp;
        split_pack(o[nj][0] * inv0, o[nj][1] * inv0, hp, lp);
        *reinterpret_cast<uint32_t*>(A3out + r0 + c)        = hp;
        *reinterpret_cast<uint32_t*>(A3out + r0 + 1024 + c) = lp;
        split_pack(o[nj][2] * inv1, o[nj][3] * inv1, hp, lp);
        *reinterpret_cast<uint32_t*>(A3out + r1 + c)        = hp;
        *reinterpret_cast<uint32_t*>(A3out + r1 + 1024 + c) = lp;
    }
}

// ---------------------------------------------------------------------------
// launch
// ---------------------------------------------------------------------------
extern "C" void kernel_launch(void* const* d_in, const int* in_sizes, int n_in,
                              void* d_out, int out_size)
{
    const float* Q    = (const float*)d_in[0];
    const float* K    = (const float*)d_in[1];
    const float* V    = (const float*)d_in[2];
    const int*   mask = (const int*)  d_in[3];
    const float* Wq   = (const float*)d_in[4];
    const float* bq   = (const float*)d_in[5];
    const float* Wk   = (const float*)d_in[6];
    const float* bk   = (const float*)d_in[7];
    const float* Wv   = (const float*)d_in[8];
    const float* bv   = (const float*)d_in[9];
    const float* Wo   = (const float*)d_in[10];
    const float* bo   = (const float*)d_in[11];
    float* out = (float*)d_out;

    __half *A3, *Wh, *Qh, *Ql, *Kh, *Vh;
    int *pos, *cnt;
    cudaGetSymbolAddress((void**)&A3, g_A3v3);
    cudaGetSymbolAddress((void**)&Wh, g_Whv4);
    cudaGetSymbolAddress((void**)&Qh, g_Qh);
    cudaGetSymbolAddress((void**)&Ql, g_Ql);
    cudaGetSymbolAddress((void**)&Kh, g_Kh);
    cudaGetSymbolAddress((void**)&Vh, g_Vh);
    cudaGetSymbolAddress((void**)&pos, g_pos);
    cudaGetSymbolAddress((void**)&cnt, g_cnt);

    cudaFuncSetAttribute(gemm_qkv, cudaFuncAttributeMaxDynamicSharedMemorySize, GEMM_SMEM);
    cudaFuncSetAttribute(gemm_out, cudaFuncAttributeMaxDynamicSharedMemorySize, GEMM_SMEM);
    cudaFuncSetAttribute(attn_mma, cudaFuncAttributeMaxDynamicSharedMemorySize, ATTN_SMEM);

    mask_scan<<<BB, 256>>>(mask, pos, cnt);
    conv_w<<<dim3(DF * DF / 1024, 4), 256>>>(Wq, Wk, Wv, Wo, Wh);
    conv_in<<<dim3(MROWS * DF / 1024, 3), 256>>>(Q, K, V, mask, pos, A3);

    gemm_qkv<<<dim3(DF / 128, MROWS / 128, 3), 128, GEMM_SMEM>>>(
        A3, Wh, bq, bk, bv, cnt, Qh, Ql, Kh, Vh);

    attn_mma<<<dim3(SS / 128, NH, BB), 256, ATTN_SMEM>>>(Qh, Ql, Kh, Vh, cnt, A3);

    gemm_out<<<dim3(DF / 128, MROWS / 128), 128, GEMM_SMEM>>>(
        A3, Wh + (size_t)3 * DF * 1024, bo, out);
}

// round 16
// speedup vs baseline: 3.3263x; 1.2686x over previous
#include <cuda_runtime.h>
#include <cuda_fp16.h>
#include <cstdint>

#define DF 1024
#define NH 16
#define DH 64
#define BB 2
#define SS 2048
#define MROWS (BB*SS)

#define KW   1024              // A width (fp16, hi only)
#define KC   64                // fp16 K per chunk
#define NCHUNK 16              // 1024 / KC
#define NSTAGE 3
#define PITCH  72
#define PITCHB 144
#define TILE_B (128 * PITCHB)               // 18432
#define STAGE_BYTES (2 * TILE_B)            // A + W = 36864
#define GEMM_SMEM (512 + NSTAGE * STAGE_BYTES)  // 111104

// attention smem: per stage Kh + Vh tiles
#define ATILE   9216                       // one 64x64 fp16 tile, pitch 144
#define ASTRIDE (2 * ATILE + 256)          // 18688
#define ATTN_SMEM (3 * ASTRIDE)            // 56064 (covers 18432 Q staging)

// ---------------------------------------------------------------------------
// Scratch
// ---------------------------------------------------------------------------
__device__ __half g_A3v3[3][(size_t)MROWS * KW];   // activations, fp16
__device__ __half g_Whv4[4][(size_t)DF * 1024];    // weights, fp16
__device__ __half g_Qh[(size_t)BB * NH * SS * DH];
__device__ __half g_Kh[(size_t)BB * NH * SS * DH];
__device__ __half g_Vh[(size_t)BB * NH * SS * DH];
__device__ int g_pos[BB * SS];
__device__ int g_cnt[BB];

// ---------------------------------------------------------------------------
// helpers
// ---------------------------------------------------------------------------
__device__ __forceinline__ uint32_t smem_u32(const void* p) {
    uint32_t a;
    asm("{ .reg .u64 t; cvta.to.shared.u64 t, %1; cvt.u32.u64 %0, t; }"
        : "=r"(a) : "l"(p));
    return a;
}

__device__ __forceinline__ void cp_async_16(uint32_t dst, const void* src) {
    asm volatile("cp.async.cg.shared.global [%0], [%1], 16;" :: "r"(dst), "l"(src) : "memory");
}
#define CP_COMMIT() asm volatile("cp.async.commit_group;" ::: "memory")
#define CP_WAIT1()  asm volatile("cp.async.wait_group 1;" ::: "memory")
#define CP_WAIT0()  asm volatile("cp.async.wait_group 0;" ::: "memory")

__device__ __forceinline__ void ldsm_x4(uint32_t& r0, uint32_t& r1, uint32_t& r2,
                                        uint32_t& r3, uint32_t addr) {
    asm volatile("ldmatrix.sync.aligned.m8n8.x4.shared.b16 {%0,%1,%2,%3}, [%4];"
                 : "=r"(r0), "=r"(r1), "=r"(r2), "=r"(r3) : "r"(addr));
}
__device__ __forceinline__ void ldsm_x4_t(uint32_t& r0, uint32_t& r1, uint32_t& r2,
                                          uint32_t& r3, uint32_t addr) {
    asm volatile("ldmatrix.sync.aligned.m8n8.x4.trans.shared.b16 {%0,%1,%2,%3}, [%4];"
                 : "=r"(r0), "=r"(r1), "=r"(r2), "=r"(r3) : "r"(addr));
}

__device__ __forceinline__ void mma16816(float* d, const uint32_t* a, const uint32_t* b) {
    asm volatile(
        "mma.sync.aligned.m16n8k16.row.col.f32.f16.f16.f32 "
        "{%0,%1,%2,%3}, {%4,%5,%6,%7}, {%8,%9}, {%0,%1,%2,%3};"
        : "+f"(d[0]), "+f"(d[1]), "+f"(d[2]), "+f"(d[3])
        : "r"(a[0]), "r"(a[1]), "r"(a[2]), "r"(a[3]), "r"(b[0]), "r"(b[1]));
}

__device__ __forceinline__ uint32_t pack_rn(float x, float y) {
    __half2 h = __floats2half2_rn(x, y);
    uint32_t r; memcpy(&r, &h, 4); return r;
}

// ---------------------------------------------------------------------------
// mask prefix scan: pos[b][s] = #valid keys before s ; cnt[b] = total valid
// ---------------------------------------------------------------------------
__global__ __launch_bounds__(256) void mask_scan(const int* __restrict__ mask,
                                                 int* __restrict__ pos, int* __restrict__ cnt)
{
    __shared__ int partial[256];
    const int b = blockIdx.x, tid = threadIdx.x;
    const int base = b * SS + tid * 8;
    int v[8], s = 0;
    #pragma unroll
    for (int i = 0; i < 8; i++) { v[i] = (mask[base + i] != 0); s += v[i]; }
    partial[tid] = s;
    __syncthreads();
    for (int off = 1; off < 256; off <<= 1) {
        int t = (tid >= off) ? partial[tid - off] : 0;
        __syncthreads();
        partial[tid] += t;
        __syncthreads();
    }
    int ex = (tid == 0) ? 0 : partial[tid - 1];
    #pragma unroll
    for (int i = 0; i < 8; i++) { pos[base + i] = ex; ex += v[i]; }
    if (tid == 255) cnt[b] = partial[255];
}

// ---------------------------------------------------------------------------
// fp16 conversions. conv_in: z=0 Q dense; z=1 K, z=2 V with row compaction.
// ---------------------------------------------------------------------------
__global__ __launch_bounds__(256) void conv_in(const float* __restrict__ Q,
                                               const float* __restrict__ K,
                                               const float* __restrict__ V,
                                               const int* __restrict__ mask,
                                               const int* __restrict__ pos,
                                               __half* __restrict__ A3)
{
    const int z = blockIdx.y;
    const float* X = z == 0 ? Q : (z == 1 ? K : V);
    __half* Y = A3 + (size_t)z * MROWS * KW;
    int idx = (blockIdx.x * 256 + threadIdx.x) * 4;
    int r = idx >> 10, k = idx & 1023;
    int rr = r;
    if (z > 0) {
        int bb_ = r >> 11, sidx = r & 2047;
        if (mask[bb_ * SS + sidx] == 0) return;       // masked key row: skip
        rr = bb_ * SS + pos[bb_ * SS + sidx];         // compacted destination
    }
    float4 x = *reinterpret_cast<const float4*>(X + idx);
    float v[4] = {x.x, x.y, x.z, x.w};
    __half hi[4];
    #pragma unroll
    for (int i = 0; i < 4; i++) hi[i] = __float2half_rn(v[i]);
    uint64_t hip;
    memcpy(&hip, hi, 8);
    *reinterpret_cast<uint64_t*>(Y + (size_t)rr * KW + k) = hip;
}

__global__ __launch_bounds__(256) void conv_w(const float* __restrict__ Wq,
                                              const float* __restrict__ Wk,
                                              const float* __restrict__ Wv,
                                              const float* __restrict__ Wo,
                                              __half* __restrict__ Wh)
{
    const float* X = blockIdx.y == 0 ? Wq : (blockIdx.y == 1 ? Wk :
                      (blockIdx.y == 2 ? Wv : Wo));
    __half* Y = Wh + (size_t)blockIdx.y * DF * 1024;
    int idx = (blockIdx.x * 256 + threadIdx.x) * 4;
    float4 x = *reinterpret_cast<const float4*>(X + idx);
    float v[4] = {x.x, x.y, x.z, x.w};
    __half hi[4];
    #pragma unroll
    for (int i = 0; i < 4; i++) hi[i] = __float2half_rn(v[i]);
    uint64_t hip;
    memcpy(&hip, hi, 8);
    *reinterpret_cast<uint64_t*>(Y + idx) = hip;
}

// ---------------------------------------------------------------------------
// GEMM mainloop: 128 threads / 4 warps (2M x 2N), warp tile 64x64.
// Pure fp16 1-term, 16 chunks of K=64, 3-stage pipeline, one barrier/chunk.
// ---------------------------------------------------------------------------
struct GemmCore {
    float acc[4][8][4];
    int m0w, n0w;

    __device__ __forceinline__ void run(uint32_t sb, int tid, int wid, int lid,
                                        const __half* Abase,
                                        const __half* Wbase) {
        m0w = (wid & 1) * 64;
        n0w = (wid >> 1) * 64;
        #pragma unroll
        for (int mi = 0; mi < 4; mi++)
            #pragma unroll
            for (int nj = 0; nj < 8; nj++)
                #pragma unroll
                for (int e = 0; e < 4; e++) acc[mi][nj][e] = 0.f;

        auto load_chunk = [&](int c, int s) {
            const int k0 = c * KC;
            const uint32_t stage = sb + 512 + s * STAGE_BYTES;
            #pragma unroll
            for (int i = 0; i < 16; i++) {
                int seg = i * 128 + tid;
                int op  = seg >> 10;                // 0=A, 1=W
                int r   = (seg & 1023) >> 3;
                int cs  = seg & 7;
                uint32_t dst = stage + op * TILE_B + (uint32_t)(r * PITCHB + cs * 16);
                const __half* src = (op ? Wbase : Abase) + (size_t)r * 1024 + k0 + cs * 8;
                cp_async_16(dst, src);
            }
        };

        load_chunk(0, 0); CP_COMMIT();
        load_chunk(1, 1); CP_COMMIT();

        for (int c = 0; c < NCHUNK; c++) {
            const int s = c % NSTAGE;
            CP_WAIT1();
            __syncthreads();                // sole barrier per chunk
            int cn = c + 2;
            if (cn < NCHUNK) load_chunk(cn, cn % NSTAGE);
            CP_COMMIT();

            const uint32_t sA = sb + 512 + s * STAGE_BYTES;
            const uint32_t sW = sA + TILE_B;
            #pragma unroll
            for (int kk = 0; kk < 4; kk++) {
                uint32_t a[4][4];
                #pragma unroll
                for (int mi = 0; mi < 4; mi++) {
                    uint32_t addr = sA + (uint32_t)((m0w + mi * 16 + (lid & 15)) * PITCHB
                                     + kk * 32 + ((lid >> 4) << 4));
                    ldsm_x4(a[mi][0], a[mi][1], a[mi][2], a[mi][3], addr);
                }
                uint32_t b[8][2];
                #pragma unroll
                for (int ni = 0; ni < 4; ni++) {
                    uint32_t addr = sW + (uint32_t)((n0w + ni * 16 + (lid & 7)
                                     + ((lid >> 4) & 1) * 8) * PITCHB
                                     + kk * 32 + (((lid >> 3) & 1) << 4));
                    uint32_t r0, r1, r2, r3;
                    ldsm_x4(r0, r1, r2, r3, addr);
                    b[2 * ni][0] = r0; b[2 * ni][1] = r1;
                    b[2 * ni + 1][0] = r2; b[2 * ni + 1][1] = r3;
                }
                #pragma unroll
                for (int mi = 0; mi < 4; mi++)
                    #pragma unroll
                    for (int nj = 0; nj < 8; nj++)
                        mma16816(acc[mi][nj], a[mi], b[nj]);
            }
        }
        CP_WAIT0();
    }
};

// ---------------------------------------------------------------------------
// Fused QKV projection GEMM over pre-compacted inputs (pure fp16).
// z=0: Q dense -> Qh. z=1: K -> Kh. z=2: V -> Vh (tiles past cnt exit;
// boundary-tile rows >= cnt store zeros).
// ---------------------------------------------------------------------------
__global__ void __launch_bounds__(128, 2)
gemm_qkv(const __half* __restrict__ A3, const __half* __restrict__ Wh,
         const float* __restrict__ bq, const float* __restrict__ bk,
         const float* __restrict__ bv, const int* __restrict__ cnt_,
         __half* __restrict__ Qh, __half* __restrict__ Kh, __half* __restrict__ Vh)
{
    extern __shared__ char smem[];
    const uint32_t sb = smem_u32(smem);
    const int tid = threadIdx.x, wid = tid >> 5, lid = tid & 31;
    const int z = blockIdx.z;
    const int m0 = blockIdx.y * 128, n0 = blockIdx.x * 128;

    int cntb = SS;                    // dense for Q
    if (z > 0) {                      // compacted K/V: skip row tiles past cnt
        cntb = cnt_[m0 >> 11];
        if ((m0 & 2047) >= cntb) return;
    }

    const float* bias = (z == 0) ? bq : (z == 1) ? bk : bv;
    float* bias_s = (float*)smem;
    if (tid < 128) bias_s[tid] = bias[n0 + tid];

    __half* H = (z == 0) ? Qh : (z == 1) ? Kh : Vh;

    GemmCore core;
    core.run(sb, tid, wid, lid,
             A3 + (size_t)z * MROWS * KW + (size_t)m0 * KW,
             Wh + (size_t)z * DF * 1024 + (size_t)n0 * 1024);

    const int g = lid >> 2, t = lid & 3;
    #pragma unroll
    for (int mi = 0; mi < 4; mi++) {
        #pragma unroll
        for (int nj = 0; nj < 8; nj++) {
            int colrel = core.n0w + nj * 8 + 2 * t;
            int col = n0 + colrel;
            int hh = col >> 6, dh = col & 63;
            float c0 = core.acc[mi][nj][0] + bias_s[colrel];
            float c1 = core.acc[mi][nj][1] + bias_s[colrel + 1];
            float c2 = core.acc[mi][nj][2] + bias_s[colrel];
            float c3 = core.acc[mi][nj][3] + bias_s[colrel + 1];
            #pragma unroll
            for (int rr = 0; rr < 2; rr++) {
                int row = m0 + core.m0w + mi * 16 + g + rr * 8;
                int bb_ = row >> 11, sidx = row & 2047;
                size_t dst = ((size_t)(bb_ * NH + hh) * SS + sidx) * DH + dh;
                float x = rr ? c2 : c0, y = rr ? c3 : c1;
                uint32_t hp = (sidx < cntb) ? pack_rn(x, y) : 0u;
                *reinterpret_cast<uint32_t*>(H + dst) = hp;
            }
        }
    }
}

// ---------------------------------------------------------------------------
// Output projection GEMM: fp32 out
// ---------------------------------------------------------------------------
__global__ void __launch_bounds__(128, 2)
gemm_out(const __half* __restrict__ A3, const __half* __restrict__ Wh,
         const float* __restrict__ bias, float* __restrict__ C)
{
    extern __shared__ char smem[];
    const uint32_t sb = smem_u32(smem);
    const int tid = threadIdx.x, wid = tid >> 5, lid = tid & 31;
    const int m0 = blockIdx.y * 128, n0 = blockIdx.x * 128;

    float* bias_s = (float*)smem;
    if (tid < 128) bias_s[tid] = bias[n0 + tid];

    GemmCore core;
    core.run(sb, tid, wid, lid, A3 + (size_t)m0 * KW, Wh + (size_t)n0 * 1024);

    const int g = lid >> 2, t = lid & 3;
    #pragma unroll
    for (int mi = 0; mi < 4; mi++) {
        #pragma unroll
        for (int nj = 0; nj < 8; nj++) {
            int colrel = core.n0w + nj * 8 + 2 * t;
            int col = n0 + colrel;
            int row0 = m0 + core.m0w + mi * 16 + g;
            float2 v0 = {core.acc[mi][nj][0] + bias_s[colrel],
                         core.acc[mi][nj][1] + bias_s[colrel + 1]};
            float2 v1 = {core.acc[mi][nj][2] + bias_s[colrel],
                         core.acc[mi][nj][3] + bias_s[colrel + 1]};
            *reinterpret_cast<float2*>(C + (size_t)row0 * DF + col) = v0;
            *reinterpret_cast<float2*>(C + (size_t)(row0 + 8) * DF + col) = v1;
        }
    }
}

// ---------------------------------------------------------------------------
// FlashAttention-2 on mma.sync over COMPACTED keys (128 q/CTA, 8 warps x 16
// q-rows). Pure fp16: S = Qh.Kh ; O = Ph.Vh.
// ---------------------------------------------------------------------------
__global__ void __launch_bounds__(256, 1)
attn_mma(const __half* __restrict__ Qh_, const __half* __restrict__ Kh_,
         const __half* __restrict__ Vh_, const int* __restrict__ cnt_,
         __half* __restrict__ A3out)
{
    extern __shared__ char smem[];
    const uint32_t sb = smem_u32(smem);
    const int tid = threadIdx.x, wid = tid >> 5, lid = tid & 31;
    const int g = lid >> 2, t4 = lid & 3;
    const int b = blockIdx.z, h = blockIdx.y;
    const int bh = b * NH + h;
    const int q0 = blockIdx.x * 128;
    const int m0w = wid * 16;
    const float SC = 0.03125f;

    const int cnt = cnt_[b];
    const int nt = (cnt + 63) >> 6;

    // ---- stage Q through smem into register a-frags ----
    {
        const size_t qbase = ((size_t)bh * SS + q0);
        #pragma unroll
        for (int i = 0; i < 4; i++) {
            int seg = i * 256 + tid;
            int row = seg >> 3, cs = seg & 7;
            cp_async_16(sb + (uint32_t)(row * PITCHB + cs * 16),
                        Qh_ + (qbase + row) * DH + cs * 8);
        }
    }
    CP_COMMIT(); CP_WAIT0(); __syncthreads();

    uint32_t qh[4][4];
    #pragma unroll
    for (int kk = 0; kk < 4; kk++) {
        uint32_t a = sb + (uint32_t)((m0w + (lid & 15)) * PITCHB + kk * 32 + ((lid >> 4) << 4));
        ldsm_x4(qh[kk][0], qh[kk][1], qh[kk][2], qh[kk][3], a);
    }
    __syncthreads();

    auto load_tile = [&](int ti, int st) {
        const uint32_t stage = sb + st * ASTRIDE;
        const size_t kbase = ((size_t)bh * SS + ti * 64);
        #pragma unroll
        for (int i = 0; i < 2; i++) {
            int seg = i * 256 + tid;
            int row = seg >> 3, cs = seg & 7;
            size_t src = (kbase + row) * DH + cs * 8;
            uint32_t d = stage + (uint32_t)(row * PITCHB + cs * 16);
            cp_async_16(d,         Kh_ + src);
            cp_async_16(d + ATILE, Vh_ + src);
        }
    };

    float m0 = -1e30f, m1 = -1e30f, l0 = 0.f, l1 = 0.f;
    float o[8][4];
    #pragma unroll
    for (int nj = 0; nj < 8; nj++)
        #pragma unroll
        for (int e = 0; e < 4; e++) o[nj][e] = 0.f;

    if (0 < nt) load_tile(0, 0);
    CP_COMMIT();
    if (1 < nt) load_tile(1, 1);
    CP_COMMIT();

    for (int ti = 0; ti < nt; ti++) {
        const int st = ti % 3;
        CP_WAIT1();
        __syncthreads();                        // sole barrier per tile
        if (ti + 2 < nt) load_tile(ti + 2, (ti + 2) % 3);
        CP_COMMIT();

        const uint32_t sK = sb + st * ASTRIDE;
        const uint32_t sV = sK + ATILE;

        // ---- S = Qh Kh^T ----
        float s[8][4];
        #pragma unroll
        for (int nj = 0; nj < 8; nj++)
            #pragma unroll
            for (int e = 0; e < 4; e++) s[nj][e] = 0.f;

        #pragma unroll
        for (int kk = 0; kk < 4; kk++) {
            uint32_t kb[4][4];
            #pragma unroll
            for (int ni = 0; ni < 4; ni++) {
                uint32_t a = sK + (uint32_t)((ni * 16 + (lid & 7) + ((lid >> 4) & 1) * 8) * PITCHB
                             + kk * 32 + (((lid >> 3) & 1) << 4));
                ldsm_x4(kb[ni][0], kb[ni][1], kb[ni][2], kb[ni][3], a);
            }
            #pragma unroll
            for (int nj = 0; nj < 8; nj++) mma16816(s[nj], qh[kk], &kb[nj >> 1][(nj & 1) * 2]);
        }

        // ---- scale + tail mask + online softmax ----
        const int kbase_idx = ti * 64;
        float tmax0 = -1e30f, tmax1 = -1e30f;
        #pragma unroll
        for (int nj = 0; nj < 8; nj++) {
            int k0i = kbase_idx + nj * 8 + 2 * t4;
            bool v0 = k0i < cnt, v1 = (k0i + 1) < cnt;
            float s0 = v0 ? s[nj][0] * SC : -1e9f;
            float s1 = v1 ? s[nj][1] * SC : -1e9f;
            float s2 = v0 ? s[nj][2] * SC : -1e9f;
            float s3 = v1 ? s[nj][3] * SC : -1e9f;
            s[nj][0] = s0; s[nj][1] = s1; s[nj][2] = s2; s[nj][3] = s3;
            tmax0 = fmaxf(tmax0, fmaxf(s0, s1));
            tmax1 = fmaxf(tmax1, fmaxf(s2, s3));
        }
        tmax0 = fmaxf(tmax0, __shfl_xor_sync(0xffffffffu, tmax0, 1));
        tmax0 = fmaxf(tmax0, __shfl_xor_sync(0xffffffffu, tmax0, 2));
        tmax1 = fmaxf(tmax1, __shfl_xor_sync(0xffffffffu, tmax1, 1));
        tmax1 = fmaxf(tmax1, __shfl_xor_sync(0xffffffffu, tmax1, 2));

        float mn0 = fmaxf(m0, tmax0), mn1 = fmaxf(m1, tmax1);
        float sc0 = __expf(m0 - mn0), sc1 = __expf(m1 - mn1);
        m0 = mn0; m1 = mn1;
        l0 *= sc0; l1 *= sc1;
        #pragma unroll
        for (int nj = 0; nj < 8; nj++) {
            o[nj][0] *= sc0; o[nj][1] *= sc0;
            o[nj][2] *= sc1; o[nj][3] *= sc1;
        }
        #pragma unroll
        for (int nj = 0; nj < 8; nj++) {
            float p0 = __expf(s[nj][0] - m0);
            float p1 = __expf(s[nj][1] - m0);
            float p2 = __expf(s[nj][2] - m1);
            float p3 = __expf(s[nj][3] - m1);
            s[nj][0] = p0; s[nj][1] = p1; s[nj][2] = p2; s[nj][3] = p3;
            l0 += p0 + p1; l1 += p2 + p3;
        }

        // ---- O += Ph Vh ----
        #pragma unroll
        for (int kk = 0; kk < 4; kk++) {
            uint32_t ah[4];
            ah[0] = pack_rn(s[2 * kk][0],     s[2 * kk][1]);
            ah[1] = pack_rn(s[2 * kk][2],     s[2 * kk][3]);
            ah[2] = pack_rn(s[2 * kk + 1][0], s[2 * kk + 1][1]);
            ah[3] = pack_rn(s[2 * kk + 1][2], s[2 * kk + 1][3]);

            uint32_t vb[4][4];
            #pragma unroll
            for (int njp = 0; njp < 4; njp++) {
                uint32_t a = sV + (uint32_t)((16 * kk + (lid & 7) + ((lid >> 3) & 1) * 8) * PITCHB
                             + (16 * njp + ((lid >> 4) & 1) * 8) * 2);
                ldsm_x4_t(vb[njp][0], vb[njp][1], vb[njp][2], vb[njp][3], a);
            }
            #pragma unroll
            for (int nj = 0; nj < 8; nj++) mma16816(o[nj], ah, &vb[nj >> 1][(nj & 1) * 2]);
        }
    }
    CP_WAIT0();

    // ---- finalize + write fp16 straight into A3 ----
    l0 += __shfl_xor_sync(0xffffffffu, l0, 1);
    l0 += __shfl_xor_sync(0xffffffffu, l0, 2);
    l1 += __shfl_xor_sync(0xffffffffu, l1, 1);
    l1 += __shfl_xor_sync(0xffffffffu, l1, 2);
    float inv0 = 1.f / l0, inv1 = 1.f / l1;

    const int srow = q0 + m0w + g;
    size_t r0 = (size_t)(b * SS + srow) * KW;
    size_t r1 = r0 + (size_t)8 * KW;
    const int colbase = h * DH;

    #pragma unroll
    for (int nj = 0; nj < 8; nj++) {
        int c = colbase + nj * 8 + 2 * t4;
        *reinterpret_cast<uint32_t*>(A3out + r0 + c) =
            pack_rn(o[nj][0] * inv0, o[nj][1] * inv0);
        *reinterpret_cast<uint32_t*>(A3out + r1 + c) =
            pack_rn(o[nj][2] * inv1, o[nj][3] * inv1);
    }
}

// ---------------------------------------------------------------------------
// launch
// ---------------------------------------------------------------------------
extern "C" void kernel_launch(void* const* d_in, const int* in_sizes, int n_in,
                              void* d_out, int out_size)
{
    const float* Q    = (const float*)d_in[0];
    const float* K    = (const float*)d_in[1];
    const float* V    = (const float*)d_in[2];
    const int*   mask = (const int*)  d_in[3];
    const float* Wq   = (const float*)d_in[4];
    const float* bq   = (const float*)d_in[5];
    const float* Wk   = (const float*)d_in[6];
    const float* bk   = (const float*)d_in[7];
    const float* Wv   = (const float*)d_in[8];
    const float* bv   = (const float*)d_in[9];
    const float* Wo   = (const float*)d_in[10];
    const float* bo   = (const float*)d_in[11];
    float* out = (float*)d_out;

    __half *A3, *Wh, *Qh, *Kh, *Vh;
    int *pos, *cnt;
    cudaGetSymbolAddress((void**)&A3, g_A3v3);
    cudaGetSymbolAddress((void**)&Wh, g_Whv4);
    cudaGetSymbolAddress((void**)&Qh, g_Qh);
    cudaGetSymbolAddress((void**)&Kh, g_Kh);
    cudaGetSymbolAddress((void**)&Vh, g_Vh);
    cudaGetSymbolAddress((void**)&pos, g_pos);
    cudaGetSymbolAddress((void**)&cnt, g_cnt);

    cudaFuncSetAttribute(gemm_qkv, cudaFuncAttributeMaxDynamicSharedMemorySize, GEMM_SMEM);
    cudaFuncSetAttribute(gemm_out, cudaFuncAttributeMaxDynamicSharedMemorySize, GEMM_SMEM);
    cudaFuncSetAttribute(attn_mma, cudaFuncAttributeMaxDynamicSharedMemorySize, ATTN_SMEM);

    mask_scan<<<BB, 256>>>(mask, pos, cnt);
    conv_w<<<dim3(DF * DF / 1024, 4), 256>>>(Wq, Wk, Wv, Wo, Wh);
    conv_in<<<dim3(MROWS * DF / 1024, 3), 256>>>(Q, K, V, mask, pos, A3);

    gemm_qkv<<<dim3(DF / 128, MROWS / 128, 3), 128, GEMM_SMEM>>>(
        A3, Wh, bq, bk, bv, cnt, Qh, Kh, Vh);

    attn_mma<<<dim3(SS / 128, NH, BB), 256, ATTN_SMEM>>>(Qh, Kh, Vh, cnt, A3);

    gemm_out<<<dim3(DF / 128, MROWS / 128), 128, GEMM_SMEM>>>(
        A3, Wh + (size_t)3 * DF * 1024, bo, out);
}

// round 17
// speedup vs baseline: 3.5031x; 1.0532x over previous
#include <cuda_runtime.h>
#include <cuda_fp16.h>
#include <cstdint>

#define DF 1024
#define NH 16
#define DH 64
#define BB 2
#define SS 2048
#define MROWS (BB*SS)

#define KW   1024              // A width (fp16, hi only)
#define KC   64                // fp16 K per chunk
#define NCHUNK 16              // 1024 / KC
#define NSTAGE 3
#define PITCH  72
#define PITCHB 144
#define TILE_B (128 * PITCHB)               // 18432
#define STAGE_BYTES (2 * TILE_B)            // A + W = 36864
#define GEMM_SMEM (512 + NSTAGE * STAGE_BYTES)  // 111104

// attention smem: per stage Kh + Vh tiles
#define ATILE   9216                       // one 64x64 fp16 tile, pitch 144
#define ASTRIDE (2 * ATILE + 256)          // 18688
#define ATTN_SMEM (3 * ASTRIDE)            // 56064 (covers 18432 Q staging)

// ---------------------------------------------------------------------------
// Scratch
// ---------------------------------------------------------------------------
__device__ __half g_A3v3[3][(size_t)MROWS * KW];   // activations, fp16
__device__ __half g_Whv4[4][(size_t)DF * 1024];    // weights, fp16
__device__ __half g_Qh[(size_t)BB * NH * SS * DH];
__device__ __half g_Kh[(size_t)BB * NH * SS * DH];
__device__ __half g_Vh[(size_t)BB * NH * SS * DH];
__device__ int g_pos[BB * SS];
__device__ int g_cnt[BB];

// ---------------------------------------------------------------------------
// helpers
// ---------------------------------------------------------------------------
__device__ __forceinline__ uint32_t smem_u32(const void* p) {
    uint32_t a;
    asm("{ .reg .u64 t; cvta.to.shared.u64 t, %1; cvt.u32.u64 %0, t; }"
        : "=r"(a) : "l"(p));
    return a;
}

__device__ __forceinline__ void cp_async_16(uint32_t dst, const void* src) {
    asm volatile("cp.async.cg.shared.global [%0], [%1], 16;" :: "r"(dst), "l"(src) : "memory");
}
#define CP_COMMIT() asm volatile("cp.async.commit_group;" ::: "memory")
#define CP_WAIT1()  asm volatile("cp.async.wait_group 1;" ::: "memory")
#define CP_WAIT0()  asm volatile("cp.async.wait_group 0;" ::: "memory")

__device__ __forceinline__ void ldsm_x4(uint32_t& r0, uint32_t& r1, uint32_t& r2,
                                        uint32_t& r3, uint32_t addr) {
    asm volatile("ldmatrix.sync.aligned.m8n8.x4.shared.b16 {%0,%1,%2,%3}, [%4];"
                 : "=r"(r0), "=r"(r1), "=r"(r2), "=r"(r3) : "r"(addr));
}
__device__ __forceinline__ void ldsm_x4_t(uint32_t& r0, uint32_t& r1, uint32_t& r2,
                                          uint32_t& r3, uint32_t addr) {
    asm volatile("ldmatrix.sync.aligned.m8n8.x4.trans.shared.b16 {%0,%1,%2,%3}, [%4];"
                 : "=r"(r0), "=r"(r1), "=r"(r2), "=r"(r3) : "r"(addr));
}

__device__ __forceinline__ void mma16816(float* d, const uint32_t* a, const uint32_t* b) {
    asm volatile(
        "mma.sync.aligned.m16n8k16.row.col.f32.f16.f16.f32 "
        "{%0,%1,%2,%3}, {%4,%5,%6,%7}, {%8,%9}, {%0,%1,%2,%3};"
        : "+f"(d[0]), "+f"(d[1]), "+f"(d[2]), "+f"(d[3])
        : "r"(a[0]), "r"(a[1]), "r"(a[2]), "r"(a[3]), "r"(b[0]), "r"(b[1]));
}

__device__ __forceinline__ uint32_t pack_rn(float x, float y) {
    __half2 h = __floats2half2_rn(x, y);
    uint32_t r; memcpy(&r, &h, 4); return r;
}

// ---------------------------------------------------------------------------
// mask prefix scan: pos[b][s] = #valid keys before s ; cnt[b] = total valid
// ---------------------------------------------------------------------------
__global__ __launch_bounds__(256) void mask_scan(const int* __restrict__ mask,
                                                 int* __restrict__ pos, int* __restrict__ cnt)
{
    __shared__ int partial[256];
    const int b = blockIdx.x, tid = threadIdx.x;
    const int base = b * SS + tid * 8;
    int v[8], s = 0;
    #pragma unroll
    for (int i = 0; i < 8; i++) { v[i] = (mask[base + i] != 0); s += v[i]; }
    partial[tid] = s;
    __syncthreads();
    for (int off = 1; off < 256; off <<= 1) {
        int t = (tid >= off) ? partial[tid - off] : 0;
        __syncthreads();
        partial[tid] += t;
        __syncthreads();
    }
    int ex = (tid == 0) ? 0 : partial[tid - 1];
    #pragma unroll
    for (int i = 0; i < 8; i++) { pos[base + i] = ex; ex += v[i]; }
    if (tid == 255) cnt[b] = partial[255];
}

// ---------------------------------------------------------------------------
// fp16 conversions. conv_in: z=0 Q dense; z=1 K, z=2 V with row compaction.
// ---------------------------------------------------------------------------
__global__ __launch_bounds__(256) void conv_in(const float* __restrict__ Q,
                                               const float* __restrict__ K,
                                               const float* __restrict__ V,
                                               const int* __restrict__ mask,
                                               const int* __restrict__ pos,
                                               __half* __restrict__ A3)
{
    const int z = blockIdx.y;
    const float* X = z == 0 ? Q : (z == 1 ? K : V);
    __half* Y = A3 + (size_t)z * MROWS * KW;
    int idx = (blockIdx.x * 256 + threadIdx.x) * 4;
    int r = idx >> 10, k = idx & 1023;
    int rr = r;
    if (z > 0) {
        int bb_ = r >> 11, sidx = r & 2047;
        if (mask[bb_ * SS + sidx] == 0) return;       // masked key row: skip
        rr = bb_ * SS + pos[bb_ * SS + sidx];         // compacted destination
    }
    float4 x = *reinterpret_cast<const float4*>(X + idx);
    float v[4] = {x.x, x.y, x.z, x.w};
    __half hi[4];
    #pragma unroll
    for (int i = 0; i < 4; i++) hi[i] = __float2half_rn(v[i]);
    uint64_t hip;
    memcpy(&hip, hi, 8);
    *reinterpret_cast<uint64_t*>(Y + (size_t)rr * KW + k) = hip;
}

__global__ __launch_bounds__(256) void conv_w(const float* __restrict__ Wq,
                                              const float* __restrict__ Wk,
                                              const float* __restrict__ Wv,
                                              const float* __restrict__ Wo,
                                              __half* __restrict__ Wh)
{
    const float* X = blockIdx.y == 0 ? Wq : (blockIdx.y == 1 ? Wk :
                      (blockIdx.y == 2 ? Wv : Wo));
    __half* Y = Wh + (size_t)blockIdx.y * DF * 1024;
    int idx = (blockIdx.x * 256 + threadIdx.x) * 4;
    float4 x = *reinterpret_cast<const float4*>(X + idx);
    float v[4] = {x.x, x.y, x.z, x.w};
    __half hi[4];
    #pragma unroll
    for (int i = 0; i < 4; i++) hi[i] = __float2half_rn(v[i]);
    uint64_t hip;
    memcpy(&hip, hi, 8);
    *reinterpret_cast<uint64_t*>(Y + idx) = hip;
}

// ---------------------------------------------------------------------------
// GEMM mainloop: 128 threads / 4 warps (2M x 2N), warp tile 64x64.
// Pure fp16 1-term, 16 chunks of K=64, 3-stage pipeline, one barrier/chunk.
// ---------------------------------------------------------------------------
struct GemmCore {
    float acc[4][8][4];
    int m0w, n0w;

    __device__ __forceinline__ void run(uint32_t sb, int tid, int wid, int lid,
                                        const __half* Abase,
                                        const __half* Wbase) {
        m0w = (wid & 1) * 64;
        n0w = (wid >> 1) * 64;
        #pragma unroll
        for (int mi = 0; mi < 4; mi++)
            #pragma unroll
            for (int nj = 0; nj < 8; nj++)
                #pragma unroll
                for (int e = 0; e < 4; e++) acc[mi][nj][e] = 0.f;

        auto load_chunk = [&](int c, int s) {
            const int k0 = c * KC;
            const uint32_t stage = sb + 512 + s * STAGE_BYTES;
            #pragma unroll
            for (int i = 0; i < 16; i++) {
                int seg = i * 128 + tid;
                int op  = seg >> 10;                // 0=A, 1=W
                int r   = (seg & 1023) >> 3;
                int cs  = seg & 7;
                uint32_t dst = stage + op * TILE_B + (uint32_t)(r * PITCHB + cs * 16);
                const __half* src = (op ? Wbase : Abase) + (size_t)r * 1024 + k0 + cs * 8;
                cp_async_16(dst, src);
            }
        };

        load_chunk(0, 0); CP_COMMIT();
        load_chunk(1, 1); CP_COMMIT();

        for (int c = 0; c < NCHUNK; c++) {
            const int s = c % NSTAGE;
            CP_WAIT1();
            __syncthreads();                // sole barrier per chunk
            int cn = c + 2;
            if (cn < NCHUNK) load_chunk(cn, cn % NSTAGE);
            CP_COMMIT();

            const uint32_t sA = sb + 512 + s * STAGE_BYTES;
            const uint32_t sW = sA + TILE_B;
            #pragma unroll
            for (int kk = 0; kk < 4; kk++) {
                uint32_t a[4][4];
                #pragma unroll
                for (int mi = 0; mi < 4; mi++) {
                    uint32_t addr = sA + (uint32_t)((m0w + mi * 16 + (lid & 15)) * PITCHB
                                     + kk * 32 + ((lid >> 4) << 4));
                    ldsm_x4(a[mi][0], a[mi][1], a[mi][2], a[mi][3], addr);
                }
                uint32_t b[8][2];
                #pragma unroll
                for (int ni = 0; ni < 4; ni++) {
                    uint32_t addr = sW + (uint32_t)((n0w + ni * 16 + (lid & 7)
                                     + ((lid >> 4) & 1) * 8) * PITCHB
                                     + kk * 32 + (((lid >> 3) & 1) << 4));
                    uint32_t r0, r1, r2, r3;
                    ldsm_x4(r0, r1, r2, r3, addr);
                    b[2 * ni][0] = r0; b[2 * ni][1] = r1;
                    b[2 * ni + 1][0] = r2; b[2 * ni + 1][1] = r3;
                }
                #pragma unroll
                for (int mi = 0; mi < 4; mi++)
                    #pragma unroll
                    for (int nj = 0; nj < 8; nj++)
                        mma16816(acc[mi][nj], a[mi], b[nj]);
            }
        }
        CP_WAIT0();
    }
};

// ---------------------------------------------------------------------------
// Fused QKV projection GEMM over pre-compacted inputs (pure fp16).
// z=0: Q dense -> Qh. z=1: K -> Kh. z=2: V -> Vh (tiles past cnt exit;
// boundary-tile rows >= cnt store zeros).
// ---------------------------------------------------------------------------
__global__ void __launch_bounds__(128, 2)
gemm_qkv(const __half* __restrict__ A3, const __half* __restrict__ Wh,
         const float* __restrict__ bq, const float* __restrict__ bk,
         const float* __restrict__ bv, const int* __restrict__ cnt_,
         __half* __restrict__ Qh, __half* __restrict__ Kh, __half* __restrict__ Vh)
{
    extern __shared__ char smem[];
    const uint32_t sb = smem_u32(smem);
    const int tid = threadIdx.x, wid = tid >> 5, lid = tid & 31;
    const int z = blockIdx.z;
    const int m0 = blockIdx.y * 128, n0 = blockIdx.x * 128;

    int cntb = SS;                    // dense for Q
    if (z > 0) {                      // compacted K/V: skip row tiles past cnt
        cntb = cnt_[m0 >> 11];
        if ((m0 & 2047) >= cntb) return;
    }

    const float* bias = (z == 0) ? bq : (z == 1) ? bk : bv;
    float* bias_s = (float*)smem;
    if (tid < 128) bias_s[tid] = bias[n0 + tid];

    __half* H = (z == 0) ? Qh : (z == 1) ? Kh : Vh;

    GemmCore core;
    core.run(sb, tid, wid, lid,
             A3 + (size_t)z * MROWS * KW + (size_t)m0 * KW,
             Wh + (size_t)z * DF * 1024 + (size_t)n0 * 1024);

    const int g = lid >> 2, t = lid & 3;
    #pragma unroll
    for (int mi = 0; mi < 4; mi++) {
        #pragma unroll
        for (int nj = 0; nj < 8; nj++) {
            int colrel = core.n0w + nj * 8 + 2 * t;
            int col = n0 + colrel;
            int hh = col >> 6, dh = col & 63;
            float c0 = core.acc[mi][nj][0] + bias_s[colrel];
            float c1 = core.acc[mi][nj][1] + bias_s[colrel + 1];
            float c2 = core.acc[mi][nj][2] + bias_s[colrel];
            float c3 = core.acc[mi][nj][3] + bias_s[colrel + 1];
            #pragma unroll
            for (int rr = 0; rr < 2; rr++) {
                int row = m0 + core.m0w + mi * 16 + g + rr * 8;
                int bb_ = row >> 11, sidx = row & 2047;
                size_t dst = ((size_t)(bb_ * NH + hh) * SS + sidx) * DH + dh;
                float x = rr ? c2 : c0, y = rr ? c3 : c1;
                uint32_t hp = (sidx < cntb) ? pack_rn(x, y) : 0u;
                *reinterpret_cast<uint32_t*>(H + dst) = hp;
            }
        }
    }
}

// ---------------------------------------------------------------------------
// Output projection GEMM: fp32 out
// ---------------------------------------------------------------------------
__global__ void __launch_bounds__(128, 2)
gemm_out(const __half* __restrict__ A3, const __half* __restrict__ Wh,
         const float* __restrict__ bias, float* __restrict__ C)
{
    extern __shared__ char smem[];
    const uint32_t sb = smem_u32(smem);
    const int tid = threadIdx.x, wid = tid >> 5, lid = tid & 31;
    const int m0 = blockIdx.y * 128, n0 = blockIdx.x * 128;

    float* bias_s = (float*)smem;
    if (tid < 128) bias_s[tid] = bias[n0 + tid];

    GemmCore core;
    core.run(sb, tid, wid, lid, A3 + (size_t)m0 * KW, Wh + (size_t)n0 * 1024);

    const int g = lid >> 2, t = lid & 3;
    #pragma unroll
    for (int mi = 0; mi < 4; mi++) {
        #pragma unroll
        for (int nj = 0; nj < 8; nj++) {
            int colrel = core.n0w + nj * 8 + 2 * t;
            int col = n0 + colrel;
            int row0 = m0 + core.m0w + mi * 16 + g;
            float2 v0 = {core.acc[mi][nj][0] + bias_s[colrel],
                         core.acc[mi][nj][1] + bias_s[colrel + 1]};
            float2 v1 = {core.acc[mi][nj][2] + bias_s[colrel],
                         core.acc[mi][nj][3] + bias_s[colrel + 1]};
            *reinterpret_cast<float2*>(C + (size_t)row0 * DF + col) = v0;
            *reinterpret_cast<float2*>(C + (size_t)(row0 + 8) * DF + col) = v1;
        }
    }
}

// ---------------------------------------------------------------------------
// FlashAttention-2 on mma.sync over COMPACTED keys (128 q/CTA, 8 warps x 16
// q-rows). Pure fp16: S = Qh.Kh ; O = Ph.Vh.  2 CTAs/SM (occupancy round).
// ---------------------------------------------------------------------------
__global__ void __launch_bounds__(256, 2)
attn_mma(const __half* __restrict__ Qh_, const __half* __restrict__ Kh_,
         const __half* __restrict__ Vh_, const int* __restrict__ cnt_,
         __half* __restrict__ A3out)
{
    extern __shared__ char smem[];
    const uint32_t sb = smem_u32(smem);
    const int tid = threadIdx.x, wid = tid >> 5, lid = tid & 31;
    const int g = lid >> 2, t4 = lid & 3;
    const int b = blockIdx.z, h = blockIdx.y;
    const int bh = b * NH + h;
    const int q0 = blockIdx.x * 128;
    const int m0w = wid * 16;
    const float SC = 0.03125f;

    const int cnt = cnt_[b];
    const int nt = (cnt + 63) >> 6;

    // ---- stage Q through smem into register a-frags ----
    {
        const size_t qbase = ((size_t)bh * SS + q0);
        #pragma unroll
        for (int i = 0; i < 4; i++) {
            int seg = i * 256 + tid;
            int row = seg >> 3, cs = seg & 7;
            cp_async_16(sb + (uint32_t)(row * PITCHB + cs * 16),
                        Qh_ + (qbase + row) * DH + cs * 8);
        }
    }
    CP_COMMIT(); CP_WAIT0(); __syncthreads();

    uint32_t qh[4][4];
    #pragma unroll
    for (int kk = 0; kk < 4; kk++) {
        uint32_t a = sb + (uint32_t)((m0w + (lid & 15)) * PITCHB + kk * 32 + ((lid >> 4) << 4));
        ldsm_x4(qh[kk][0], qh[kk][1], qh[kk][2], qh[kk][3], a);
    }
    __syncthreads();

    auto load_tile = [&](int ti, int st) {
        const uint32_t stage = sb + st * ASTRIDE;
        const size_t kbase = ((size_t)bh * SS + ti * 64);
        #pragma unroll
        for (int i = 0; i < 2; i++) {
            int seg = i * 256 + tid;
            int row = seg >> 3, cs = seg & 7;
            size_t src = (kbase + row) * DH + cs * 8;
            uint32_t d = stage + (uint32_t)(row * PITCHB + cs * 16);
            cp_async_16(d,         Kh_ + src);
            cp_async_16(d + ATILE, Vh_ + src);
        }
    };

    float m0 = -1e30f, m1 = -1e30f, l0 = 0.f, l1 = 0.f;
    float o[8][4];
    #pragma unroll
    for (int nj = 0; nj < 8; nj++)
        #pragma unroll
        for (int e = 0; e < 4; e++) o[nj][e] = 0.f;

    if (0 < nt) load_tile(0, 0);
    CP_COMMIT();
    if (1 < nt) load_tile(1, 1);
    CP_COMMIT();

    for (int ti = 0; ti < nt; ti++) {
        const int st = ti % 3;
        CP_WAIT1();
        __syncthreads();                        // sole barrier per tile
        if (ti + 2 < nt) load_tile(ti + 2, (ti + 2) % 3);
        CP_COMMIT();

        const uint32_t sK = sb + st * ASTRIDE;
        const uint32_t sV = sK + ATILE;

        // ---- S = Qh Kh^T ----
        float s[8][4];
        #pragma unroll
        for (int nj = 0; nj < 8; nj++)
            #pragma unroll
            for (int e = 0; e < 4; e++) s[nj][e] = 0.f;

        #pragma unroll
        for (int kk = 0; kk < 4; kk++) {
            uint32_t kb[4][4];
            #pragma unroll
            for (int ni = 0; ni < 4; ni++) {
                uint32_t a = sK + (uint32_t)((ni * 16 + (lid & 7) + ((lid >> 4) & 1) * 8) * PITCHB
                             + kk * 32 + (((lid >> 3) & 1) << 4));
                ldsm_x4(kb[ni][0], kb[ni][1], kb[ni][2], kb[ni][3], a);
            }
            #pragma unroll
            for (int nj = 0; nj < 8; nj++) mma16816(s[nj], qh[kk], &kb[nj >> 1][(nj & 1) * 2]);
        }

        // ---- scale + tail mask + online softmax ----
        const int kbase_idx = ti * 64;
        float tmax0 = -1e30f, tmax1 = -1e30f;
        #pragma unroll
        for (int nj = 0; nj < 8; nj++) {
            int k0i = kbase_idx + nj * 8 + 2 * t4;
            bool v0 = k0i < cnt, v1 = (k0i + 1) < cnt;
            float s0 = v0 ? s[nj][0] * SC : -1e9f;
            float s1 = v1 ? s[nj][1] * SC : -1e9f;
            float s2 = v0 ? s[nj][2] * SC : -1e9f;
            float s3 = v1 ? s[nj][3] * SC : -1e9f;
            s[nj][0] = s0; s[nj][1] = s1; s[nj][2] = s2; s[nj][3] = s3;
            tmax0 = fmaxf(tmax0, fmaxf(s0, s1));
            tmax1 = fmaxf(tmax1, fmaxf(s2, s3));
        }
        tmax0 = fmaxf(tmax0, __shfl_xor_sync(0xffffffffu, tmax0, 1));
        tmax0 = fmaxf(tmax0, __shfl_xor_sync(0xffffffffu, tmax0, 2));
        tmax1 = fmaxf(tmax1, __shfl_xor_sync(0xffffffffu, tmax1, 1));
        tmax1 = fmaxf(tmax1, __shfl_xor_sync(0xffffffffu, tmax1, 2));

        float mn0 = fmaxf(m0, tmax0), mn1 = fmaxf(m1, tmax1);
        float sc0 = __expf(m0 - mn0), sc1 = __expf(m1 - mn1);
        m0 = mn0; m1 = mn1;
        l0 *= sc0; l1 *= sc1;
        #pragma unroll
        for (int nj = 0; nj < 8; nj++) {
            o[nj][0] *= sc0; o[nj][1] *= sc0;
            o[nj][2] *= sc1; o[nj][3] *= sc1;
        }
        #pragma unroll
        for (int nj = 0; nj < 8; nj++) {
            float p0 = __expf(s[nj][0] - m0);
            float p1 = __expf(s[nj][1] - m0);
            float p2 = __expf(s[nj][2] - m1);
            float p3 = __expf(s[nj][3] - m1);
            s[nj][0] = p0; s[nj][1] = p1; s[nj][2] = p2; s[nj][3] = p3;
            l0 += p0 + p1; l1 += p2 + p3;
        }

        // ---- O += Ph Vh ----
        #pragma unroll
        for (int kk = 0; kk < 4; kk++) {
            uint32_t ah[4];
            ah[0] = pack_rn(s[2 * kk][0],     s[2 * kk][1]);
            ah[1] = pack_rn(s[2 * kk][2],     s[2 * kk][3]);
            ah[2] = pack_rn(s[2 * kk + 1][0], s[2 * kk + 1][1]);
            ah[3] = pack_rn(s[2 * kk + 1][2], s[2 * kk + 1][3]);

            uint32_t vb[4][4];
            #pragma unroll
            for (int njp = 0; njp < 4; njp++) {
                uint32_t a = sV + (uint32_t)((16 * kk + (lid & 7) + ((lid >> 3) & 1) * 8) * PITCHB
                             + (16 * njp + ((lid >> 4) & 1) * 8) * 2);
                ldsm_x4_t(vb[njp][0], vb[njp][1], vb[njp][2], vb[njp][3], a);
            }
            #pragma unroll
            for (int nj = 0; nj < 8; nj++) mma16816(o[nj], ah, &vb[nj >> 1][(nj & 1) * 2]);
        }
    }
    CP_WAIT0();

    // ---- finalize + write fp16 straight into A3 ----
    l0 += __shfl_xor_sync(0xffffffffu, l0, 1);
    l0 += __shfl_xor_sync(0xffffffffu, l0, 2);
    l1 += __shfl_xor_sync(0xffffffffu, l1, 1);
    l1 += __shfl_xor_sync(0xffffffffu, l1, 2);
    float inv0 = 1.f / l0, inv1 = 1.f / l1;

    const int srow = q0 + m0w + g;
    size_t r0 = (size_t)(b * SS + srow) * KW;
    size_t r1 = r0 + (size_t)8 * KW;
    const int colbase = h * DH;

    #pragma unroll
    for (int nj = 0; nj < 8; nj++) {
        int c = colbase + nj * 8 + 2 * t4;
        *reinterpret_cast<uint32_t*>(A3out + r0 + c) =
            pack_rn(o[nj][0] * inv0, o[nj][1] * inv0);
        *reinterpret_cast<uint32_t*>(A3out + r1 + c) =
            pack_rn(o[nj][2] * inv1, o[nj][3] * inv1);
    }
}

// ---------------------------------------------------------------------------
// launch
// ---------------------------------------------------------------------------
extern "C" void kernel_launch(void* const* d_in, const int* in_sizes, int n_in,
                              void* d_out, int out_size)
{
    const float* Q    = (const float*)d_in[0];
    const float* K    = (const float*)d_in[1];
    const float* V    = (const float*)d_in[2];
    const int*   mask = (const int*)  d_in[3];
    const float* Wq   = (const float*)d_in[4];
    const float* bq   = (const float*)d_in[5];
    const float* Wk   = (const float*)d_in[6];
    const float* bk   = (const float*)d_in[7];
    const float* Wv   = (const float*)d_in[8];
    const float* bv   = (const float*)d_in[9];
    const float* Wo   = (const float*)d_in[10];
    const float* bo   = (const float*)d_in[11];
    float* out = (float*)d_out;

    __half *A3, *Wh, *Qh, *Kh, *Vh;
    int *pos, *cnt;
    cudaGetSymbolAddress((void**)&A3, g_A3v3);
    cudaGetSymbolAddress((void**)&Wh, g_Whv4);
    cudaGetSymbolAddress((void**)&Qh, g_Qh);
    cudaGetSymbolAddress((void**)&Kh, g_Kh);
    cudaGetSymbolAddress((void**)&Vh, g_Vh);
    cudaGetSymbolAddress((void**)&pos, g_pos);
    cudaGetSymbolAddress((void**)&cnt, g_cnt);

    cudaFuncSetAttribute(gemm_qkv, cudaFuncAttributeMaxDynamicSharedMemorySize, GEMM_SMEM);
    cudaFuncSetAttribute(gemm_out, cudaFuncAttributeMaxDynamicSharedMemorySize, GEMM_SMEM);
    cudaFuncSetAttribute(attn_mma, cudaFuncAttributeMaxDynamicSharedMemorySize, ATTN_SMEM);

    mask_scan<<<BB, 256>>>(mask, pos, cnt);
    conv_w<<<dim3(DF * DF / 1024, 4), 256>>>(Wq, Wk, Wv, Wo, Wh);
    conv_in<<<dim3(MROWS * DF / 1024, 3), 256>>>(Q, K, V, mask, pos, A3);

    gemm_qkv<<<dim3(DF / 128, MROWS / 128, 3), 128, GEMM_SMEM>>>(
        A3, Wh, bq, bk, bv, cnt, Qh, Kh, Vh);

    attn_mma<<<dim3(SS / 128, NH, BB), 256, ATTN_SMEM>>>(Qh, Kh, Vh, cnt, A3);

    gemm_out<<<dim3(DF / 128, MROWS / 128), 128, GEMM_SMEM>>>(
        A3, Wh + (size_t)3 * DF * 1024, bo, out);
}